// round 1
// baseline (speedup 1.0000x reference)
#include <cuda_runtime.h>
#include <math.h>

// Scratch (allocation-free rule: __device__ globals)
__device__ float g_qkv[4096 * 3072];   // 48 MB
__device__ float g_y[4096 * 1024];     // 16 MB

// ---------------------------------------------------------------------------
// Tiled fp32 GEMM + bias:  C[M,N] = A[M,K] @ B[K,N] + bias[N]
// 64x64 block tile, 16-deep k tile, 16x16 threads, 4x4 register tile.
// ---------------------------------------------------------------------------
__global__ __launch_bounds__(256) void gemm_bias_kernel(
    const float* __restrict__ A, const float* __restrict__ B,
    const float* __restrict__ bias, float* __restrict__ C,
    int M, int N, int K)
{
    __shared__ float As[16][68];   // [k][m], stride 68 keeps float4 16B-aligned
    __shared__ float Bs[16][68];   // [k][n]

    const int tid = threadIdx.x;
    const int tx = tid & 15, ty = tid >> 4;
    const int m0 = blockIdx.x * 64;
    const int n0 = blockIdx.y * 64;

    float acc[4][4] = {};

    const float* Aptr = A + (size_t)m0 * K;
    const float* Bptr = B + n0;

    for (int k0 = 0; k0 < K; k0 += 16) {
        #pragma unroll
        for (int i = 0; i < 4; i++) {
            int idx = tid + i * 256;
            int m = idx >> 4, kk = idx & 15;
            As[kk][m] = Aptr[(size_t)m * K + k0 + kk];
        }
        #pragma unroll
        for (int i = 0; i < 4; i++) {
            int idx = tid + i * 256;
            int kk = idx >> 6, n = idx & 63;
            Bs[kk][n] = Bptr[(size_t)(k0 + kk) * N + n];
        }
        __syncthreads();

        #pragma unroll
        for (int kk = 0; kk < 16; kk++) {
            float4 av = *(const float4*)&As[kk][ty * 4];
            float4 bv = *(const float4*)&Bs[kk][tx * 4];
            float a[4] = {av.x, av.y, av.z, av.w};
            float b[4] = {bv.x, bv.y, bv.z, bv.w};
            #pragma unroll
            for (int i = 0; i < 4; i++)
                #pragma unroll
                for (int j = 0; j < 4; j++)
                    acc[i][j] = fmaf(a[i], b[j], acc[i][j]);
        }
        __syncthreads();
    }

    #pragma unroll
    for (int i = 0; i < 4; i++) {
        int row = m0 + ty * 4 + i;
        #pragma unroll
        for (int j = 0; j < 4; j++) {
            int col = n0 + tx * 4 + j;
            C[(size_t)row * N + col] = acc[i][j] + bias[col];
        }
    }
}

// ---------------------------------------------------------------------------
// Causal flash attention (fp32, online softmax).
// Grid: (q_tile 0..31, bh 0..31). Block: 256 threads (16x16).
// Tiles: BQ=BK=64, hd=64. qkv layout: row (b*2048+t), cols:
//   Q at [h*64 .. ), K at [1024 + h*64 .. ), V at [2048 + h*64 .. ).
// ---------------------------------------------------------------------------
__global__ __launch_bounds__(256) void attn_kernel(
    const float* __restrict__ qkv, float* __restrict__ y)
{
    extern __shared__ float smbuf[];
    float* Qs = smbuf;                // 64 x 68
    float* Ks = smbuf + 64 * 68;
    float* Vs = smbuf + 2 * 64 * 68;
    float* Ps = smbuf + 3 * 64 * 68;

    const int qt = blockIdx.x;        // query tile
    const int bh = blockIdx.y;        // b*16 + h
    const int b = bh >> 4, h = bh & 15;
    const int tid = threadIdx.x;
    const int tx = tid & 15, ty = tid >> 4;
    const int q0 = qt * 64;
    const int rowbase = b * 2048;
    const int colq = h * 64;

    // Load Q tile (pre-scaled by 1/sqrt(64))
    for (int i = tid; i < 64 * 64; i += 256) {
        int r = i >> 6, d = i & 63;
        Qs[r * 68 + d] = qkv[(size_t)(rowbase + q0 + r) * 3072 + colq + d] * 0.125f;
    }

    float m_i[4], l_i[4], o[4][4];
    #pragma unroll
    for (int i = 0; i < 4; i++) {
        m_i[i] = -INFINITY; l_i[i] = 0.f;
        #pragma unroll
        for (int c = 0; c < 4; c++) o[i][c] = 0.f;
    }

    for (int kb = 0; kb <= qt; kb++) {
        const int k0 = kb * 64;
        __syncthreads();   // protect Ks/Vs/Ps reuse from previous iteration (and Q load on iter 0)
        for (int i = tid; i < 64 * 64; i += 256) {
            int r = i >> 6, d = i & 63;
            size_t g = (size_t)(rowbase + k0 + r) * 3072 + colq + d;
            Ks[r * 68 + d] = qkv[g + 1024];
            Vs[r * 68 + d] = qkv[g + 2048];
        }
        __syncthreads();

        // S = Q K^T  (4x4 per thread)
        float s[4][4] = {};
        #pragma unroll
        for (int d4 = 0; d4 < 16; d4++) {
            float4 qv[4], kv[4];
            #pragma unroll
            for (int i = 0; i < 4; i++) qv[i] = *(const float4*)&Qs[(ty*4+i)*68 + d4*4];
            #pragma unroll
            for (int j = 0; j < 4; j++) kv[j] = *(const float4*)&Ks[(tx*4+j)*68 + d4*4];
            #pragma unroll
            for (int i = 0; i < 4; i++)
                #pragma unroll
                for (int j = 0; j < 4; j++) {
                    s[i][j] = fmaf(qv[i].x, kv[j].x, s[i][j]);
                    s[i][j] = fmaf(qv[i].y, kv[j].y, s[i][j]);
                    s[i][j] = fmaf(qv[i].z, kv[j].z, s[i][j]);
                    s[i][j] = fmaf(qv[i].w, kv[j].w, s[i][j]);
                }
        }

        // Causal mask — only the diagonal tile needs it
        if (kb == qt) {
            #pragma unroll
            for (int i = 0; i < 4; i++)
                #pragma unroll
                for (int j = 0; j < 4; j++)
                    if (tx * 4 + j > ty * 4 + i) s[i][j] = -INFINITY;
        }

        // Online softmax update (row groups of 16 threads share a row)
        #pragma unroll
        for (int i = 0; i < 4; i++) {
            float tm = fmaxf(fmaxf(s[i][0], s[i][1]), fmaxf(s[i][2], s[i][3]));
            #pragma unroll
            for (int off = 1; off < 16; off <<= 1)
                tm = fmaxf(tm, __shfl_xor_sync(0xffffffffu, tm, off, 16));
            float nm = fmaxf(m_i[i], tm);
            float al = __expf(m_i[i] - nm);
            float rs = 0.f;
            #pragma unroll
            for (int j = 0; j < 4; j++) { s[i][j] = __expf(s[i][j] - nm); rs += s[i][j]; }
            #pragma unroll
            for (int off = 1; off < 16; off <<= 1)
                rs += __shfl_xor_sync(0xffffffffu, rs, off, 16);
            l_i[i] = l_i[i] * al + rs;
            m_i[i] = nm;
            #pragma unroll
            for (int c = 0; c < 4; c++) o[i][c] *= al;
        }

        // Share P via smem, then O += P @ V
        #pragma unroll
        for (int i = 0; i < 4; i++)
            *(float4*)&Ps[(ty*4+i)*68 + tx*4] = make_float4(s[i][0], s[i][1], s[i][2], s[i][3]);
        __syncthreads();

        #pragma unroll
        for (int j4 = 0; j4 < 16; j4++) {
            float4 pv[4];
            #pragma unroll
            for (int i = 0; i < 4; i++) pv[i] = *(const float4*)&Ps[(ty*4+i)*68 + j4*4];
            #pragma unroll
            for (int jj = 0; jj < 4; jj++) {
                float4 vv = *(const float4*)&Vs[(j4*4+jj)*68 + tx*4];
                #pragma unroll
                for (int i = 0; i < 4; i++) {
                    float p = (jj == 0) ? pv[i].x : (jj == 1) ? pv[i].y
                            : (jj == 2) ? pv[i].z : pv[i].w;
                    o[i][0] = fmaf(p, vv.x, o[i][0]);
                    o[i][1] = fmaf(p, vv.y, o[i][1]);
                    o[i][2] = fmaf(p, vv.z, o[i][2]);
                    o[i][3] = fmaf(p, vv.w, o[i][3]);
                }
            }
        }
    }

    // Normalize and write y[b, t, h*64 + d]
    #pragma unroll
    for (int i = 0; i < 4; i++) {
        float inv = 1.f / l_i[i];
        int row = rowbase + q0 + ty * 4 + i;
        #pragma unroll
        for (int c = 0; c < 4; c++)
            y[(size_t)row * 1024 + colq + tx * 4 + c] = o[i][c] * inv;
    }
}

// ---------------------------------------------------------------------------
extern "C" void kernel_launch(void* const* d_in, const int* in_sizes, int n_in,
                              void* d_out, int out_size)
{
    const float* x     = (const float*)d_in[0];
    const float* w_qkv = (const float*)d_in[1];
    const float* b_qkv = (const float*)d_in[2];
    const float* w_out = (const float*)d_in[3];
    const float* b_out = (const float*)d_in[4];
    float* out = (float*)d_out;

    float* qkv; cudaGetSymbolAddress((void**)&qkv, g_qkv);
    float* yb;  cudaGetSymbolAddress((void**)&yb,  g_y);

    dim3 blk(256);

    // 1) QKV projection: [4096,1024] @ [1024,3072] + b
    gemm_bias_kernel<<<dim3(64, 48), blk>>>(x, w_qkv, b_qkv, qkv, 4096, 3072, 1024);

    // 2) Causal flash attention
    size_t smem = (size_t)4 * 64 * 68 * sizeof(float);   // 69632 B
    cudaFuncSetAttribute(attn_kernel, cudaFuncAttributeMaxDynamicSharedMemorySize, (int)smem);
    attn_kernel<<<dim3(32, 32), blk, smem>>>(qkv, yb);

    // 3) Output projection: [4096,1024] @ [1024,1024] + b
    gemm_bias_kernel<<<dim3(64, 16), blk>>>(yb, w_out, b_out, out, 4096, 1024, 1024);
}

// round 3
// speedup vs baseline: 1.4976x; 1.4976x over previous
#include <cuda_runtime.h>
#include <math.h>
#include <cstdint>

// Scratch (allocation-free rule: __device__ globals)
__device__ float g_qkv[4096 * 3072];   // 48 MB
__device__ float g_y[4096 * 1024];     // 16 MB

// ---------------------------------------------------------------------------
// Helpers
// ---------------------------------------------------------------------------
__device__ __forceinline__ uint32_t smem_u32(const void* p) {
    uint32_t a;
    asm("{ .reg .u64 t; cvta.to.shared.u64 t, %1; cvt.u32.u64 %0, t; }"
        : "=r"(a) : "l"(p));
    return a;
}

__device__ __forceinline__ void cp_async16(uint32_t dst, const void* src) {
    asm volatile("cp.async.cg.shared.global [%0], [%1], 16;" :: "r"(dst), "l"(src));
}
__device__ __forceinline__ void cp_commit() {
    asm volatile("cp.async.commit_group;");
}
__device__ __forceinline__ uint32_t f2tf32(float f) {
    uint32_t u;
    asm("cvt.rna.tf32.f32 %0, %1;" : "=r"(u) : "f"(f));
    return u;
}

__device__ __forceinline__ void mma_tf32_16x8x8(
    float* c, const uint32_t* a, const uint32_t* b) {
    asm volatile(
        "mma.sync.aligned.m16n8k8.row.col.f32.tf32.tf32.f32 "
        "{%0,%1,%2,%3}, {%4,%5,%6,%7}, {%8,%9}, {%0,%1,%2,%3};"
        : "+f"(c[0]), "+f"(c[1]), "+f"(c[2]), "+f"(c[3])
        : "r"(a[0]), "r"(a[1]), "r"(a[2]), "r"(a[3]), "r"(b[0]), "r"(b[1]));
}

// ---------------------------------------------------------------------------
// tf32 mma.sync GEMM + bias:  C[M,N] = A[M,K] @ B[K,N] + bias[N]
// CTA tile 128x128, K-chunk 32, 3-stage cp.async pipeline.
// 8 warps: warp grid 2(M) x 4(N), warp tile 64x32 = 4 mfrag(16) x 4 nfrag(8).
// smem: A [128][36] floats (row-major, padded), B [32][136] floats.
// Fragment-load bank math (4B banks, mod 32):
//   A: (l/4)*36 + l%4  -> 4r+c distinct (r<8,c<4)  conflict-free
//   B: (l%4)*136 + l/4 -> 8c+r distinct            conflict-free
// ---------------------------------------------------------------------------
#define A_STRIDE 36
#define B_STRIDE 136
#define A_TILE_F (128 * A_STRIDE)            // 4608 floats
#define B_TILE_F (32 * B_STRIDE)             // 4352 floats
#define STAGE_F  (A_TILE_F + B_TILE_F)       // 8960 floats = 35840 B
#define GEMM_SMEM (3 * STAGE_F * 4)          // 107520 B

__global__ __launch_bounds__(256, 1)
void gemm_tc(const float* __restrict__ A, const float* __restrict__ B,
             const float* __restrict__ bias, float* __restrict__ C,
             int M, int N, int K)
{
    extern __shared__ __align__(16) float smem[];

    const int tid = threadIdx.x;
    const int wid = tid >> 5, lane = tid & 31;
    const int m0 = blockIdx.x * 128;
    const int n0 = blockIdx.y * 128;
    const int wm = wid & 1;          // 0..1 -> m offset wm*64
    const int wn = wid >> 1;         // 0..3 -> n offset wn*32

    const uint32_t sbase = smem_u32(smem);

    // --- cp.async prefetch of one K-chunk (32) into a stage ---
    // A: 128 rows x 32 floats; thread -> (row = i/8, c4 = i%8), 4 iters
    // B:  32 rows x 128 floats; thread -> (krow = i/32, c4 = i%32), 4 iters
    auto prefetch = [&](int k0, int stage) {
        uint32_t Ad = sbase + stage * STAGE_F * 4;
        uint32_t Bd = Ad + A_TILE_F * 4;
        #pragma unroll
        for (int i = 0; i < 4; i++) {
            int s = tid + i * 256;
            int r = s >> 3, c4 = s & 7;
            cp_async16(Ad + (r * A_STRIDE + c4 * 4) * 4,
                       A + (size_t)(m0 + r) * K + k0 + c4 * 4);
        }
        #pragma unroll
        for (int i = 0; i < 4; i++) {
            int s = tid + i * 256;
            int kr = s >> 5, c4 = s & 31;
            cp_async16(Bd + (kr * B_STRIDE + c4 * 4) * 4,
                       B + (size_t)(k0 + kr) * N + n0 + c4 * 4);
        }
        cp_commit();
    };

    float acc[4][4][4];
    #pragma unroll
    for (int i = 0; i < 4; i++)
        #pragma unroll
        for (int j = 0; j < 4; j++)
            #pragma unroll
            for (int r = 0; r < 4; r++) acc[i][j][r] = 0.f;

    const int NCH = K >> 5;
    prefetch(0, 0);
    if (NCH > 1) prefetch(32, 1);

    const int lr = lane >> 2;        // 0..7
    const int lc = lane & 3;         // 0..3

    for (int c = 0; c < NCH; c++) {
        // Wait for chunk c (leave at most the next chunk in flight)
        if (c == NCH - 1)
            asm volatile("cp.async.wait_group 0;" ::: "memory");
        else
            asm volatile("cp.async.wait_group 1;" ::: "memory");
        __syncthreads();

        // Prefetch chunk c+2 into stage (c+2)%3 (its last readers were at
        // iter c-1, fenced by the syncthreads above)
        if (c + 2 < NCH) prefetch((c + 2) * 32, (c + 2) % 3);

        const float* As = smem + (c % 3) * STAGE_F;
        const float* Bs = As + A_TILE_F;

        #pragma unroll
        for (int ks = 0; ks < 4; ks++) {
            const int kb = ks * 8;
            uint32_t af[4][4], bf[4][2];
            #pragma unroll
            for (int mf = 0; mf < 4; mf++) {
                int r0 = wm * 64 + mf * 16 + lr;
                af[mf][0] = f2tf32(As[r0 * A_STRIDE + kb + lc]);
                af[mf][1] = f2tf32(As[(r0 + 8) * A_STRIDE + kb + lc]);
                af[mf][2] = f2tf32(As[r0 * A_STRIDE + kb + lc + 4]);
                af[mf][3] = f2tf32(As[(r0 + 8) * A_STRIDE + kb + lc + 4]);
            }
            #pragma unroll
            for (int nf = 0; nf < 4; nf++) {
                int c0 = wn * 32 + nf * 8 + lr;
                bf[nf][0] = f2tf32(Bs[(kb + lc) * B_STRIDE + c0]);
                bf[nf][1] = f2tf32(Bs[(kb + lc + 4) * B_STRIDE + c0]);
            }
            #pragma unroll
            for (int mf = 0; mf < 4; mf++)
                #pragma unroll
                for (int nf = 0; nf < 4; nf++)
                    mma_tf32_16x8x8(acc[mf][nf], af[mf], bf[nf]);
        }
        __syncthreads();
    }

    // Epilogue: c0/c1 -> (row, 2*lc), c2/c3 -> (row+8, 2*lc); add bias.
    #pragma unroll
    for (int mf = 0; mf < 4; mf++) {
        int row = m0 + wm * 64 + mf * 16 + lr;
        #pragma unroll
        for (int nf = 0; nf < 4; nf++) {
            int col = n0 + wn * 32 + nf * 8 + 2 * lc;
            float b0 = bias[col], b1 = bias[col + 1];
            float2 v0 = make_float2(acc[mf][nf][0] + b0, acc[mf][nf][1] + b1);
            float2 v1 = make_float2(acc[mf][nf][2] + b0, acc[mf][nf][3] + b1);
            *(float2*)&C[(size_t)row * N + col] = v0;
            *(float2*)&C[(size_t)(row + 8) * N + col] = v1;
        }
    }
}

// ---------------------------------------------------------------------------
// Causal flash attention (fp32, online softmax) — unchanged (passing).
// Grid: (q_tile 0..31, bh 0..31). Block: 256 threads (16x16).
// ---------------------------------------------------------------------------
__global__ __launch_bounds__(256) void attn_kernel(
    const float* __restrict__ qkv, float* __restrict__ y)
{
    extern __shared__ float smbuf[];
    float* Qs = smbuf;                // 64 x 68
    float* Ks = smbuf + 64 * 68;
    float* Vs = smbuf + 2 * 64 * 68;
    float* Ps = smbuf + 3 * 64 * 68;

    const int qt = blockIdx.x;
    const int bh = blockIdx.y;
    const int b = bh >> 4, h = bh & 15;
    const int tid = threadIdx.x;
    const int tx = tid & 15, ty = tid >> 4;
    const int q0 = qt * 64;
    const int rowbase = b * 2048;
    const int colq = h * 64;

    for (int i = tid; i < 64 * 64; i += 256) {
        int r = i >> 6, d = i & 63;
        Qs[r * 68 + d] = qkv[(size_t)(rowbase + q0 + r) * 3072 + colq + d] * 0.125f;
    }

    float m_i[4], l_i[4], o[4][4];
    #pragma unroll
    for (int i = 0; i < 4; i++) {
        m_i[i] = -INFINITY; l_i[i] = 0.f;
        #pragma unroll
        for (int c = 0; c < 4; c++) o[i][c] = 0.f;
    }

    for (int kb = 0; kb <= qt; kb++) {
        const int k0 = kb * 64;
        __syncthreads();
        for (int i = tid; i < 64 * 64; i += 256) {
            int r = i >> 6, d = i & 63;
            size_t g = (size_t)(rowbase + k0 + r) * 3072 + colq + d;
            Ks[r * 68 + d] = qkv[g + 1024];
            Vs[r * 68 + d] = qkv[g + 2048];
        }
        __syncthreads();

        float s[4][4] = {};
        #pragma unroll
        for (int d4 = 0; d4 < 16; d4++) {
            float4 qv[4], kv[4];
            #pragma unroll
            for (int i = 0; i < 4; i++) qv[i] = *(const float4*)&Qs[(ty*4+i)*68 + d4*4];
            #pragma unroll
            for (int j = 0; j < 4; j++) kv[j] = *(const float4*)&Ks[(tx*4+j)*68 + d4*4];
            #pragma unroll
            for (int i = 0; i < 4; i++)
                #pragma unroll
                for (int j = 0; j < 4; j++) {
                    s[i][j] = fmaf(qv[i].x, kv[j].x, s[i][j]);
                    s[i][j] = fmaf(qv[i].y, kv[j].y, s[i][j]);
                    s[i][j] = fmaf(qv[i].z, kv[j].z, s[i][j]);
                    s[i][j] = fmaf(qv[i].w, kv[j].w, s[i][j]);
                }
        }

        if (kb == qt) {
            #pragma unroll
            for (int i = 0; i < 4; i++)
                #pragma unroll
                for (int j = 0; j < 4; j++)
                    if (tx * 4 + j > ty * 4 + i) s[i][j] = -INFINITY;
        }

        #pragma unroll
        for (int i = 0; i < 4; i++) {
            float tm = fmaxf(fmaxf(s[i][0], s[i][1]), fmaxf(s[i][2], s[i][3]));
            #pragma unroll
            for (int off = 1; off < 16; off <<= 1)
                tm = fmaxf(tm, __shfl_xor_sync(0xffffffffu, tm, off, 16));
            float nm = fmaxf(m_i[i], tm);
            float al = __expf(m_i[i] - nm);
            float rs = 0.f;
            #pragma unroll
            for (int j = 0; j < 4; j++) { s[i][j] = __expf(s[i][j] - nm); rs += s[i][j]; }
            #pragma unroll
            for (int off = 1; off < 16; off <<= 1)
                rs += __shfl_xor_sync(0xffffffffu, rs, off, 16);
            l_i[i] = l_i[i] * al + rs;
            m_i[i] = nm;
            #pragma unroll
            for (int c = 0; c < 4; c++) o[i][c] *= al;
        }

        #pragma unroll
        for (int i = 0; i < 4; i++)
            *(float4*)&Ps[(ty*4+i)*68 + tx*4] = make_float4(s[i][0], s[i][1], s[i][2], s[i][3]);
        __syncthreads();

        #pragma unroll
        for (int j4 = 0; j4 < 16; j4++) {
            float4 pv[4];
            #pragma unroll
            for (int i = 0; i < 4; i++) pv[i] = *(const float4*)&Ps[(ty*4+i)*68 + j4*4];
            #pragma unroll
            for (int jj = 0; jj < 4; jj++) {
                float4 vv = *(const float4*)&Vs[(j4*4+jj)*68 + tx*4];
                #pragma unroll
                for (int i = 0; i < 4; i++) {
                    float p = (jj == 0) ? pv[i].x : (jj == 1) ? pv[i].y
                            : (jj == 2) ? pv[i].z : pv[i].w;
                    o[i][0] = fmaf(p, vv.x, o[i][0]);
                    o[i][1] = fmaf(p, vv.y, o[i][1]);
                    o[i][2] = fmaf(p, vv.z, o[i][2]);
                    o[i][3] = fmaf(p, vv.w, o[i][3]);
                }
            }
        }
    }

    #pragma unroll
    for (int i = 0; i < 4; i++) {
        float inv = 1.f / l_i[i];
        int row = rowbase + q0 + ty * 4 + i;
        #pragma unroll
        for (int c = 0; c < 4; c++)
            y[(size_t)row * 1024 + colq + tx * 4 + c] = o[i][c] * inv;
    }
}

// ---------------------------------------------------------------------------
extern "C" void kernel_launch(void* const* d_in, const int* in_sizes, int n_in,
                              void* d_out, int out_size)
{
    const float* x     = (const float*)d_in[0];
    const float* w_qkv = (const float*)d_in[1];
    const float* b_qkv = (const float*)d_in[2];
    const float* w_out = (const float*)d_in[3];
    const float* b_out = (const float*)d_in[4];
    float* out = (float*)d_out;

    float* qkv; cudaGetSymbolAddress((void**)&qkv, g_qkv);
    float* yb;  cudaGetSymbolAddress((void**)&yb,  g_y);

    cudaFuncSetAttribute(gemm_tc, cudaFuncAttributeMaxDynamicSharedMemorySize, GEMM_SMEM);

    // 1) QKV projection: [4096,1024] @ [1024,3072] + b  (mma.sync tf32)
    gemm_tc<<<dim3(32, 24), 256, GEMM_SMEM>>>(x, w_qkv, b_qkv, qkv, 4096, 3072, 1024);

    // 2) Causal flash attention (fp32 SIMT)
    size_t smem = (size_t)4 * 64 * 68 * sizeof(float);   // 69632 B
    cudaFuncSetAttribute(attn_kernel, cudaFuncAttributeMaxDynamicSharedMemorySize, (int)smem);
    attn_kernel<<<dim3(32, 32), 256, smem>>>(qkv, yb);

    // 3) Output projection: [4096,1024] @ [1024,1024] + b  (mma.sync tf32)
    gemm_tc<<<dim3(32, 8), 256, GEMM_SMEM>>>(yb, w_out, b_out, out, 4096, 1024, 1024);
}

// round 5
// speedup vs baseline: 1.9360x; 1.2928x over previous
#include <cuda_runtime.h>
#include <math.h>
#include <cstdint>

// Scratch (allocation-free rule: __device__ globals)
__device__ float g_qkv[4096 * 3072];   // 48 MB
__device__ float g_y[4096 * 1024];     // 16 MB

// ---------------------------------------------------------------------------
// Helpers
// ---------------------------------------------------------------------------
__device__ __forceinline__ uint32_t smem_u32(const void* p) {
    uint32_t a;
    asm("{ .reg .u64 t; cvta.to.shared.u64 t, %1; cvt.u32.u64 %0, t; }"
        : "=r"(a) : "l"(p));
    return a;
}
__device__ __forceinline__ void cp_async16(uint32_t dst, const void* src) {
    asm volatile("cp.async.cg.shared.global [%0], [%1], 16;" :: "r"(dst), "l"(src));
}
__device__ __forceinline__ void cp_commit() {
    asm volatile("cp.async.commit_group;");
}
__device__ __forceinline__ uint32_t f2tf32(float f) {
    uint32_t u;
    asm("cvt.rna.tf32.f32 %0, %1;" : "=r"(u) : "f"(f));
    return u;
}
__device__ __forceinline__ float tf32r(float x) {   // round-to-nearest tf32, as f32
    float r;
    asm("cvt.rna.tf32.f32 %0, %1;" : "=f"(r) : "f"(x));
    return r;
}
__device__ __forceinline__ void mma_tf32_16x8x8(
    float* c, const uint32_t* a, const uint32_t* b) {
    asm volatile(
        "mma.sync.aligned.m16n8k8.row.col.f32.tf32.tf32.f32 "
        "{%0,%1,%2,%3}, {%4,%5,%6,%7}, {%8,%9}, {%0,%1,%2,%3};"
        : "+f"(c[0]), "+f"(c[1]), "+f"(c[2]), "+f"(c[3])
        : "r"(a[0]), "r"(a[1]), "r"(a[2]), "r"(a[3]), "r"(b[0]), "r"(b[1]));
}

// ---------------------------------------------------------------------------
// tf32 mma.sync GEMM + bias (unchanged from round 3, passing at 229us QKV)
// ---------------------------------------------------------------------------
#define A_STRIDE 36
#define B_STRIDE 136
#define A_TILE_F (128 * A_STRIDE)
#define B_TILE_F (32 * B_STRIDE)
#define STAGE_F  (A_TILE_F + B_TILE_F)
#define GEMM_SMEM (3 * STAGE_F * 4)

__global__ __launch_bounds__(256, 1)
void gemm_tc(const float* __restrict__ A, const float* __restrict__ B,
             const float* __restrict__ bias, float* __restrict__ C,
             int M, int N, int K)
{
    extern __shared__ __align__(16) float smem[];

    const int tid = threadIdx.x;
    const int wid = tid >> 5, lane = tid & 31;
    const int m0 = blockIdx.x * 128;
    const int n0 = blockIdx.y * 128;
    const int wm = wid & 1;
    const int wn = wid >> 1;

    const uint32_t sbase = smem_u32(smem);

    auto prefetch = [&](int k0, int stage) {
        uint32_t Ad = sbase + stage * STAGE_F * 4;
        uint32_t Bd = Ad + A_TILE_F * 4;
        #pragma unroll
        for (int i = 0; i < 4; i++) {
            int s = tid + i * 256;
            int r = s >> 3, c4 = s & 7;
            cp_async16(Ad + (r * A_STRIDE + c4 * 4) * 4,
                       A + (size_t)(m0 + r) * K + k0 + c4 * 4);
        }
        #pragma unroll
        for (int i = 0; i < 4; i++) {
            int s = tid + i * 256;
            int kr = s >> 5, c4 = s & 31;
            cp_async16(Bd + (kr * B_STRIDE + c4 * 4) * 4,
                       B + (size_t)(k0 + kr) * N + n0 + c4 * 4);
        }
        cp_commit();
    };

    float acc[4][4][4];
    #pragma unroll
    for (int i = 0; i < 4; i++)
        #pragma unroll
        for (int j = 0; j < 4; j++)
            #pragma unroll
            for (int r = 0; r < 4; r++) acc[i][j][r] = 0.f;

    const int NCH = K >> 5;
    prefetch(0, 0);
    if (NCH > 1) prefetch(32, 1);

    const int lr = lane >> 2;
    const int lc = lane & 3;

    for (int c = 0; c < NCH; c++) {
        if (c == NCH - 1)
            asm volatile("cp.async.wait_group 0;" ::: "memory");
        else
            asm volatile("cp.async.wait_group 1;" ::: "memory");
        __syncthreads();

        if (c + 2 < NCH) prefetch((c + 2) * 32, (c + 2) % 3);

        const float* As = smem + (c % 3) * STAGE_F;
        const float* Bs = As + A_TILE_F;

        #pragma unroll
        for (int ks = 0; ks < 4; ks++) {
            const int kb = ks * 8;
            uint32_t af[4][4], bf[4][2];
            #pragma unroll
            for (int mf = 0; mf < 4; mf++) {
                int r0 = wm * 64 + mf * 16 + lr;
                af[mf][0] = f2tf32(As[r0 * A_STRIDE + kb + lc]);
                af[mf][1] = f2tf32(As[(r0 + 8) * A_STRIDE + kb + lc]);
                af[mf][2] = f2tf32(As[r0 * A_STRIDE + kb + lc + 4]);
                af[mf][3] = f2tf32(As[(r0 + 8) * A_STRIDE + kb + lc + 4]);
            }
            #pragma unroll
            for (int nf = 0; nf < 4; nf++) {
                int c0 = wn * 32 + nf * 8 + lr;
                bf[nf][0] = f2tf32(Bs[(kb + lc) * B_STRIDE + c0]);
                bf[nf][1] = f2tf32(Bs[(kb + lc + 4) * B_STRIDE + c0]);
            }
            #pragma unroll
            for (int mf = 0; mf < 4; mf++)
                #pragma unroll
                for (int nf = 0; nf < 4; nf++)
                    mma_tf32_16x8x8(acc[mf][nf], af[mf], bf[nf]);
        }
        __syncthreads();
    }

    #pragma unroll
    for (int mf = 0; mf < 4; mf++) {
        int row = m0 + wm * 64 + mf * 16 + lr;
        #pragma unroll
        for (int nf = 0; nf < 4; nf++) {
            int col = n0 + wn * 32 + nf * 8 + 2 * lc;
            float b0 = bias[col], b1 = bias[col + 1];
            float2 v0 = make_float2(acc[mf][nf][0] + b0, acc[mf][nf][1] + b1);
            float2 v1 = make_float2(acc[mf][nf][2] + b0, acc[mf][nf][3] + b1);
            *(float2*)&C[(size_t)row * N + col] = v0;
            *(float2*)&C[(size_t)(row + 8) * N + col] = v1;
        }
    }
}

// ---------------------------------------------------------------------------
// Tensor-core causal flash attention (tf32 mma.sync, online softmax).
// BQ=128, BK=64. 256 threads = 8 warps; warp w owns q-rows 16w..16w+15.
// S = Q K^T with split-tf32 (3 MMAs: hi*hi + hi*lo + lo*hi) for near-fp32 S.
// P V in plain tf32 (errors average under softmax weights).
// smem floats: Qhi/Qlo[128][68], Khi/Klo/Kraw[64][68], Vs/Vraw[64][72], Ps[128][68]
// K tile in gmem is [t][d] == [n][k] layout wanted by B-frags; V is [k][n]. No transpose.
// ---------------------------------------------------------------------------
#define ATTN_SMEM ((2*128*68 + 3*64*68 + 2*64*72 + 128*68) * 4)   // 193536 B

__global__ __launch_bounds__(256, 1)
void attn_tc(const float* __restrict__ qkv, float* __restrict__ y)
{
    extern __shared__ __align__(16) float sm[];
    float* Qhi  = sm;                    // 128*68
    float* Qlo  = Qhi  + 128 * 68;
    float* Khi  = Qlo  + 128 * 68;       // 64*68
    float* Klo  = Khi  + 64 * 68;
    float* Kraw = Klo  + 64 * 68;
    float* Vs   = Kraw + 64 * 68;        // 64*72
    float* Vraw = Vs   + 64 * 72;
    float* Ps   = Vraw + 64 * 72;        // 128*68

    const int qt = 15 - blockIdx.x;      // heavy tiles first (better wave tail)
    const int bh = blockIdx.y;
    const int b = bh >> 4, h = bh & 15;
    const int tid = threadIdx.x;
    const int wid = tid >> 5, lane = tid & 31;
    const int lr = lane >> 2, lc = lane & 3;
    const int q0 = qt * 128;
    const int rowbase = b * 2048;
    const int colq = h * 64;

    const uint32_t sbase = smem_u32(sm);
    const uint32_t KrawA = sbase + (uint32_t)((Kraw - sm) * 4);
    const uint32_t VrawA = sbase + (uint32_t)((Vraw - sm) * 4);

    // Load Q (scaled) and split into hi/lo tf32 halves
    for (int i = tid; i < 128 * 64; i += 256) {
        int r = i >> 6, c = i & 63;
        float x = qkv[(size_t)(rowbase + q0 + r) * 3072 + colq + c] * 0.125f;
        float hi = tf32r(x);
        Qhi[r * 68 + c] = hi;
        Qlo[r * 68 + c] = tf32r(x - hi);
    }

    auto prefetch = [&](int kt) {
        #pragma unroll
        for (int j = 0; j < 4; j++) {
            int s = tid + j * 256;
            int r = s >> 4, c4 = s & 15;
            const float* src = qkv + (size_t)(rowbase + kt * 64 + r) * 3072 + colq + c4 * 4;
            cp_async16(KrawA + (r * 68 + c4 * 4) * 4, src + 1024);
            cp_async16(VrawA + (r * 72 + c4 * 4) * 4, src + 2048);
        }
        cp_commit();
    };

    prefetch(0);

    float m_i[2] = {-INFINITY, -INFINITY};
    float l_i[2] = {0.f, 0.f};
    float acc_o[8][4];
    #pragma unroll
    for (int nf = 0; nf < 8; nf++)
        #pragma unroll
        for (int c = 0; c < 4; c++) acc_o[nf][c] = 0.f;

    const int ktmax = 2 * qt + 1;
    const int r_row = 16 * wid + lr;            // local q-row for c0/c1 (c2/c3 = +8)
    const int prow = r_row * 68;

    for (int kt = 0; kt <= ktmax; kt++) {
        asm volatile("cp.async.wait_group 0;" ::: "memory");
        __syncthreads();                        // raw ready; prev compute done w/ Khi/Klo/Vs

        // Convert K -> hi/lo, V -> tf32-rounded
        for (int i = tid; i < 64 * 64; i += 256) {
            int r = i >> 6, c = i & 63;
            float x = Kraw[r * 68 + c];
            float hi = tf32r(x);
            Khi[r * 68 + c] = hi;
            Klo[r * 68 + c] = tf32r(x - hi);
            Vs[r * 72 + c] = tf32r(Vraw[r * 72 + c]);
        }
        __syncthreads();

        if (kt < ktmax) prefetch(kt + 1);       // overlaps MMA below

        // ---- S = Q K^T (split tf32) ----
        float sacc[8][4];
        #pragma unroll
        for (int nf = 0; nf < 8; nf++)
            #pragma unroll
            for (int c = 0; c < 4; c++) sacc[nf][c] = 0.f;

        #pragma unroll
        for (int ks = 0; ks < 8; ks++) {
            const int kb = ks * 8;
            uint32_t ah[4], alo[4];
            const int ra = prow + kb + lc;
            ah[0] = __float_as_uint(Qhi[ra]);
            ah[1] = __float_as_uint(Qhi[ra + 8 * 68]);
            ah[2] = __float_as_uint(Qhi[ra + 4]);
            ah[3] = __float_as_uint(Qhi[ra + 8 * 68 + 4]);
            alo[0] = __float_as_uint(Qlo[ra]);
            alo[1] = __float_as_uint(Qlo[ra + 8 * 68]);
            alo[2] = __float_as_uint(Qlo[ra + 4]);
            alo[3] = __float_as_uint(Qlo[ra + 8 * 68 + 4]);
            #pragma unroll
            for (int nf = 0; nf < 8; nf++) {
                const int cb = (8 * nf + lr) * 68 + kb + lc;
                uint32_t bhf[2], blf[2];
                bhf[0] = __float_as_uint(Khi[cb]);
                bhf[1] = __float_as_uint(Khi[cb + 4]);
                blf[0] = __float_as_uint(Klo[cb]);
                blf[1] = __float_as_uint(Klo[cb + 4]);
                mma_tf32_16x8x8(sacc[nf], ah, bhf);
                mma_tf32_16x8x8(sacc[nf], ah, blf);
                mma_tf32_16x8x8(sacc[nf], alo, bhf);
            }
        }

        // ---- Causal mask (only the 2 diagonal k-tiles need it) ----
        if (kt >= 2 * qt) {
            const int rg = q0 + r_row;
            const int cb0 = kt * 64 + 2 * lc;
            #pragma unroll
            for (int nf = 0; nf < 8; nf++) {
                int c0 = cb0 + 8 * nf;
                if (c0     > rg)     sacc[nf][0] = -INFINITY;
                if (c0 + 1 > rg)     sacc[nf][1] = -INFINITY;
                if (c0     > rg + 8) sacc[nf][2] = -INFINITY;
                if (c0 + 1 > rg + 8) sacc[nf][3] = -INFINITY;
            }
        }

        // ---- Online softmax (rows fully within warp; reduce across 4 lanes) ----
        float tm0 = -INFINITY, tm1 = -INFINITY;
        #pragma unroll
        for (int nf = 0; nf < 8; nf++) {
            tm0 = fmaxf(tm0, fmaxf(sacc[nf][0], sacc[nf][1]));
            tm1 = fmaxf(tm1, fmaxf(sacc[nf][2], sacc[nf][3]));
        }
        tm0 = fmaxf(tm0, __shfl_xor_sync(0xffffffffu, tm0, 1));
        tm0 = fmaxf(tm0, __shfl_xor_sync(0xffffffffu, tm0, 2));
        tm1 = fmaxf(tm1, __shfl_xor_sync(0xffffffffu, tm1, 1));
        tm1 = fmaxf(tm1, __shfl_xor_sync(0xffffffffu, tm1, 2));

        const float nm0 = fmaxf(m_i[0], tm0);
        const float nm1 = fmaxf(m_i[1], tm1);
        const float sc0 = __expf(m_i[0] - nm0);
        const float sc1 = __expf(m_i[1] - nm1);
        float rs0 = 0.f, rs1 = 0.f;
        #pragma unroll
        for (int nf = 0; nf < 8; nf++) {
            sacc[nf][0] = __expf(sacc[nf][0] - nm0);
            sacc[nf][1] = __expf(sacc[nf][1] - nm0);
            sacc[nf][2] = __expf(sacc[nf][2] - nm1);
            sacc[nf][3] = __expf(sacc[nf][3] - nm1);
            rs0 += sacc[nf][0] + sacc[nf][1];
            rs1 += sacc[nf][2] + sacc[nf][3];
        }
        rs0 += __shfl_xor_sync(0xffffffffu, rs0, 1);
        rs0 += __shfl_xor_sync(0xffffffffu, rs0, 2);
        rs1 += __shfl_xor_sync(0xffffffffu, rs1, 1);
        rs1 += __shfl_xor_sync(0xffffffffu, rs1, 2);
        l_i[0] = l_i[0] * sc0 + rs0;
        l_i[1] = l_i[1] * sc1 + rs1;
        m_i[0] = nm0;
        m_i[1] = nm1;
        #pragma unroll
        for (int nf = 0; nf < 8; nf++) {
            acc_o[nf][0] *= sc0; acc_o[nf][1] *= sc0;
            acc_o[nf][2] *= sc1; acc_o[nf][3] *= sc1;
        }

        // ---- Stage P through smem (per-warp private rows) ----
        #pragma unroll
        for (int nf = 0; nf < 8; nf++) {
            *(float2*)&Ps[prow + 8 * nf + 2 * lc] =
                make_float2(sacc[nf][0], sacc[nf][1]);
            *(float2*)&Ps[prow + 8 * 68 + 8 * nf + 2 * lc] =
                make_float2(sacc[nf][2], sacc[nf][3]);
        }
        __syncwarp();

        // ---- O += P V (plain tf32) ----
        #pragma unroll
        for (int ks = 0; ks < 8; ks++) {
            const int kb = ks * 8;
            uint32_t pa[4];
            const int ra = prow + kb + lc;
            pa[0] = f2tf32(Ps[ra]);
            pa[1] = f2tf32(Ps[ra + 8 * 68]);
            pa[2] = f2tf32(Ps[ra + 4]);
            pa[3] = f2tf32(Ps[ra + 8 * 68 + 4]);
            #pragma unroll
            for (int nf = 0; nf < 8; nf++) {
                const int cb = (kb + lc) * 72 + 8 * nf + lr;
                uint32_t vb[2];
                vb[0] = __float_as_uint(Vs[cb]);
                vb[1] = __float_as_uint(Vs[cb + 4 * 72]);
                mma_tf32_16x8x8(acc_o[nf], pa, vb);
            }
        }
        __syncwarp();    // P reads done before next iteration's P stores
    }

    // ---- Epilogue: normalize and store ----
    const float il0 = 1.f / l_i[0];
    const float il1 = 1.f / l_i[1];
    const size_t row0 = (size_t)(rowbase + q0 + r_row) * 1024;
    const size_t row1 = row0 + 8 * 1024;
    #pragma unroll
    for (int nf = 0; nf < 8; nf++) {
        int col = colq + 8 * nf + 2 * lc;
        *(float2*)&y[row0 + col] = make_float2(acc_o[nf][0] * il0, acc_o[nf][1] * il0);
        *(float2*)&y[row1 + col] = make_float2(acc_o[nf][2] * il1, acc_o[nf][3] * il1);
    }
}

// ---------------------------------------------------------------------------
extern "C" void kernel_launch(void* const* d_in, const int* in_sizes, int n_in,
                              void* d_out, int out_size)
{
    const float* x     = (const float*)d_in[0];
    const float* w_qkv = (const float*)d_in[1];
    const float* b_qkv = (const float*)d_in[2];
    const float* w_out = (const float*)d_in[3];
    const float* b_out = (const float*)d_in[4];
    float* out = (float*)d_out;

    float* qkv; cudaGetSymbolAddress((void**)&qkv, g_qkv);
    float* yb;  cudaGetSymbolAddress((void**)&yb,  g_y);

    cudaFuncSetAttribute(gemm_tc, cudaFuncAttributeMaxDynamicSharedMemorySize, GEMM_SMEM);
    cudaFuncSetAttribute(attn_tc, cudaFuncAttributeMaxDynamicSharedMemorySize, ATTN_SMEM);

    // 1) QKV projection: [4096,1024] @ [1024,3072] + b  (mma.sync tf32)
    gemm_tc<<<dim3(32, 24), 256, GEMM_SMEM>>>(x, w_qkv, b_qkv, qkv, 4096, 3072, 1024);

    // 2) Causal flash attention (mma.sync tf32, split-tf32 QK^T)
    attn_tc<<<dim3(16, 32), 256, ATTN_SMEM>>>(qkv, yb);

    // 3) Output projection: [4096,1024] @ [1024,1024] + b  (mma.sync tf32)
    gemm_tc<<<dim3(32, 8), 256, GEMM_SMEM>>>(yb, w_out, b_out, out, 4096, 1024, 1024);
}

// round 7
// speedup vs baseline: 3.2277x; 1.6672x over previous
#include <cuda_runtime.h>
#include <math.h>
#include <cstdint>

// Scratch (allocation-free rule: __device__ globals)
__device__ float g_qkv[4096 * 3072];   // 48 MB
__device__ float g_y[4096 * 1024];     // 16 MB

// ---------------------------------------------------------------------------
// Helpers
// ---------------------------------------------------------------------------
__device__ __forceinline__ uint32_t smem_u32(const void* p) {
    uint32_t a;
    asm("{ .reg .u64 t; cvta.to.shared.u64 t, %1; cvt.u32.u64 %0, t; }"
        : "=r"(a) : "l"(p));
    return a;
}
__device__ __forceinline__ void cp_async16(uint32_t dst, const void* src) {
    asm volatile("cp.async.cg.shared.global [%0], [%1], 16;" :: "r"(dst), "l"(src));
}
__device__ __forceinline__ void cp_commit() {
    asm volatile("cp.async.commit_group;");
}
__device__ __forceinline__ uint32_t f2tf32(float f) {
    uint32_t u;
    asm("cvt.rna.tf32.f32 %0, %1;" : "=r"(u) : "f"(f));
    return u;
}
__device__ __forceinline__ float tf32r(float x) {   // round-to-nearest tf32, as f32
    float r;
    asm("cvt.rna.tf32.f32 %0, %1;" : "=f"(r) : "f"(x));
    return r;
}
__device__ __forceinline__ void mma_tf32_16x8x8(
    float* c, const uint32_t* a, const uint32_t* b) {
    asm volatile(
        "mma.sync.aligned.m16n8k8.row.col.f32.tf32.tf32.f32 "
        "{%0,%1,%2,%3}, {%4,%5,%6,%7}, {%8,%9}, {%0,%1,%2,%3};"
        : "+f"(c[0]), "+f"(c[1]), "+f"(c[2]), "+f"(c[3])
        : "r"(a[0]), "r"(a[1]), "r"(a[2]), "r"(a[3]), "r"(b[0]), "r"(b[1]));
}

// ---------------------------------------------------------------------------
// tf32 mma.sync GEMM + bias.  Round-6 change: __launch_bounds__(256, 2)
// (regs 134 -> <=128) so 2 CTAs/SM co-reside (smem 2*107.5KB = 215KB <= 228KB).
// ---------------------------------------------------------------------------
#define A_STRIDE 36
#define B_STRIDE 136
#define A_TILE_F (128 * A_STRIDE)
#define B_TILE_F (32 * B_STRIDE)
#define STAGE_F  (A_TILE_F + B_TILE_F)
#define GEMM_SMEM (3 * STAGE_F * 4)

__global__ __launch_bounds__(256, 2)
void gemm_tc(const float* __restrict__ A, const float* __restrict__ B,
             const float* __restrict__ bias, float* __restrict__ C,
             int M, int N, int K)
{
    extern __shared__ __align__(16) float smem[];

    const int tid = threadIdx.x;
    const int wid = tid >> 5, lane = tid & 31;
    const int m0 = blockIdx.x * 128;
    const int n0 = blockIdx.y * 128;
    const int wm = wid & 1;
    const int wn = wid >> 1;

    const uint32_t sbase = smem_u32(smem);

    auto prefetch = [&](int k0, int stage) {
        uint32_t Ad = sbase + stage * STAGE_F * 4;
        uint32_t Bd = Ad + A_TILE_F * 4;
        #pragma unroll
        for (int i = 0; i < 4; i++) {
            int s = tid + i * 256;
            int r = s >> 3, c4 = s & 7;
            cp_async16(Ad + (r * A_STRIDE + c4 * 4) * 4,
                       A + (size_t)(m0 + r) * K + k0 + c4 * 4);
        }
        #pragma unroll
        for (int i = 0; i < 4; i++) {
            int s = tid + i * 256;
            int kr = s >> 5, c4 = s & 31;
            cp_async16(Bd + (kr * B_STRIDE + c4 * 4) * 4,
                       B + (size_t)(k0 + kr) * N + n0 + c4 * 4);
        }
        cp_commit();
    };

    float acc[4][4][4];
    #pragma unroll
    for (int i = 0; i < 4; i++)
        #pragma unroll
        for (int j = 0; j < 4; j++)
            #pragma unroll
            for (int r = 0; r < 4; r++) acc[i][j][r] = 0.f;

    const int NCH = K >> 5;
    prefetch(0, 0);
    if (NCH > 1) prefetch(32, 1);

    const int lr = lane >> 2;
    const int lc = lane & 3;

    for (int c = 0; c < NCH; c++) {
        if (c == NCH - 1)
            asm volatile("cp.async.wait_group 0;" ::: "memory");
        else
            asm volatile("cp.async.wait_group 1;" ::: "memory");
        __syncthreads();

        if (c + 2 < NCH) prefetch((c + 2) * 32, (c + 2) % 3);

        const float* As = smem + (c % 3) * STAGE_F;
        const float* Bs = As + A_TILE_F;

        #pragma unroll
        for (int ks = 0; ks < 4; ks++) {
            const int kb = ks * 8;
            uint32_t af[4][4], bf[4][2];
            #pragma unroll
            for (int mf = 0; mf < 4; mf++) {
                int r0 = wm * 64 + mf * 16 + lr;
                af[mf][0] = f2tf32(As[r0 * A_STRIDE + kb + lc]);
                af[mf][1] = f2tf32(As[(r0 + 8) * A_STRIDE + kb + lc]);
                af[mf][2] = f2tf32(As[r0 * A_STRIDE + kb + lc + 4]);
                af[mf][3] = f2tf32(As[(r0 + 8) * A_STRIDE + kb + lc + 4]);
            }
            #pragma unroll
            for (int nf = 0; nf < 4; nf++) {
                int c0 = wn * 32 + nf * 8 + lr;
                bf[nf][0] = f2tf32(Bs[(kb + lc) * B_STRIDE + c0]);
                bf[nf][1] = f2tf32(Bs[(kb + lc + 4) * B_STRIDE + c0]);
            }
            #pragma unroll
            for (int mf = 0; mf < 4; mf++)
                #pragma unroll
                for (int nf = 0; nf < 4; nf++)
                    mma_tf32_16x8x8(acc[mf][nf], af[mf], bf[nf]);
        }
        __syncthreads();
    }

    #pragma unroll
    for (int mf = 0; mf < 4; mf++) {
        int row = m0 + wm * 64 + mf * 16 + lr;
        #pragma unroll
        for (int nf = 0; nf < 4; nf++) {
            int col = n0 + wn * 32 + nf * 8 + 2 * lc;
            float b0 = bias[col], b1 = bias[col + 1];
            float2 v0 = make_float2(acc[mf][nf][0] + b0, acc[mf][nf][1] + b1);
            float2 v1 = make_float2(acc[mf][nf][2] + b0, acc[mf][nf][3] + b1);
            *(float2*)&C[(size_t)row * N + col] = v0;
            *(float2*)&C[(size_t)(row + 8) * N + col] = v1;
        }
    }
}

// ---------------------------------------------------------------------------
// Tensor-core causal flash attention (tf32 mma.sync, online softmax).
// Round-6 restructure:
//  - K hi/lo split + V tf32 rounding folded into fragment loads (registers);
//    the separate convert pass and its barrier are GONE.
//  - K/V raw tiles triple-buffered (ring of 3) -> ONE __syncthreads per tile,
//    prefetch(kt+2) issued right after it, overlapping all MMA work.
// smem floats: Qhi/Qlo[128][68], Kraw[3][64*68], Vraw[3][64*72], Ps[128][68]
//   total 52992 floats = 211,968 B (fits 227KB; 1 CTA/SM by design).
// ---------------------------------------------------------------------------
#define ATTN_SMEM ((2*128*68 + 3*64*68 + 3*64*72 + 128*68) * 4)

__global__ __launch_bounds__(256, 1)
void attn_tc(const float* __restrict__ qkv, float* __restrict__ y)
{
    extern __shared__ __align__(16) float sm[];
    float* Qhi  = sm;                        // 128*68
    float* Qlo  = Qhi + 128 * 68;
    float* Kraw = Qlo + 128 * 68;            // 3 x 64*68
    float* Vraw = Kraw + 3 * 64 * 68;        // 3 x 64*72
    float* Ps   = Vraw + 3 * 64 * 72;        // 128*68

    const int qt = 15 - blockIdx.x;          // heavy tiles first
    const int bh = blockIdx.y;
    const int b = bh >> 4, h = bh & 15;
    const int tid = threadIdx.x;
    const int wid = tid >> 5, lane = tid & 31;
    const int lr = lane >> 2, lc = lane & 3;
    const int q0 = qt * 128;
    const int rowbase = b * 2048;
    const int colq = h * 64;

    const uint32_t sbase = smem_u32(sm);
    const uint32_t KrawA = sbase + (uint32_t)((Kraw - sm) * 4);
    const uint32_t VrawA = sbase + (uint32_t)((Vraw - sm) * 4);

    // Load Q (scaled) and split into hi/lo tf32 halves (once per CTA)
    for (int i = tid; i < 128 * 64; i += 256) {
        int r = i >> 6, c = i & 63;
        float x = qkv[(size_t)(rowbase + q0 + r) * 3072 + colq + c] * 0.125f;
        float hi = tf32r(x);
        Qhi[r * 68 + c] = hi;
        Qlo[r * 68 + c] = tf32r(x - hi);
    }

    auto prefetch = [&](int kt) {
        const int buf = kt % 3;
        const uint32_t Kd = KrawA + buf * (64 * 68 * 4);
        const uint32_t Vd = VrawA + buf * (64 * 72 * 4);
        #pragma unroll
        for (int j = 0; j < 4; j++) {
            int s = tid + j * 256;
            int r = s >> 4, c4 = s & 15;
            const float* src = qkv + (size_t)(rowbase + kt * 64 + r) * 3072 + colq + c4 * 4;
            cp_async16(Kd + (r * 68 + c4 * 4) * 4, src + 1024);
            cp_async16(Vd + (r * 72 + c4 * 4) * 4, src + 2048);
        }
        cp_commit();
    };

    const int ktmax = 2 * qt + 1;
    prefetch(0);
    prefetch(1);     // ktmax >= 1 always

    float m_i[2] = {-INFINITY, -INFINITY};
    float l_i[2] = {0.f, 0.f};
    float acc_o[8][4];
    #pragma unroll
    for (int nf = 0; nf < 8; nf++)
        #pragma unroll
        for (int c = 0; c < 4; c++) acc_o[nf][c] = 0.f;

    const int r_row = 16 * wid + lr;
    const int prow = r_row * 68;

    for (int kt = 0; kt <= ktmax; kt++) {
        if (kt == ktmax)
            asm volatile("cp.async.wait_group 0;" ::: "memory");
        else
            asm volatile("cp.async.wait_group 1;" ::: "memory");
        __syncthreads();     // tile kt ready; everyone done with buf (kt+2)%3

        if (kt + 2 <= ktmax) prefetch(kt + 2);

        const float* Kb = Kraw + (kt % 3) * (64 * 68);
        const float* Vb = Vraw + (kt % 3) * (64 * 72);

        // ---- S = Q K^T (split tf32; K split in registers) ----
        float sacc[8][4];
        #pragma unroll
        for (int nf = 0; nf < 8; nf++)
            #pragma unroll
            for (int c = 0; c < 4; c++) sacc[nf][c] = 0.f;

        #pragma unroll
        for (int ks = 0; ks < 8; ks++) {
            const int kb = ks * 8;
            uint32_t ah[4], alo[4];
            const int ra = prow + kb + lc;
            ah[0] = __float_as_uint(Qhi[ra]);
            ah[1] = __float_as_uint(Qhi[ra + 8 * 68]);
            ah[2] = __float_as_uint(Qhi[ra + 4]);
            ah[3] = __float_as_uint(Qhi[ra + 8 * 68 + 4]);
            alo[0] = __float_as_uint(Qlo[ra]);
            alo[1] = __float_as_uint(Qlo[ra + 8 * 68]);
            alo[2] = __float_as_uint(Qlo[ra + 4]);
            alo[3] = __float_as_uint(Qlo[ra + 8 * 68 + 4]);
            #pragma unroll
            for (int nf = 0; nf < 8; nf++) {
                const int cb = (8 * nf + lr) * 68 + kb + lc;
                float x0 = Kb[cb], x1 = Kb[cb + 4];
                float h0 = tf32r(x0), h1 = tf32r(x1);
                uint32_t bhf[2], blf[2];
                bhf[0] = __float_as_uint(h0);
                bhf[1] = __float_as_uint(h1);
                blf[0] = f2tf32(x0 - h0);
                blf[1] = f2tf32(x1 - h1);
                mma_tf32_16x8x8(sacc[nf], ah, bhf);
                mma_tf32_16x8x8(sacc[nf], ah, blf);
                mma_tf32_16x8x8(sacc[nf], alo, bhf);
            }
        }

        // ---- Causal mask (only the 2 diagonal k-tiles) ----
        if (kt >= 2 * qt) {
            const int rg = q0 + r_row;
            const int cb0 = kt * 64 + 2 * lc;
            #pragma unroll
            for (int nf = 0; nf < 8; nf++) {
                int c0 = cb0 + 8 * nf;
                if (c0     > rg)     sacc[nf][0] = -INFINITY;
                if (c0 + 1 > rg)     sacc[nf][1] = -INFINITY;
                if (c0     > rg + 8) sacc[nf][2] = -INFINITY;
                if (c0 + 1 > rg + 8) sacc[nf][3] = -INFINITY;
            }
        }

        // ---- Online softmax (rows within warp; reduce across 4 lanes) ----
        float tm0 = -INFINITY, tm1 = -INFINITY;
        #pragma unroll
        for (int nf = 0; nf < 8; nf++) {
            tm0 = fmaxf(tm0, fmaxf(sacc[nf][0], sacc[nf][1]));
            tm1 = fmaxf(tm1, fmaxf(sacc[nf][2], sacc[nf][3]));
        }
        tm0 = fmaxf(tm0, __shfl_xor_sync(0xffffffffu, tm0, 1));
        tm0 = fmaxf(tm0, __shfl_xor_sync(0xffffffffu, tm0, 2));
        tm1 = fmaxf(tm1, __shfl_xor_sync(0xffffffffu, tm1, 1));
        tm1 = fmaxf(tm1, __shfl_xor_sync(0xffffffffu, tm1, 2));

        const float nm0 = fmaxf(m_i[0], tm0);
        const float nm1 = fmaxf(m_i[1], tm1);
        const float sc0 = __expf(m_i[0] - nm0);
        const float sc1 = __expf(m_i[1] - nm1);
        float rs0 = 0.f, rs1 = 0.f;
        #pragma unroll
        for (int nf = 0; nf < 8; nf++) {
            sacc[nf][0] = __expf(sacc[nf][0] - nm0);
            sacc[nf][1] = __expf(sacc[nf][1] - nm0);
            sacc[nf][2] = __expf(sacc[nf][2] - nm1);
            sacc[nf][3] = __expf(sacc[nf][3] - nm1);
            rs0 += sacc[nf][0] + sacc[nf][1];
            rs1 += sacc[nf][2] + sacc[nf][3];
        }
        rs0 += __shfl_xor_sync(0xffffffffu, rs0, 1);
        rs0 += __shfl_xor_sync(0xffffffffu, rs0, 2);
        rs1 += __shfl_xor_sync(0xffffffffu, rs1, 1);
        rs1 += __shfl_xor_sync(0xffffffffu, rs1, 2);
        l_i[0] = l_i[0] * sc0 + rs0;
        l_i[1] = l_i[1] * sc1 + rs1;
        m_i[0] = nm0;
        m_i[1] = nm1;
        #pragma unroll
        for (int nf = 0; nf < 8; nf++) {
            acc_o[nf][0] *= sc0; acc_o[nf][1] *= sc0;
            acc_o[nf][2] *= sc1; acc_o[nf][3] *= sc1;
        }

        // ---- Stage P through smem (per-warp private rows) ----
        #pragma unroll
        for (int nf = 0; nf < 8; nf++) {
            *(float2*)&Ps[prow + 8 * nf + 2 * lc] =
                make_float2(sacc[nf][0], sacc[nf][1]);
            *(float2*)&Ps[prow + 8 * 68 + 8 * nf + 2 * lc] =
                make_float2(sacc[nf][2], sacc[nf][3]);
        }
        __syncwarp();

        // ---- O += P V (plain tf32; V rounded at load) ----
        #pragma unroll
        for (int ks = 0; ks < 8; ks++) {
            const int kb = ks * 8;
            uint32_t pa[4];
            const int ra = prow + kb + lc;
            pa[0] = f2tf32(Ps[ra]);
            pa[1] = f2tf32(Ps[ra + 8 * 68]);
            pa[2] = f2tf32(Ps[ra + 4]);
            pa[3] = f2tf32(Ps[ra + 8 * 68 + 4]);
            #pragma unroll
            for (int nf = 0; nf < 8; nf++) {
                const int cb = (kb + lc) * 72 + 8 * nf + lr;
                uint32_t vb[2];
                vb[0] = f2tf32(Vb[cb]);
                vb[1] = f2tf32(Vb[cb + 4 * 72]);
                mma_tf32_16x8x8(acc_o[nf], pa, vb);
            }
        }
        __syncwarp();    // P reads done before next iteration's P stores
    }

    // ---- Epilogue: normalize and store ----
    const float il0 = 1.f / l_i[0];
    const float il1 = 1.f / l_i[1];
    const size_t row0 = (size_t)(rowbase + q0 + r_row) * 1024;
    const size_t row1 = row0 + 8 * 1024;
    #pragma unroll
    for (int nf = 0; nf < 8; nf++) {
        int col = colq + 8 * nf + 2 * lc;
        *(float2*)&y[row0 + col] = make_float2(acc_o[nf][0] * il0, acc_o[nf][1] * il0);
        *(float2*)&y[row1 + col] = make_float2(acc_o[nf][2] * il1, acc_o[nf][3] * il1);
    }
}

// ---------------------------------------------------------------------------
extern "C" void kernel_launch(void* const* d_in, const int* in_sizes, int n_in,
                              void* d_out, int out_size)
{
    const float* x     = (const float*)d_in[0];
    const float* w_qkv = (const float*)d_in[1];
    const float* b_qkv = (const float*)d_in[2];
    const float* w_out = (const float*)d_in[3];
    const float* b_out = (const float*)d_in[4];
    float* out = (float*)d_out;

    float* qkv; cudaGetSymbolAddress((void**)&qkv, g_qkv);
    float* yb;  cudaGetSymbolAddress((void**)&yb,  g_y);

    cudaFuncSetAttribute(gemm_tc, cudaFuncAttributeMaxDynamicSharedMemorySize, GEMM_SMEM);
    cudaFuncSetAttribute(attn_tc, cudaFuncAttributeMaxDynamicSharedMemorySize, ATTN_SMEM);

    // 1) QKV projection: [4096,1024] @ [1024,3072] + b  (mma.sync tf32)
    gemm_tc<<<dim3(32, 24), 256, GEMM_SMEM>>>(x, w_qkv, b_qkv, qkv, 4096, 3072, 1024);

    // 2) Causal flash attention (mma.sync tf32, split-tf32 QK^T)
    attn_tc<<<dim3(16, 32), 256, ATTN_SMEM>>>(qkv, yb);

    // 3) Output projection: [4096,1024] @ [1024,1024] + b  (mma.sync tf32)
    gemm_tc<<<dim3(32, 8), 256, GEMM_SMEM>>>(yb, w_out, b_out, out, 4096, 1024, 1024);
}

// round 8
// speedup vs baseline: 3.2493x; 1.0067x over previous
#include <cuda_runtime.h>
#include <math.h>
#include <cstdint>

// Scratch (allocation-free rule: __device__ globals)
__device__ float g_qkv[4096 * 3072];     // 48 MB
__device__ float g_y[4096 * 1024];       // 16 MB
__device__ float g_xr[4096 * 1024];      // 16 MB  (tf32-rounded x)
__device__ float g_wqkvr[1024 * 3072];   // 12 MB  (tf32-rounded w_qkv)
__device__ float g_woutr[1024 * 1024];   //  4 MB  (tf32-rounded w_out)

// ---------------------------------------------------------------------------
// Helpers
// ---------------------------------------------------------------------------
__device__ __forceinline__ uint32_t smem_u32(const void* p) {
    uint32_t a;
    asm("{ .reg .u64 t; cvta.to.shared.u64 t, %1; cvt.u32.u64 %0, t; }"
        : "=r"(a) : "l"(p));
    return a;
}
__device__ __forceinline__ void cp_async16(uint32_t dst, const void* src) {
    asm volatile("cp.async.cg.shared.global [%0], [%1], 16;" :: "r"(dst), "l"(src));
}
__device__ __forceinline__ void cp_commit() {
    asm volatile("cp.async.commit_group;");
}
__device__ __forceinline__ uint32_t f2tf32(float f) {
    uint32_t u;
    asm("cvt.rna.tf32.f32 %0, %1;" : "=r"(u) : "f"(f));
    return u;
}
__device__ __forceinline__ float tf32r(float x) {   // round-to-nearest tf32, as f32
    float r;
    asm("cvt.rna.tf32.f32 %0, %1;" : "=f"(r) : "f"(x));
    return r;
}
__device__ __forceinline__ void mma_tf32_16x8x8(
    float* c, const uint32_t* a, const uint32_t* b) {
    asm volatile(
        "mma.sync.aligned.m16n8k8.row.col.f32.tf32.tf32.f32 "
        "{%0,%1,%2,%3}, {%4,%5,%6,%7}, {%8,%9}, {%0,%1,%2,%3};"
        : "+f"(c[0]), "+f"(c[1]), "+f"(c[2]), "+f"(c[3])
        : "r"(a[0]), "r"(a[1]), "r"(a[2]), "r"(a[3]), "r"(b[0]), "r"(b[1]));
}

// ---------------------------------------------------------------------------
// Pre-round pass: dst[i] = tf32_rna(src[i]).  Idempotent -> deterministic.
// ---------------------------------------------------------------------------
__global__ __launch_bounds__(256) void round_tf32(
    const float* __restrict__ s, float* __restrict__ d, int n4)
{
    int stride = gridDim.x * blockDim.x;
    for (int i = blockIdx.x * blockDim.x + threadIdx.x; i < n4; i += stride) {
        float4 v = ((const float4*)s)[i];
        v.x = tf32r(v.x); v.y = tf32r(v.y); v.z = tf32r(v.z); v.w = tf32r(v.w);
        ((float4*)d)[i] = v;
    }
}

// ---------------------------------------------------------------------------
// tf32 mma.sync GEMM + bias.  Round-8: operands are PRE-ROUNDED to tf32, so
// fragment loads pass raw bits (no cvt in the mainloop).
// ---------------------------------------------------------------------------
#define A_STRIDE 36
#define B_STRIDE 136
#define A_TILE_F (128 * A_STRIDE)
#define B_TILE_F (32 * B_STRIDE)
#define STAGE_F  (A_TILE_F + B_TILE_F)
#define GEMM_SMEM (3 * STAGE_F * 4)

__global__ __launch_bounds__(256, 2)
void gemm_tc(const float* __restrict__ A, const float* __restrict__ B,
             const float* __restrict__ bias, float* __restrict__ C,
             int M, int N, int K)
{
    extern __shared__ __align__(16) float smem[];

    const int tid = threadIdx.x;
    const int wid = tid >> 5, lane = tid & 31;
    const int m0 = blockIdx.x * 128;
    const int n0 = blockIdx.y * 128;
    const int wm = wid & 1;
    const int wn = wid >> 1;

    const uint32_t sbase = smem_u32(smem);

    auto prefetch = [&](int k0, int stage) {
        uint32_t Ad = sbase + stage * STAGE_F * 4;
        uint32_t Bd = Ad + A_TILE_F * 4;
        #pragma unroll
        for (int i = 0; i < 4; i++) {
            int s = tid + i * 256;
            int r = s >> 3, c4 = s & 7;
            cp_async16(Ad + (r * A_STRIDE + c4 * 4) * 4,
                       A + (size_t)(m0 + r) * K + k0 + c4 * 4);
        }
        #pragma unroll
        for (int i = 0; i < 4; i++) {
            int s = tid + i * 256;
            int kr = s >> 5, c4 = s & 31;
            cp_async16(Bd + (kr * B_STRIDE + c4 * 4) * 4,
                       B + (size_t)(k0 + kr) * N + n0 + c4 * 4);
        }
        cp_commit();
    };

    float acc[4][4][4];
    #pragma unroll
    for (int i = 0; i < 4; i++)
        #pragma unroll
        for (int j = 0; j < 4; j++)
            #pragma unroll
            for (int r = 0; r < 4; r++) acc[i][j][r] = 0.f;

    const int NCH = K >> 5;
    prefetch(0, 0);
    if (NCH > 1) prefetch(32, 1);

    const int lr = lane >> 2;
    const int lc = lane & 3;

    for (int c = 0; c < NCH; c++) {
        if (c == NCH - 1)
            asm volatile("cp.async.wait_group 0;" ::: "memory");
        else
            asm volatile("cp.async.wait_group 1;" ::: "memory");
        __syncthreads();

        if (c + 2 < NCH) prefetch((c + 2) * 32, (c + 2) % 3);

        const float* As = smem + (c % 3) * STAGE_F;
        const float* Bs = As + A_TILE_F;

        #pragma unroll
        for (int ks = 0; ks < 4; ks++) {
            const int kb = ks * 8;
            uint32_t af[4][4], bf[4][2];
            #pragma unroll
            for (int mf = 0; mf < 4; mf++) {
                int r0 = wm * 64 + mf * 16 + lr;
                af[mf][0] = __float_as_uint(As[r0 * A_STRIDE + kb + lc]);
                af[mf][1] = __float_as_uint(As[(r0 + 8) * A_STRIDE + kb + lc]);
                af[mf][2] = __float_as_uint(As[r0 * A_STRIDE + kb + lc + 4]);
                af[mf][3] = __float_as_uint(As[(r0 + 8) * A_STRIDE + kb + lc + 4]);
            }
            #pragma unroll
            for (int nf = 0; nf < 4; nf++) {
                int c0 = wn * 32 + nf * 8 + lr;
                bf[nf][0] = __float_as_uint(Bs[(kb + lc) * B_STRIDE + c0]);
                bf[nf][1] = __float_as_uint(Bs[(kb + lc + 4) * B_STRIDE + c0]);
            }
            #pragma unroll
            for (int mf = 0; mf < 4; mf++)
                #pragma unroll
                for (int nf = 0; nf < 4; nf++)
                    mma_tf32_16x8x8(acc[mf][nf], af[mf], bf[nf]);
        }
        __syncthreads();
    }

    #pragma unroll
    for (int mf = 0; mf < 4; mf++) {
        int row = m0 + wm * 64 + mf * 16 + lr;
        #pragma unroll
        for (int nf = 0; nf < 4; nf++) {
            int col = n0 + wn * 32 + nf * 8 + 2 * lc;
            float b0 = bias[col], b1 = bias[col + 1];
            float2 v0 = make_float2(acc[mf][nf][0] + b0, acc[mf][nf][1] + b1);
            float2 v1 = make_float2(acc[mf][nf][2] + b0, acc[mf][nf][3] + b1);
            *(float2*)&C[(size_t)row * N + col] = v0;
            *(float2*)&C[(size_t)(row + 8) * N + col] = v1;
        }
    }
}

// ---------------------------------------------------------------------------
// Tensor-core causal flash attention (tf32 mma.sync, online softmax).
// Round-8: 2 CTAs/SM.  smem = Qraw[128][68] + K ring2[64][68] + V ring2[64][72]
// = 106,496 B.  Q hi/lo split done in registers at fragment load; P moved from
// C-fragment to A-fragment layout via register shuffles (no Ps array).
// ---------------------------------------------------------------------------
#define ATTN_SMEM ((128*68 + 2*64*68 + 2*64*72) * 4)

__global__ __launch_bounds__(256, 2)
void attn_tc(const float* __restrict__ qkv, float* __restrict__ y)
{
    extern __shared__ __align__(16) float sm[];
    float* Qr = sm;                      // 128*68
    float* Kr = Qr + 128 * 68;           // 2 x 64*68
    float* Vr = Kr + 2 * 64 * 68;        // 2 x 64*72

    const int qt = 15 - blockIdx.x;      // heavy tiles first
    const int bh = blockIdx.y;
    const int b = bh >> 4, h = bh & 15;
    const int tid = threadIdx.x;
    const int wid = tid >> 5, lane = tid & 31;
    const int lr = lane >> 2, lc = lane & 3;
    const int q0 = qt * 128;
    const int rowbase = b * 2048;
    const int colq = h * 64;

    const uint32_t sbase = smem_u32(sm);
    const uint32_t KrA = sbase + 128 * 68 * 4;
    const uint32_t VrA = KrA + 2 * 64 * 68 * 4;

    // Load Q (scaled, raw fp32)
    for (int i = tid; i < 128 * 64; i += 256) {
        int r = i >> 6, c = i & 63;
        Qr[r * 68 + c] = qkv[(size_t)(rowbase + q0 + r) * 3072 + colq + c] * 0.125f;
    }

    auto prefetch = [&](int kt) {
        const int buf = kt & 1;
        const uint32_t Kd = KrA + buf * (64 * 68 * 4);
        const uint32_t Vd = VrA + buf * (64 * 72 * 4);
        #pragma unroll
        for (int j = 0; j < 4; j++) {
            int s = tid + j * 256;
            int r = s >> 4, c4 = s & 15;
            const float* src = qkv + (size_t)(rowbase + kt * 64 + r) * 3072 + colq + c4 * 4;
            cp_async16(Kd + (r * 68 + c4 * 4) * 4, src + 1024);
            cp_async16(Vd + (r * 72 + c4 * 4) * 4, src + 2048);
        }
        cp_commit();
    };

    const int ktmax = 2 * qt + 1;
    prefetch(0);

    float m_i[2] = {-INFINITY, -INFINITY};
    float l_i[2] = {0.f, 0.f};
    float acc_o[8][4];
    #pragma unroll
    for (int nf = 0; nf < 8; nf++)
        #pragma unroll
        for (int c = 0; c < 4; c++) acc_o[nf][c] = 0.f;

    const int r_row = 16 * wid + lr;

    for (int kt = 0; kt <= ktmax; kt++) {
        asm volatile("cp.async.wait_group 0;" ::: "memory");
        __syncthreads();     // tile kt ready; all warps done reading buf kt^1

        if (kt + 1 <= ktmax) prefetch(kt + 1);

        const float* Kb = Kr + (kt & 1) * (64 * 68);
        const float* Vb = Vr + (kt & 1) * (64 * 72);

        // ---- S = Q K^T (split tf32; Q and K split in registers) ----
        float sacc[8][4];
        #pragma unroll
        for (int nf = 0; nf < 8; nf++)
            #pragma unroll
            for (int c = 0; c < 4; c++) sacc[nf][c] = 0.f;

        #pragma unroll
        for (int ks = 0; ks < 8; ks++) {
            const int kb = ks * 8;
            const int ra = r_row * 68 + kb + lc;
            float xq0 = Qr[ra];
            float xq1 = Qr[ra + 8 * 68];
            float xq2 = Qr[ra + 4];
            float xq3 = Qr[ra + 8 * 68 + 4];
            float qh0 = tf32r(xq0), qh1 = tf32r(xq1);
            float qh2 = tf32r(xq2), qh3 = tf32r(xq3);
            uint32_t ah[4], alo[4];
            ah[0] = __float_as_uint(qh0); ah[1] = __float_as_uint(qh1);
            ah[2] = __float_as_uint(qh2); ah[3] = __float_as_uint(qh3);
            alo[0] = f2tf32(xq0 - qh0); alo[1] = f2tf32(xq1 - qh1);
            alo[2] = f2tf32(xq2 - qh2); alo[3] = f2tf32(xq3 - qh3);
            #pragma unroll
            for (int nf = 0; nf < 8; nf++) {
                const int cb = (8 * nf + lr) * 68 + kb + lc;
                float x0 = Kb[cb], x1 = Kb[cb + 4];
                float h0 = tf32r(x0), h1 = tf32r(x1);
                uint32_t bhf[2], blf[2];
                bhf[0] = __float_as_uint(h0);
                bhf[1] = __float_as_uint(h1);
                blf[0] = f2tf32(x0 - h0);
                blf[1] = f2tf32(x1 - h1);
                mma_tf32_16x8x8(sacc[nf], ah, bhf);
                mma_tf32_16x8x8(sacc[nf], ah, blf);
                mma_tf32_16x8x8(sacc[nf], alo, bhf);
            }
        }

        // ---- Causal mask (only the 2 diagonal k-tiles) ----
        if (kt >= 2 * qt) {
            const int rg = q0 + r_row;
            const int cb0 = kt * 64 + 2 * lc;
            #pragma unroll
            for (int nf = 0; nf < 8; nf++) {
                int c0 = cb0 + 8 * nf;
                if (c0     > rg)     sacc[nf][0] = -INFINITY;
                if (c0 + 1 > rg)     sacc[nf][1] = -INFINITY;
                if (c0     > rg + 8) sacc[nf][2] = -INFINITY;
                if (c0 + 1 > rg + 8) sacc[nf][3] = -INFINITY;
            }
        }

        // ---- Online softmax (rows within warp; reduce across 4 lanes) ----
        float tm0 = -INFINITY, tm1 = -INFINITY;
        #pragma unroll
        for (int nf = 0; nf < 8; nf++) {
            tm0 = fmaxf(tm0, fmaxf(sacc[nf][0], sacc[nf][1]));
            tm1 = fmaxf(tm1, fmaxf(sacc[nf][2], sacc[nf][3]));
        }
        tm0 = fmaxf(tm0, __shfl_xor_sync(0xffffffffu, tm0, 1));
        tm0 = fmaxf(tm0, __shfl_xor_sync(0xffffffffu, tm0, 2));
        tm1 = fmaxf(tm1, __shfl_xor_sync(0xffffffffu, tm1, 1));
        tm1 = fmaxf(tm1, __shfl_xor_sync(0xffffffffu, tm1, 2));

        const float nm0 = fmaxf(m_i[0], tm0);
        const float nm1 = fmaxf(m_i[1], tm1);
        const float sc0 = __expf(m_i[0] - nm0);
        const float sc1 = __expf(m_i[1] - nm1);
        float rs0 = 0.f, rs1 = 0.f;
        #pragma unroll
        for (int nf = 0; nf < 8; nf++) {
            sacc[nf][0] = __expf(sacc[nf][0] - nm0);
            sacc[nf][1] = __expf(sacc[nf][1] - nm0);
            sacc[nf][2] = __expf(sacc[nf][2] - nm1);
            sacc[nf][3] = __expf(sacc[nf][3] - nm1);
            rs0 += sacc[nf][0] + sacc[nf][1];
            rs1 += sacc[nf][2] + sacc[nf][3];
        }
        rs0 += __shfl_xor_sync(0xffffffffu, rs0, 1);
        rs0 += __shfl_xor_sync(0xffffffffu, rs0, 2);
        rs1 += __shfl_xor_sync(0xffffffffu, rs1, 1);
        rs1 += __shfl_xor_sync(0xffffffffu, rs1, 2);
        l_i[0] = l_i[0] * sc0 + rs0;
        l_i[1] = l_i[1] * sc1 + rs1;
        m_i[0] = nm0;
        m_i[1] = nm1;
        #pragma unroll
        for (int nf = 0; nf < 8; nf++) {
            acc_o[nf][0] *= sc0; acc_o[nf][1] *= sc0;
            acc_o[nf][2] *= sc1; acc_o[nf][3] *= sc1;
        }

        // ---- O += P V ----
        // P is in C-fragment layout (row r_row/+8, col 8nf+2lc+{0,1}).
        // A-fragment for column c needs owner lane 4*lr + ((c&7)>>1), register
        // selected by (c&1) and row half. Two shuffles + select per value.
        #pragma unroll
        for (int ks = 0; ks < 8; ks++) {
            const int kb = ks * 8;
            const int srcL = 4 * lr + (lc >> 1);
            const int srcH = srcL + 2;
            const bool odd = lc & 1;
            float p00 = __shfl_sync(0xffffffffu, sacc[ks][0], srcL);
            float p01 = __shfl_sync(0xffffffffu, sacc[ks][1], srcL);
            float p20 = __shfl_sync(0xffffffffu, sacc[ks][2], srcL);
            float p21 = __shfl_sync(0xffffffffu, sacc[ks][3], srcL);
            float q00 = __shfl_sync(0xffffffffu, sacc[ks][0], srcH);
            float q01 = __shfl_sync(0xffffffffu, sacc[ks][1], srcH);
            float q20 = __shfl_sync(0xffffffffu, sacc[ks][2], srcH);
            float q21 = __shfl_sync(0xffffffffu, sacc[ks][3], srcH);
            uint32_t pa[4];
            pa[0] = f2tf32(odd ? p01 : p00);    // row lr,   col kb+lc
            pa[1] = f2tf32(odd ? p21 : p20);    // row lr+8, col kb+lc
            pa[2] = f2tf32(odd ? q01 : q00);    // row lr,   col kb+lc+4
            pa[3] = f2tf32(odd ? q21 : q20);    // row lr+8, col kb+lc+4
            #pragma unroll
            for (int nf = 0; nf < 8; nf++) {
                const int cb = (kb + lc) * 72 + 8 * nf + lr;
                uint32_t vb[2];
                vb[0] = f2tf32(Vb[cb]);
                vb[1] = f2tf32(Vb[cb + 4 * 72]);
                mma_tf32_16x8x8(acc_o[nf], pa, vb);
            }
        }
    }

    // ---- Epilogue: normalize, round to tf32 (out-proj A operand), store ----
    const float il0 = 1.f / l_i[0];
    const float il1 = 1.f / l_i[1];
    const size_t row0 = (size_t)(rowbase + q0 + r_row) * 1024;
    const size_t row1 = row0 + 8 * 1024;
    #pragma unroll
    for (int nf = 0; nf < 8; nf++) {
        int col = colq + 8 * nf + 2 * lc;
        *(float2*)&y[row0 + col] = make_float2(tf32r(acc_o[nf][0] * il0),
                                               tf32r(acc_o[nf][1] * il0));
        *(float2*)&y[row1 + col] = make_float2(tf32r(acc_o[nf][2] * il1),
                                               tf32r(acc_o[nf][3] * il1));
    }
}

// ---------------------------------------------------------------------------
extern "C" void kernel_launch(void* const* d_in, const int* in_sizes, int n_in,
                              void* d_out, int out_size)
{
    const float* x     = (const float*)d_in[0];
    const float* w_qkv = (const float*)d_in[1];
    const float* b_qkv = (const float*)d_in[2];
    const float* w_out = (const float*)d_in[3];
    const float* b_out = (const float*)d_in[4];
    float* out = (float*)d_out;

    float* qkv;  cudaGetSymbolAddress((void**)&qkv,  g_qkv);
    float* yb;   cudaGetSymbolAddress((void**)&yb,   g_y);
    float* xr;   cudaGetSymbolAddress((void**)&xr,   g_xr);
    float* wqr;  cudaGetSymbolAddress((void**)&wqr,  g_wqkvr);
    float* wor;  cudaGetSymbolAddress((void**)&wor,  g_woutr);

    cudaFuncSetAttribute(gemm_tc, cudaFuncAttributeMaxDynamicSharedMemorySize, GEMM_SMEM);
    cudaFuncSetAttribute(attn_tc, cudaFuncAttributeMaxDynamicSharedMemorySize, ATTN_SMEM);

    // 0) Pre-round operands to tf32 (RNA) once
    round_tf32<<<1184, 256>>>(x,     xr,  4096 * 1024 / 4);
    round_tf32<<<1184, 256>>>(w_qkv, wqr, 1024 * 3072 / 4);
    round_tf32<<<1184, 256>>>(w_out, wor, 1024 * 1024 / 4);

    // 1) QKV projection: [4096,1024] @ [1024,3072] + b  (mma.sync tf32)
    gemm_tc<<<dim3(32, 24), 256, GEMM_SMEM>>>(xr, wqr, b_qkv, qkv, 4096, 3072, 1024);

    // 2) Causal flash attention (mma.sync tf32, split-tf32 QK^T)
    attn_tc<<<dim3(16, 32), 256, ATTN_SMEM>>>(qkv, yb);

    // 3) Output projection: [4096,1024] @ [1024,1024] + b  (mma.sync tf32)
    gemm_tc<<<dim3(32, 8), 256, GEMM_SMEM>>>(yb, wor, b_out, out, 4096, 1024, 1024);
}

// round 9
// speedup vs baseline: 4.1086x; 1.2644x over previous
#include <cuda_runtime.h>
#include <cuda_fp16.h>
#include <math.h>
#include <cstdint>

// Scratch (allocation-free rule: __device__ globals)
__device__ __half g_qhi[4096 * 1024];    // Q hi halves (pre-scaled by 0.125)
__device__ __half g_qlo[4096 * 1024];    // Q lo halves
__device__ __half g_khi[4096 * 1024];    // K hi halves
__device__ __half g_klo[4096 * 1024];    // K lo halves
__device__ float  g_v[4096 * 1024];      // V fp32
__device__ float  g_y[4096 * 1024];      // attention output (tf32-rounded)
__device__ float  g_xr[4096 * 1024];     // tf32-rounded x
__device__ float  g_wqkvr[1024 * 3072];  // tf32-rounded w_qkv
__device__ float  g_woutr[1024 * 1024];  // tf32-rounded w_out

// ---------------------------------------------------------------------------
// Helpers
// ---------------------------------------------------------------------------
__device__ __forceinline__ uint32_t smem_u32(const void* p) {
    uint32_t a;
    asm("{ .reg .u64 t; cvta.to.shared.u64 t, %1; cvt.u32.u64 %0, t; }"
        : "=r"(a) : "l"(p));
    return a;
}
__device__ __forceinline__ void cp_async16(uint32_t dst, const void* src) {
    asm volatile("cp.async.cg.shared.global [%0], [%1], 16;" :: "r"(dst), "l"(src));
}
__device__ __forceinline__ void cp_commit() {
    asm volatile("cp.async.commit_group;");
}
__device__ __forceinline__ uint32_t f2tf32(float f) {
    uint32_t u;
    asm("cvt.rna.tf32.f32 %0, %1;" : "=r"(u) : "f"(f));
    return u;
}
__device__ __forceinline__ float tf32r(float x) {
    float r;
    asm("cvt.rna.tf32.f32 %0, %1;" : "=f"(r) : "f"(x));
    return r;
}
__device__ __forceinline__ void mma_tf32_16x8x8(
    float* c, const uint32_t* a, const uint32_t* b) {
    asm volatile(
        "mma.sync.aligned.m16n8k8.row.col.f32.tf32.tf32.f32 "
        "{%0,%1,%2,%3}, {%4,%5,%6,%7}, {%8,%9}, {%0,%1,%2,%3};"
        : "+f"(c[0]), "+f"(c[1]), "+f"(c[2]), "+f"(c[3])
        : "r"(a[0]), "r"(a[1]), "r"(a[2]), "r"(a[3]), "r"(b[0]), "r"(b[1]));
}
__device__ __forceinline__ void mma_f16_16x8x16(
    float* c, const uint32_t* a, const uint32_t* b) {
    asm volatile(
        "mma.sync.aligned.m16n8k16.row.col.f32.f16.f16.f32 "
        "{%0,%1,%2,%3}, {%4,%5,%6,%7}, {%8,%9}, {%0,%1,%2,%3};"
        : "+f"(c[0]), "+f"(c[1]), "+f"(c[2]), "+f"(c[3])
        : "r"(a[0]), "r"(a[1]), "r"(a[2]), "r"(a[3]), "r"(b[0]), "r"(b[1]));
}

// Split a float pair to fp16 hi/lo planes (Markidis): hi+lo carries ~22 bits.
__device__ __forceinline__ void store_split(
    __half* hp, __half* lp, size_t idx, float x, float yv)
{
    __half hx = __float2half_rn(x),  hy = __float2half_rn(yv);
    __half lx = __float2half_rn(x  - __half2float(hx));
    __half ly = __float2half_rn(yv - __half2float(hy));
    *(__half2*)&hp[idx] = __halves2half2(hx, hy);
    *(__half2*)&lp[idx] = __halves2half2(lx, ly);
}

// ---------------------------------------------------------------------------
// Pre-round pass: dst[i] = tf32_rna(src[i]).
// ---------------------------------------------------------------------------
__global__ __launch_bounds__(256) void round_tf32(
    const float* __restrict__ s, float* __restrict__ d, int n4)
{
    int stride = gridDim.x * blockDim.x;
    for (int i = blockIdx.x * blockDim.x + threadIdx.x; i < n4; i += stride) {
        float4 v = ((const float4*)s)[i];
        v.x = tf32r(v.x); v.y = tf32r(v.y); v.z = tf32r(v.z); v.w = tf32r(v.w);
        ((float4*)d)[i] = v;
    }
}

// ---------------------------------------------------------------------------
// tf32 mma.sync GEMM + bias.  split_mode=1: epilogue routes columns to
// Q(hi/lo, pre-scaled 0.125) / K(hi/lo) / V(f32) planes for attention.
// ---------------------------------------------------------------------------
#define A_STRIDE 36
#define B_STRIDE 136
#define A_TILE_F (128 * A_STRIDE)
#define B_TILE_F (32 * B_STRIDE)
#define STAGE_F  (A_TILE_F + B_TILE_F)
#define GEMM_SMEM (3 * STAGE_F * 4)

__global__ __launch_bounds__(256, 2)
void gemm_tc(const float* __restrict__ A, const float* __restrict__ B,
             const float* __restrict__ bias, float* __restrict__ C,
             int M, int N, int K,
             __half* qhi, __half* qlo, __half* khi, __half* klo,
             float* vplane, int split_mode)
{
    extern __shared__ __align__(16) float smem[];

    const int tid = threadIdx.x;
    const int wid = tid >> 5, lane = tid & 31;
    const int m0 = blockIdx.x * 128;
    const int n0 = blockIdx.y * 128;
    const int wm = wid & 1;
    const int wn = wid >> 1;

    const uint32_t sbase = smem_u32(smem);

    auto prefetch = [&](int k0, int stage) {
        uint32_t Ad = sbase + stage * STAGE_F * 4;
        uint32_t Bd = Ad + A_TILE_F * 4;
        #pragma unroll
        for (int i = 0; i < 4; i++) {
            int s = tid + i * 256;
            int r = s >> 3, c4 = s & 7;
            cp_async16(Ad + (r * A_STRIDE + c4 * 4) * 4,
                       A + (size_t)(m0 + r) * K + k0 + c4 * 4);
        }
        #pragma unroll
        for (int i = 0; i < 4; i++) {
            int s = tid + i * 256;
            int kr = s >> 5, c4 = s & 31;
            cp_async16(Bd + (kr * B_STRIDE + c4 * 4) * 4,
                       B + (size_t)(k0 + kr) * N + n0 + c4 * 4);
        }
        cp_commit();
    };

    float acc[4][4][4];
    #pragma unroll
    for (int i = 0; i < 4; i++)
        #pragma unroll
        for (int j = 0; j < 4; j++)
            #pragma unroll
            for (int r = 0; r < 4; r++) acc[i][j][r] = 0.f;

    const int NCH = K >> 5;
    prefetch(0, 0);
    if (NCH > 1) prefetch(32, 1);

    const int lr = lane >> 2;
    const int lc = lane & 3;

    for (int c = 0; c < NCH; c++) {
        if (c == NCH - 1)
            asm volatile("cp.async.wait_group 0;" ::: "memory");
        else
            asm volatile("cp.async.wait_group 1;" ::: "memory");
        __syncthreads();

        if (c + 2 < NCH) prefetch((c + 2) * 32, (c + 2) % 3);

        const float* As = smem + (c % 3) * STAGE_F;
        const float* Bs = As + A_TILE_F;

        #pragma unroll
        for (int ks = 0; ks < 4; ks++) {
            const int kb = ks * 8;
            uint32_t af[4][4], bf[4][2];
            #pragma unroll
            for (int mf = 0; mf < 4; mf++) {
                int r0 = wm * 64 + mf * 16 + lr;
                af[mf][0] = __float_as_uint(As[r0 * A_STRIDE + kb + lc]);
                af[mf][1] = __float_as_uint(As[(r0 + 8) * A_STRIDE + kb + lc]);
                af[mf][2] = __float_as_uint(As[r0 * A_STRIDE + kb + lc + 4]);
                af[mf][3] = __float_as_uint(As[(r0 + 8) * A_STRIDE + kb + lc + 4]);
            }
            #pragma unroll
            for (int nf = 0; nf < 4; nf++) {
                int c0 = wn * 32 + nf * 8 + lr;
                bf[nf][0] = __float_as_uint(Bs[(kb + lc) * B_STRIDE + c0]);
                bf[nf][1] = __float_as_uint(Bs[(kb + lc + 4) * B_STRIDE + c0]);
            }
            #pragma unroll
            for (int mf = 0; mf < 4; mf++)
                #pragma unroll
                for (int nf = 0; nf < 4; nf++)
                    mma_tf32_16x8x8(acc[mf][nf], af[mf], bf[nf]);
        }
        __syncthreads();
    }

    #pragma unroll
    for (int mf = 0; mf < 4; mf++) {
        int row = m0 + wm * 64 + mf * 16 + lr;
        #pragma unroll
        for (int nf = 0; nf < 4; nf++) {
            int col = n0 + wn * 32 + nf * 8 + 2 * lc;
            float b0 = bias[col], b1 = bias[col + 1];
            float v00 = acc[mf][nf][0] + b0, v01 = acc[mf][nf][1] + b1;
            float v10 = acc[mf][nf][2] + b0, v11 = acc[mf][nf][3] + b1;
            if (!split_mode) {
                *(float2*)&C[(size_t)row * N + col] = make_float2(v00, v01);
                *(float2*)&C[(size_t)(row + 8) * N + col] = make_float2(v10, v11);
            } else if (col < 1024) {         // Q plane, fold 1/sqrt(hd)
                store_split(qhi, qlo, (size_t)row * 1024 + col,
                            v00 * 0.125f, v01 * 0.125f);
                store_split(qhi, qlo, (size_t)(row + 8) * 1024 + col,
                            v10 * 0.125f, v11 * 0.125f);
            } else if (col < 2048) {         // K plane
                store_split(khi, klo, (size_t)row * 1024 + col - 1024, v00, v01);
                store_split(khi, klo, (size_t)(row + 8) * 1024 + col - 1024, v10, v11);
            } else {                         // V plane (f32)
                *(float2*)&vplane[(size_t)row * 1024 + col - 2048] = make_float2(v00, v01);
                *(float2*)&vplane[(size_t)(row + 8) * 1024 + col - 2048] = make_float2(v10, v11);
            }
        }
    }
}

// ---------------------------------------------------------------------------
// Tensor-core causal flash attention.
// Round-9: QK^T via fp16 Markidis split (m16n8k16, 3 MMAs per k16) with Q/K
// PRE-SPLIT into hi/lo half planes by the QKV GEMM epilogue — zero conversion
// math in the mainloop.  PV stays tf32 (proven round-8 path).
// smem: Qh/Ql[128][72]h, Kh/Kl ring2 [64][72]h, V ring2 [64][72]f  = 110,592 B.
// ---------------------------------------------------------------------------
#define ATTN_SMEM 110592

__global__ __launch_bounds__(256, 2)
void attn_tc(const __half* __restrict__ qh_g, const __half* __restrict__ ql_g,
             const __half* __restrict__ kh_g, const __half* __restrict__ kl_g,
             const float*  __restrict__ v_g,  float* __restrict__ y)
{
    extern __shared__ __align__(16) char smraw[];
    __half* Qh = (__half*)smraw;                 // 128*72
    __half* Ql = Qh + 128 * 72;
    __half* Kh = Ql + 128 * 72;                  // 2 x 64*72
    __half* Kl = Kh + 2 * 64 * 72;
    float*  Vs = (float*)(Kl + 2 * 64 * 72);     // 2 x 64*72

    const int qt = 15 - blockIdx.x;              // heavy tiles first
    const int bh = blockIdx.y;
    const int b = bh >> 4, h = bh & 15;
    const int tid = threadIdx.x;
    const int wid = tid >> 5, lane = tid & 31;
    const int lr = lane >> 2, lc = lane & 3;
    const int q0 = qt * 128;
    const int rowbase = b * 2048;
    const int colq = h * 64;

    const uint32_t sbase = smem_u32(smraw);
    const uint32_t QhA = sbase;
    const uint32_t QlA = QhA + 128 * 72 * 2;
    const uint32_t KhA = QlA + 128 * 72 * 2;
    const uint32_t KlA = KhA + 2 * 64 * 72 * 2;
    const uint32_t VA  = KlA + 2 * 64 * 72 * 2;

    // Async-load Q hi/lo tiles (128 rows x 64 halves each)
    #pragma unroll
    for (int j = 0; j < 4; j++) {
        int s = tid + j * 256;
        int r = s >> 3, seg = s & 7;
        size_t g = (size_t)(rowbase + q0 + r) * 1024 + colq + seg * 8;
        cp_async16(QhA + (r * 72 + seg * 8) * 2, qh_g + g);
        cp_async16(QlA + (r * 72 + seg * 8) * 2, ql_g + g);
    }
    cp_commit();

    auto prefetch = [&](int kt) {
        const int buf = kt & 1;
        const uint32_t Khd = KhA + buf * (64 * 72 * 2);
        const uint32_t Kld = KlA + buf * (64 * 72 * 2);
        const uint32_t Vd  = VA  + buf * (64 * 72 * 4);
        #pragma unroll
        for (int j = 0; j < 2; j++) {
            int s = tid + j * 256;
            int r = s >> 3, seg = s & 7;
            size_t g = (size_t)(rowbase + kt * 64 + r) * 1024 + colq + seg * 8;
            cp_async16(Khd + (r * 72 + seg * 8) * 2, kh_g + g);
            cp_async16(Kld + (r * 72 + seg * 8) * 2, kl_g + g);
        }
        #pragma unroll
        for (int j = 0; j < 4; j++) {
            int s = tid + j * 256;
            int r = s >> 4, seg = s & 15;
            cp_async16(Vd + (r * 72 + seg * 4) * 4,
                       v_g + (size_t)(rowbase + kt * 64 + r) * 1024 + colq + seg * 4);
        }
        cp_commit();
    };

    const int ktmax = 2 * qt + 1;
    prefetch(0);

    float m_i[2] = {-INFINITY, -INFINITY};
    float l_i[2] = {0.f, 0.f};
    float acc_o[8][4];
    #pragma unroll
    for (int nf = 0; nf < 8; nf++)
        #pragma unroll
        for (int c = 0; c < 4; c++) acc_o[nf][c] = 0.f;

    const int r_row = 16 * wid + lr;

    for (int kt = 0; kt <= ktmax; kt++) {
        asm volatile("cp.async.wait_group 0;" ::: "memory");
        __syncthreads();     // tile kt (and Q on kt=0) ready; buf kt^1 free

        if (kt + 1 <= ktmax) prefetch(kt + 1);

        const __half* Khb = Kh + (kt & 1) * (64 * 72);
        const __half* Klb = Kl + (kt & 1) * (64 * 72);
        const float*  Vb  = Vs + (kt & 1) * (64 * 72);

        // ---- S = Q K^T : fp16 Markidis split, m16n8k16, 4 k-steps ----
        float sacc[8][4];
        #pragma unroll
        for (int nf = 0; nf < 8; nf++)
            #pragma unroll
            for (int c = 0; c < 4; c++) sacc[nf][c] = 0.f;

        #pragma unroll
        for (int ks = 0; ks < 4; ks++) {
            const int kb = ks * 16;
            const int ra = r_row * 72 + kb + 2 * lc;
            uint32_t ah[4], al[4];
            ah[0] = *(const uint32_t*)&Qh[ra];
            ah[1] = *(const uint32_t*)&Qh[ra + 8 * 72];
            ah[2] = *(const uint32_t*)&Qh[ra + 8];
            ah[3] = *(const uint32_t*)&Qh[ra + 8 * 72 + 8];
            al[0] = *(const uint32_t*)&Ql[ra];
            al[1] = *(const uint32_t*)&Ql[ra + 8 * 72];
            al[2] = *(const uint32_t*)&Ql[ra + 8];
            al[3] = *(const uint32_t*)&Ql[ra + 8 * 72 + 8];
            #pragma unroll
            for (int nf = 0; nf < 8; nf++) {
                const int cb = (8 * nf + lr) * 72 + kb + 2 * lc;
                uint32_t bh2[2], bl2[2];
                bh2[0] = *(const uint32_t*)&Khb[cb];
                bh2[1] = *(const uint32_t*)&Khb[cb + 8];
                bl2[0] = *(const uint32_t*)&Klb[cb];
                bl2[1] = *(const uint32_t*)&Klb[cb + 8];
                mma_f16_16x8x16(sacc[nf], ah, bh2);
                mma_f16_16x8x16(sacc[nf], ah, bl2);
                mma_f16_16x8x16(sacc[nf], al, bh2);
            }
        }

        // ---- Causal mask (only the 2 diagonal k-tiles) ----
        if (kt >= 2 * qt) {
            const int rg = q0 + r_row;
            const int cb0 = kt * 64 + 2 * lc;
            #pragma unroll
            for (int nf = 0; nf < 8; nf++) {
                int c0 = cb0 + 8 * nf;
                if (c0     > rg)     sacc[nf][0] = -INFINITY;
                if (c0 + 1 > rg)     sacc[nf][1] = -INFINITY;
                if (c0     > rg + 8) sacc[nf][2] = -INFINITY;
                if (c0 + 1 > rg + 8) sacc[nf][3] = -INFINITY;
            }
        }

        // ---- Online softmax ----
        float tm0 = -INFINITY, tm1 = -INFINITY;
        #pragma unroll
        for (int nf = 0; nf < 8; nf++) {
            tm0 = fmaxf(tm0, fmaxf(sacc[nf][0], sacc[nf][1]));
            tm1 = fmaxf(tm1, fmaxf(sacc[nf][2], sacc[nf][3]));
        }
        tm0 = fmaxf(tm0, __shfl_xor_sync(0xffffffffu, tm0, 1));
        tm0 = fmaxf(tm0, __shfl_xor_sync(0xffffffffu, tm0, 2));
        tm1 = fmaxf(tm1, __shfl_xor_sync(0xffffffffu, tm1, 1));
        tm1 = fmaxf(tm1, __shfl_xor_sync(0xffffffffu, tm1, 2));

        const float nm0 = fmaxf(m_i[0], tm0);
        const float nm1 = fmaxf(m_i[1], tm1);
        const float sc0 = __expf(m_i[0] - nm0);
        const float sc1 = __expf(m_i[1] - nm1);
        float rs0 = 0.f, rs1 = 0.f;
        #pragma unroll
        for (int nf = 0; nf < 8; nf++) {
            sacc[nf][0] = __expf(sacc[nf][0] - nm0);
            sacc[nf][1] = __expf(sacc[nf][1] - nm0);
            sacc[nf][2] = __expf(sacc[nf][2] - nm1);
            sacc[nf][3] = __expf(sacc[nf][3] - nm1);
            rs0 += sacc[nf][0] + sacc[nf][1];
            rs1 += sacc[nf][2] + sacc[nf][3];
        }
        rs0 += __shfl_xor_sync(0xffffffffu, rs0, 1);
        rs0 += __shfl_xor_sync(0xffffffffu, rs0, 2);
        rs1 += __shfl_xor_sync(0xffffffffu, rs1, 1);
        rs1 += __shfl_xor_sync(0xffffffffu, rs1, 2);
        l_i[0] = l_i[0] * sc0 + rs0;
        l_i[1] = l_i[1] * sc1 + rs1;
        m_i[0] = nm0;
        m_i[1] = nm1;
        #pragma unroll
        for (int nf = 0; nf < 8; nf++) {
            acc_o[nf][0] *= sc0; acc_o[nf][1] *= sc0;
            acc_o[nf][2] *= sc1; acc_o[nf][3] *= sc1;
        }

        // ---- O += P V (tf32; P via register shuffles, proven round-8) ----
        #pragma unroll
        for (int ks = 0; ks < 8; ks++) {
            const int kb = ks * 8;
            const int srcL = 4 * lr + (lc >> 1);
            const int srcH = srcL + 2;
            const bool odd = lc & 1;
            float p00 = __shfl_sync(0xffffffffu, sacc[ks][0], srcL);
            float p01 = __shfl_sync(0xffffffffu, sacc[ks][1], srcL);
            float p20 = __shfl_sync(0xffffffffu, sacc[ks][2], srcL);
            float p21 = __shfl_sync(0xffffffffu, sacc[ks][3], srcL);
            float q00 = __shfl_sync(0xffffffffu, sacc[ks][0], srcH);
            float q01 = __shfl_sync(0xffffffffu, sacc[ks][1], srcH);
            float q20 = __shfl_sync(0xffffffffu, sacc[ks][2], srcH);
            float q21 = __shfl_sync(0xffffffffu, sacc[ks][3], srcH);
            uint32_t pa[4];
            pa[0] = f2tf32(odd ? p01 : p00);
            pa[1] = f2tf32(odd ? p21 : p20);
            pa[2] = f2tf32(odd ? q01 : q00);
            pa[3] = f2tf32(odd ? q21 : q20);
            #pragma unroll
            for (int nf = 0; nf < 8; nf++) {
                const int cb = (kb + lc) * 72 + 8 * nf + lr;
                uint32_t vb[2];
                vb[0] = f2tf32(Vb[cb]);
                vb[1] = f2tf32(Vb[cb + 4 * 72]);
                mma_tf32_16x8x8(acc_o[nf], pa, vb);
            }
        }
    }

    // ---- Epilogue: normalize, tf32-round (out-proj A operand), store ----
    const float il0 = 1.f / l_i[0];
    const float il1 = 1.f / l_i[1];
    const size_t row0 = (size_t)(rowbase + q0 + r_row) * 1024;
    const size_t row1 = row0 + 8 * 1024;
    #pragma unroll
    for (int nf = 0; nf < 8; nf++) {
        int col = colq + 8 * nf + 2 * lc;
        *(float2*)&y[row0 + col] = make_float2(tf32r(acc_o[nf][0] * il0),
                                               tf32r(acc_o[nf][1] * il0));
        *(float2*)&y[row1 + col] = make_float2(tf32r(acc_o[nf][2] * il1),
                                               tf32r(acc_o[nf][3] * il1));
    }
}

// ---------------------------------------------------------------------------
extern "C" void kernel_launch(void* const* d_in, const int* in_sizes, int n_in,
                              void* d_out, int out_size)
{
    const float* x     = (const float*)d_in[0];
    const float* w_qkv = (const float*)d_in[1];
    const float* b_qkv = (const float*)d_in[2];
    const float* w_out = (const float*)d_in[3];
    const float* b_out = (const float*)d_in[4];
    float* out = (float*)d_out;

    __half *qhi, *qlo, *khi, *klo;
    float *vpl, *yb, *xr, *wqr, *wor;
    cudaGetSymbolAddress((void**)&qhi, g_qhi);
    cudaGetSymbolAddress((void**)&qlo, g_qlo);
    cudaGetSymbolAddress((void**)&khi, g_khi);
    cudaGetSymbolAddress((void**)&klo, g_klo);
    cudaGetSymbolAddress((void**)&vpl, g_v);
    cudaGetSymbolAddress((void**)&yb,  g_y);
    cudaGetSymbolAddress((void**)&xr,  g_xr);
    cudaGetSymbolAddress((void**)&wqr, g_wqkvr);
    cudaGetSymbolAddress((void**)&wor, g_woutr);

    cudaFuncSetAttribute(gemm_tc, cudaFuncAttributeMaxDynamicSharedMemorySize, GEMM_SMEM);
    cudaFuncSetAttribute(attn_tc, cudaFuncAttributeMaxDynamicSharedMemorySize, ATTN_SMEM);

    // 0) Pre-round GEMM operands to tf32 once
    round_tf32<<<1184, 256>>>(x,     xr,  4096 * 1024 / 4);
    round_tf32<<<1184, 256>>>(w_qkv, wqr, 1024 * 3072 / 4);
    round_tf32<<<1184, 256>>>(w_out, wor, 1024 * 1024 / 4);

    // 1) QKV projection -> split Q/K hi-lo half planes + V f32 plane
    gemm_tc<<<dim3(32, 24), 256, GEMM_SMEM>>>(xr, wqr, b_qkv, nullptr,
                                              4096, 3072, 1024,
                                              qhi, qlo, khi, klo, vpl, 1);

    // 2) Causal flash attention (fp16-split QK^T + tf32 PV)
    attn_tc<<<dim3(16, 32), 256, ATTN_SMEM>>>(qhi, qlo, khi, klo, vpl, yb);

    // 3) Output projection
    gemm_tc<<<dim3(32, 8), 256, GEMM_SMEM>>>(yb, wor, b_out, out,
                                             4096, 1024, 1024,
                                             nullptr, nullptr, nullptr, nullptr,
                                             nullptr, 0);
}

// round 10
// speedup vs baseline: 6.9517x; 1.6920x over previous
#include <cuda_runtime.h>
#include <cuda_fp16.h>
#include <math.h>
#include <cstdint>

// Scratch (allocation-free rule: __device__ globals)
__device__ __half g_qhi[4096 * 1024];    // Q hi halves (pre-scaled by 0.125)
__device__ __half g_qlo[4096 * 1024];    // Q lo halves
__device__ __half g_khi[4096 * 1024];    // K hi halves
__device__ __half g_klo[4096 * 1024];    // K lo halves
__device__ __half g_vh [4096 * 1024];    // V fp16
__device__ __half g_yh [4096 * 1024];    // attention output, fp16
__device__ __half g_xh [4096 * 1024];    // fp16 x
__device__ __half g_wqkvh[1024 * 3072];  // fp16 w_qkv
__device__ __half g_wouth[1024 * 1024];  // fp16 w_out

// ---------------------------------------------------------------------------
// Helpers
// ---------------------------------------------------------------------------
__device__ __forceinline__ uint32_t smem_u32(const void* p) {
    uint32_t a;
    asm("{ .reg .u64 t; cvta.to.shared.u64 t, %1; cvt.u32.u64 %0, t; }"
        : "=r"(a) : "l"(p));
    return a;
}
__device__ __forceinline__ void cp_async16(uint32_t dst, const void* src) {
    asm volatile("cp.async.cg.shared.global [%0], [%1], 16;" :: "r"(dst), "l"(src));
}
__device__ __forceinline__ void cp_commit() {
    asm volatile("cp.async.commit_group;");
}
__device__ __forceinline__ void mma_f16_16x8x16(
    float* c, const uint32_t* a, const uint32_t* b) {
    asm volatile(
        "mma.sync.aligned.m16n8k16.row.col.f32.f16.f16.f32 "
        "{%0,%1,%2,%3}, {%4,%5,%6,%7}, {%8,%9}, {%0,%1,%2,%3};"
        : "+f"(c[0]), "+f"(c[1]), "+f"(c[2]), "+f"(c[3])
        : "r"(a[0]), "r"(a[1]), "r"(a[2]), "r"(a[3]), "r"(b[0]), "r"(b[1]));
}
__device__ __forceinline__ void ldmx4(uint32_t* r, uint32_t addr) {
    asm volatile("ldmatrix.sync.aligned.m8n8.x4.shared.b16 {%0,%1,%2,%3}, [%4];"
        : "=r"(r[0]), "=r"(r[1]), "=r"(r[2]), "=r"(r[3]) : "r"(addr));
}
__device__ __forceinline__ void ldmx4t(uint32_t* r, uint32_t addr) {
    asm volatile("ldmatrix.sync.aligned.m8n8.x4.trans.shared.b16 {%0,%1,%2,%3}, [%4];"
        : "=r"(r[0]), "=r"(r[1]), "=r"(r[2]), "=r"(r[3]) : "r"(addr));
}
// pack(lo, hi) -> b32 half2 {lo in [15:0], hi in [31:16]}
__device__ __forceinline__ uint32_t packh2(float lo, float hi) {
    uint32_t d;
    asm("cvt.rn.f16x2.f32 %0, %1, %2;" : "=r"(d) : "f"(hi), "f"(lo));
    return d;
}

// Markidis split store: hi+lo carries ~22 mantissa bits.
__device__ __forceinline__ void store_split(
    __half* hp, __half* lp, size_t idx, float x, float yv)
{
    __half hx = __float2half_rn(x),  hy = __float2half_rn(yv);
    __half lx = __float2half_rn(x  - __half2float(hx));
    __half ly = __float2half_rn(yv - __half2float(hy));
    *(__half2*)&hp[idx] = __halves2half2(hx, hy);
    *(__half2*)&lp[idx] = __halves2half2(lx, ly);
}

// ---------------------------------------------------------------------------
// Prepass: f32 -> f16
// ---------------------------------------------------------------------------
__global__ __launch_bounds__(256) void to_half(
    const float* __restrict__ s, __half* __restrict__ d, int n4)
{
    int stride = gridDim.x * blockDim.x;
    for (int i = blockIdx.x * blockDim.x + threadIdx.x; i < n4; i += stride) {
        float4 v = ((const float4*)s)[i];
        uint2 o;
        o.x = packh2(v.x, v.y);
        o.y = packh2(v.z, v.w);
        ((uint2*)d)[i] = o;
    }
}

// ---------------------------------------------------------------------------
// fp16 mma.sync GEMM + bias:  C[M,N] = A[M,K] @ B[K,N] + bias[N], f32 accum.
// CTA 128x128, k-chunk 64, 3-stage cp.async ring, all frags via ldmatrix.
// A smem [128 m][72 k] halves;  B smem [64 k][136 n] halves.
// split_mode=1: epilogue writes Q/K hi-lo split planes (Q pre-scaled) + V f16.
// ---------------------------------------------------------------------------
#define GA_TILE_H (128 * 72)
#define GB_TILE_H (64 * 136)
#define GSTAGE_H  (GA_TILE_H + GB_TILE_H)
#define GEMM_SMEM (3 * GSTAGE_H * 2)        // 107,520 B

__global__ __launch_bounds__(256, 2)
void gemm_tc(const __half* __restrict__ A, const __half* __restrict__ B,
             const float* __restrict__ bias, float* __restrict__ C,
             int M, int N, int K,
             __half* qhi, __half* qlo, __half* khi, __half* klo,
             __half* vplane, int split_mode)
{
    extern __shared__ __align__(16) __half smh[];

    const int tid = threadIdx.x;
    const int wid = tid >> 5, lane = tid & 31;
    const int m0 = blockIdx.x * 128;
    const int n0 = blockIdx.y * 128;
    const int wm = wid & 1;
    const int wn = wid >> 1;

    const uint32_t sbase = smem_u32(smh);

    auto prefetch = [&](int k0, int stage) {
        uint32_t Ad = sbase + stage * GSTAGE_H * 2;
        uint32_t Bd = Ad + GA_TILE_H * 2;
        #pragma unroll
        for (int i = 0; i < 4; i++) {           // A: 128 rows x 8 segs
            int s = tid + i * 256;
            int r = s >> 3, seg = s & 7;
            cp_async16(Ad + (r * 72 + seg * 8) * 2,
                       A + (size_t)(m0 + r) * K + k0 + seg * 8);
        }
        #pragma unroll
        for (int i = 0; i < 4; i++) {           // B: 64 rows x 16 segs
            int s = tid + i * 256;
            int r = s >> 4, seg = s & 15;
            cp_async16(Bd + (r * 136 + seg * 8) * 2,
                       B + (size_t)(k0 + r) * N + n0 + seg * 8);
        }
        cp_commit();
    };

    float acc[4][4][4];
    #pragma unroll
    for (int i = 0; i < 4; i++)
        #pragma unroll
        for (int j = 0; j < 4; j++)
            #pragma unroll
            for (int r = 0; r < 4; r++) acc[i][j][r] = 0.f;

    const int NCH = K >> 6;                     // k-chunk 64
    prefetch(0, 0);
    if (NCH > 1) prefetch(64, 1);

    const int l15 = lane & 15;
    const uint32_t koff16 = (lane & 16) ? 8 : 0;   // second k8 / second n8 selector
    const uint32_t koff8  = (lane & 8)  ? 8 : 0;

    for (int c = 0; c < NCH; c++) {
        if (c == NCH - 1)
            asm volatile("cp.async.wait_group 0;" ::: "memory");
        else
            asm volatile("cp.async.wait_group 1;" ::: "memory");
        __syncthreads();

        if (c + 2 < NCH) prefetch((c + 2) * 64, (c + 2) % 3);

        const uint32_t Asm = sbase + (c % 3) * GSTAGE_H * 2;
        const uint32_t Bsm = Asm + GA_TILE_H * 2;

        #pragma unroll
        for (int ks = 0; ks < 4; ks++) {
            const int kb = ks * 16;
            uint32_t af[4][4], bf[4][2];
            #pragma unroll
            for (int mf = 0; mf < 4; mf++)      // A: non-trans x4
                ldmx4(af[mf], Asm + ((wm * 64 + mf * 16 + l15) * 72 + kb + koff16) * 2);
            #pragma unroll
            for (int nfp = 0; nfp < 2; nfp++) { // B: trans x4 -> 2 n-frags
                uint32_t t[4];
                ldmx4t(t, Bsm + ((kb + l15) * 136 + wn * 32 + nfp * 16 + koff16) * 2);
                bf[2 * nfp][0] = t[0]; bf[2 * nfp][1] = t[1];
                bf[2 * nfp + 1][0] = t[2]; bf[2 * nfp + 1][1] = t[3];
            }
            #pragma unroll
            for (int mf = 0; mf < 4; mf++)
                #pragma unroll
                for (int nf = 0; nf < 4; nf++)
                    mma_f16_16x8x16(acc[mf][nf], af[mf], bf[nf]);
        }
        __syncthreads();
    }

    const int lr = lane >> 2;
    const int lc = lane & 3;
    #pragma unroll
    for (int mf = 0; mf < 4; mf++) {
        int row = m0 + wm * 64 + mf * 16 + lr;
        #pragma unroll
        for (int nf = 0; nf < 4; nf++) {
            int col = n0 + wn * 32 + nf * 8 + 2 * lc;
            float b0 = bias[col], b1 = bias[col + 1];
            float v00 = acc[mf][nf][0] + b0, v01 = acc[mf][nf][1] + b1;
            float v10 = acc[mf][nf][2] + b0, v11 = acc[mf][nf][3] + b1;
            if (!split_mode) {
                *(float2*)&C[(size_t)row * N + col] = make_float2(v00, v01);
                *(float2*)&C[(size_t)(row + 8) * N + col] = make_float2(v10, v11);
            } else if (col < 1024) {            // Q plane, fold 1/sqrt(hd)
                store_split(qhi, qlo, (size_t)row * 1024 + col,
                            v00 * 0.125f, v01 * 0.125f);
                store_split(qhi, qlo, (size_t)(row + 8) * 1024 + col,
                            v10 * 0.125f, v11 * 0.125f);
            } else if (col < 2048) {            // K plane
                store_split(khi, klo, (size_t)row * 1024 + col - 1024, v00, v01);
                store_split(khi, klo, (size_t)(row + 8) * 1024 + col - 1024, v10, v11);
            } else {                            // V plane (f16)
                *(uint32_t*)&vplane[(size_t)row * 1024 + col - 2048] = packh2(v00, v01);
                *(uint32_t*)&vplane[(size_t)(row + 8) * 1024 + col - 2048] = packh2(v10, v11);
            }
        }
    }
}

// ---------------------------------------------------------------------------
// Causal flash attention, all-fp16 tensor ops.
// QK^T: fp16 Markidis split (3 MMAs / k16), frags via ldmatrix.
// PV:   fp16 P directly from S C-frags (no shuffles), V via ldmatrix.x4.trans.
// smem halves: Qh/Ql[128][72], Kh/Kl ring2[64][72], Vh ring2[64][72] = 92,160 B.
// ---------------------------------------------------------------------------
#define ATTN_SMEM 92160

__global__ __launch_bounds__(256, 2)
void attn_tc(const __half* __restrict__ qh_g, const __half* __restrict__ ql_g,
             const __half* __restrict__ kh_g, const __half* __restrict__ kl_g,
             const __half* __restrict__ v_g,  __half* __restrict__ y)
{
    extern __shared__ __align__(16) __half smh[];

    const int qt = 15 - blockIdx.x;              // heavy tiles first
    const int bh = blockIdx.y;
    const int b = bh >> 4, h = bh & 15;
    const int tid = threadIdx.x;
    const int wid = tid >> 5, lane = tid & 31;
    const int lr = lane >> 2, lc = lane & 3;
    const int l15 = lane & 15;
    const uint32_t koff16 = (lane & 16) ? 8 : 0;
    const uint32_t koff8  = (lane & 8)  ? 8 : 0;
    const int l7 = lane & 7;
    const int q0 = qt * 128;
    const int rowbase = b * 2048;
    const int colq = h * 64;

    const uint32_t sbase = smem_u32(smh);
    const uint32_t QhA = sbase;                       // 128*72 h
    const uint32_t QlA = QhA + 128 * 72 * 2;
    const uint32_t KhA = QlA + 128 * 72 * 2;          // 2 x 64*72 h
    const uint32_t KlA = KhA + 2 * 64 * 72 * 2;
    const uint32_t VA  = KlA + 2 * 64 * 72 * 2;       // 2 x 64*72 h

    // Async-load Q hi/lo tiles
    #pragma unroll
    for (int j = 0; j < 4; j++) {
        int s = tid + j * 256;
        int r = s >> 3, seg = s & 7;
        size_t g = (size_t)(rowbase + q0 + r) * 1024 + colq + seg * 8;
        cp_async16(QhA + (r * 72 + seg * 8) * 2, qh_g + g);
        cp_async16(QlA + (r * 72 + seg * 8) * 2, ql_g + g);
    }
    cp_commit();

    auto prefetch = [&](int kt) {
        const int buf = kt & 1;
        const uint32_t Khd = KhA + buf * (64 * 72 * 2);
        const uint32_t Kld = KlA + buf * (64 * 72 * 2);
        const uint32_t Vd  = VA  + buf * (64 * 72 * 2);
        #pragma unroll
        for (int j = 0; j < 2; j++) {
            int s = tid + j * 256;
            int r = s >> 3, seg = s & 7;
            size_t g = (size_t)(rowbase + kt * 64 + r) * 1024 + colq + seg * 8;
            cp_async16(Khd + (r * 72 + seg * 8) * 2, kh_g + g);
            cp_async16(Kld + (r * 72 + seg * 8) * 2, kl_g + g);
            cp_async16(Vd  + (r * 72 + seg * 8) * 2, v_g  + g);
        }
        cp_commit();
    };

    const int ktmax = 2 * qt + 1;
    prefetch(0);

    float m_i[2] = {-INFINITY, -INFINITY};
    float l_i[2] = {0.f, 0.f};
    float acc_o[8][4];
    #pragma unroll
    for (int nf = 0; nf < 8; nf++)
        #pragma unroll
        for (int c = 0; c < 4; c++) acc_o[nf][c] = 0.f;

    const int r_row = 16 * wid + lr;

    for (int kt = 0; kt <= ktmax; kt++) {
        asm volatile("cp.async.wait_group 0;" ::: "memory");
        __syncthreads();     // tile kt (and Q on kt=0) ready; buf kt^1 free

        if (kt + 1 <= ktmax) prefetch(kt + 1);

        const uint32_t KhB = KhA + (kt & 1) * (64 * 72 * 2);
        const uint32_t KlB = KlA + (kt & 1) * (64 * 72 * 2);
        const uint32_t VB  = VA  + (kt & 1) * (64 * 72 * 2);

        // ---- S = Q K^T : fp16 Markidis split, ldmatrix frags ----
        float sacc[8][4];
        #pragma unroll
        for (int nf = 0; nf < 8; nf++)
            #pragma unroll
            for (int c = 0; c < 4; c++) sacc[nf][c] = 0.f;

        #pragma unroll
        for (int ks = 0; ks < 4; ks++) {
            const int kb = ks * 16;
            uint32_t ah[4], al[4];
            ldmx4(ah, QhA + ((16 * wid + l15) * 72 + kb + koff16) * 2);
            ldmx4(al, QlA + ((16 * wid + l15) * 72 + kb + koff16) * 2);
            #pragma unroll
            for (int nfp = 0; nfp < 4; nfp++) {
                // K [n][k] non-trans x4: mats (n:16nfp+0-7 / +8-15) x (kb / kb+8)
                uint32_t bh2[4], bl2[4];
                uint32_t kaddr = ((16 * nfp + l7 + koff16) * 72 + kb + koff8) * 2;
                ldmx4(bh2, KhB + kaddr);
                ldmx4(bl2, KlB + kaddr);
                mma_f16_16x8x16(sacc[2 * nfp],     ah, bh2);
                mma_f16_16x8x16(sacc[2 * nfp],     ah, bl2);
                mma_f16_16x8x16(sacc[2 * nfp],     al, bh2);
                mma_f16_16x8x16(sacc[2 * nfp + 1], ah, bh2 + 2);
                mma_f16_16x8x16(sacc[2 * nfp + 1], ah, bl2 + 2);
                mma_f16_16x8x16(sacc[2 * nfp + 1], al, bh2 + 2);
            }
        }

        // ---- Causal mask (only the 2 diagonal k-tiles) ----
        if (kt >= 2 * qt) {
            const int rg = q0 + r_row;
            const int cb0 = kt * 64 + 2 * lc;
            #pragma unroll
            for (int nf = 0; nf < 8; nf++) {
                int c0 = cb0 + 8 * nf;
                if (c0     > rg)     sacc[nf][0] = -INFINITY;
                if (c0 + 1 > rg)     sacc[nf][1] = -INFINITY;
                if (c0     > rg + 8) sacc[nf][2] = -INFINITY;
                if (c0 + 1 > rg + 8) sacc[nf][3] = -INFINITY;
            }
        }

        // ---- Online softmax ----
        float tm0 = -INFINITY, tm1 = -INFINITY;
        #pragma unroll
        for (int nf = 0; nf < 8; nf++) {
            tm0 = fmaxf(tm0, fmaxf(sacc[nf][0], sacc[nf][1]));
            tm1 = fmaxf(tm1, fmaxf(sacc[nf][2], sacc[nf][3]));
        }
        tm0 = fmaxf(tm0, __shfl_xor_sync(0xffffffffu, tm0, 1));
        tm0 = fmaxf(tm0, __shfl_xor_sync(0xffffffffu, tm0, 2));
        tm1 = fmaxf(tm1, __shfl_xor_sync(0xffffffffu, tm1, 1));
        tm1 = fmaxf(tm1, __shfl_xor_sync(0xffffffffu, tm1, 2));

        const float nm0 = fmaxf(m_i[0], tm0);
        const float nm1 = fmaxf(m_i[1], tm1);
        const float sc0 = __expf(m_i[0] - nm0);
        const float sc1 = __expf(m_i[1] - nm1);
        float rs0 = 0.f, rs1 = 0.f;
        #pragma unroll
        for (int nf = 0; nf < 8; nf++) {
            sacc[nf][0] = __expf(sacc[nf][0] - nm0);
            sacc[nf][1] = __expf(sacc[nf][1] - nm0);
            sacc[nf][2] = __expf(sacc[nf][2] - nm1);
            sacc[nf][3] = __expf(sacc[nf][3] - nm1);
            rs0 += sacc[nf][0] + sacc[nf][1];
            rs1 += sacc[nf][2] + sacc[nf][3];
        }
        rs0 += __shfl_xor_sync(0xffffffffu, rs0, 1);
        rs0 += __shfl_xor_sync(0xffffffffu, rs0, 2);
        rs1 += __shfl_xor_sync(0xffffffffu, rs1, 1);
        rs1 += __shfl_xor_sync(0xffffffffu, rs1, 2);
        l_i[0] = l_i[0] * sc0 + rs0;
        l_i[1] = l_i[1] * sc1 + rs1;
        m_i[0] = nm0;
        m_i[1] = nm1;
        #pragma unroll
        for (int nf = 0; nf < 8; nf++) {
            acc_o[nf][0] *= sc0; acc_o[nf][1] *= sc0;
            acc_o[nf][2] *= sc1; acc_o[nf][3] *= sc1;
        }

        // ---- O += P V : fp16.  S C-frag IS the PV A-frag (no shuffles). ----
        #pragma unroll
        for (int ks = 0; ks < 4; ks++) {
            uint32_t pa[4];
            pa[0] = packh2(sacc[2 * ks][0],     sacc[2 * ks][1]);
            pa[1] = packh2(sacc[2 * ks][2],     sacc[2 * ks][3]);
            pa[2] = packh2(sacc[2 * ks + 1][0], sacc[2 * ks + 1][1]);
            pa[3] = packh2(sacc[2 * ks + 1][2], sacc[2 * ks + 1][3]);
            #pragma unroll
            for (int nfp = 0; nfp < 4; nfp++) {
                // V [k][n] trans x4: mats (k:16ks+0-7/+8-15) x (n:16nfp/+8)
                uint32_t tv[4];
                ldmx4t(tv, VB + ((16 * ks + l7 + koff8) * 72 + 16 * nfp + koff16) * 2);
                mma_f16_16x8x16(acc_o[2 * nfp],     pa, tv);
                mma_f16_16x8x16(acc_o[2 * nfp + 1], pa, tv + 2);
            }
        }
    }

    // ---- Epilogue: normalize, store y as f16 (out-proj A operand) ----
    const float il0 = 1.f / l_i[0];
    const float il1 = 1.f / l_i[1];
    const size_t row0 = (size_t)(rowbase + q0 + r_row) * 1024;
    const size_t row1 = row0 + 8 * 1024;
    #pragma unroll
    for (int nf = 0; nf < 8; nf++) {
        int col = colq + 8 * nf + 2 * lc;
        *(uint32_t*)&y[row0 + col] = packh2(acc_o[nf][0] * il0, acc_o[nf][1] * il0);
        *(uint32_t*)&y[row1 + col] = packh2(acc_o[nf][2] * il1, acc_o[nf][3] * il1);
    }
}

// ---------------------------------------------------------------------------
extern "C" void kernel_launch(void* const* d_in, const int* in_sizes, int n_in,
                              void* d_out, int out_size)
{
    const float* x     = (const float*)d_in[0];
    const float* w_qkv = (const float*)d_in[1];
    const float* b_qkv = (const float*)d_in[2];
    const float* w_out = (const float*)d_in[3];
    const float* b_out = (const float*)d_in[4];
    float* out = (float*)d_out;

    __half *qhi, *qlo, *khi, *klo, *vh, *yh, *xh, *wqh, *woh;
    cudaGetSymbolAddress((void**)&qhi, g_qhi);
    cudaGetSymbolAddress((void**)&qlo, g_qlo);
    cudaGetSymbolAddress((void**)&khi, g_khi);
    cudaGetSymbolAddress((void**)&klo, g_klo);
    cudaGetSymbolAddress((void**)&vh,  g_vh);
    cudaGetSymbolAddress((void**)&yh,  g_yh);
    cudaGetSymbolAddress((void**)&xh,  g_xh);
    cudaGetSymbolAddress((void**)&wqh, g_wqkvh);
    cudaGetSymbolAddress((void**)&woh, g_wouth);

    cudaFuncSetAttribute(gemm_tc, cudaFuncAttributeMaxDynamicSharedMemorySize, GEMM_SMEM);
    cudaFuncSetAttribute(attn_tc, cudaFuncAttributeMaxDynamicSharedMemorySize, ATTN_SMEM);

    // 0) Convert operands to f16 once
    to_half<<<1184, 256>>>(x,     xh,  4096 * 1024 / 4);
    to_half<<<1184, 256>>>(w_qkv, wqh, 1024 * 3072 / 4);
    to_half<<<1184, 256>>>(w_out, woh, 1024 * 1024 / 4);

    // 1) QKV projection -> Q/K hi-lo split planes + V f16 plane
    gemm_tc<<<dim3(32, 24), 256, GEMM_SMEM>>>(xh, wqh, b_qkv, nullptr,
                                              4096, 3072, 1024,
                                              qhi, qlo, khi, klo, vh, 1);

    // 2) Causal flash attention (fp16 split QK^T + fp16 PV)
    attn_tc<<<dim3(16, 32), 256, ATTN_SMEM>>>(qhi, qlo, khi, klo, vh, yh);

    // 3) Output projection
    gemm_tc<<<dim3(32, 8), 256, GEMM_SMEM>>>(yh, woh, b_out, out,
                                             4096, 1024, 1024,
                                             nullptr, nullptr, nullptr, nullptr,
                                             nullptr, 0);
}

// round 11
// speedup vs baseline: 7.2195x; 1.0385x over previous
#include <cuda_runtime.h>
#include <cuda_fp16.h>
#include <math.h>
#include <cstdint>

// Scratch (allocation-free rule: __device__ globals)
__device__ __half g_qhi[4096 * 1024];    // Q hi halves (pre-scaled by 0.125)
__device__ __half g_qlo[4096 * 1024];    // Q lo halves
__device__ __half g_khi[4096 * 1024];    // K hi halves
__device__ __half g_klo[4096 * 1024];    // K lo halves
__device__ __half g_vh [4096 * 1024];    // V fp16
__device__ __half g_yh [4096 * 1024];    // attention output, fp16
__device__ __half g_xh [4096 * 1024];    // fp16 x
__device__ __half g_wqkvh[1024 * 3072];  // fp16 w_qkv
__device__ __half g_wouth[1024 * 1024];  // fp16 w_out

// ---------------------------------------------------------------------------
// Helpers
// ---------------------------------------------------------------------------
__device__ __forceinline__ uint32_t smem_u32(const void* p) {
    uint32_t a;
    asm("{ .reg .u64 t; cvta.to.shared.u64 t, %1; cvt.u32.u64 %0, t; }"
        : "=r"(a) : "l"(p));
    return a;
}
__device__ __forceinline__ void cp_async16(uint32_t dst, const void* src) {
    asm volatile("cp.async.cg.shared.global [%0], [%1], 16;" :: "r"(dst), "l"(src));
}
__device__ __forceinline__ void cp_commit() {
    asm volatile("cp.async.commit_group;");
}
__device__ __forceinline__ void mma_f16_16x8x16(
    float* c, const uint32_t* a, const uint32_t* b) {
    asm volatile(
        "mma.sync.aligned.m16n8k16.row.col.f32.f16.f16.f32 "
        "{%0,%1,%2,%3}, {%4,%5,%6,%7}, {%8,%9}, {%0,%1,%2,%3};"
        : "+f"(c[0]), "+f"(c[1]), "+f"(c[2]), "+f"(c[3])
        : "r"(a[0]), "r"(a[1]), "r"(a[2]), "r"(a[3]), "r"(b[0]), "r"(b[1]));
}
__device__ __forceinline__ void ldmx4(uint32_t* r, uint32_t addr) {
    asm volatile("ldmatrix.sync.aligned.m8n8.x4.shared.b16 {%0,%1,%2,%3}, [%4];"
        : "=r"(r[0]), "=r"(r[1]), "=r"(r[2]), "=r"(r[3]) : "r"(addr));
}
__device__ __forceinline__ void ldmx4t(uint32_t* r, uint32_t addr) {
    asm volatile("ldmatrix.sync.aligned.m8n8.x4.trans.shared.b16 {%0,%1,%2,%3}, [%4];"
        : "=r"(r[0]), "=r"(r[1]), "=r"(r[2]), "=r"(r[3]) : "r"(addr));
}
__device__ __forceinline__ void ldmx2t(uint32_t* r, uint32_t addr) {
    asm volatile("ldmatrix.sync.aligned.m8n8.x2.trans.shared.b16 {%0,%1}, [%2];"
        : "=r"(r[0]), "=r"(r[1]) : "r"(addr));
}
// pack(lo, hi) -> b32 half2 {lo in [15:0], hi in [31:16]}
__device__ __forceinline__ uint32_t packh2(float lo, float hi) {
    uint32_t d;
    asm("cvt.rn.f16x2.f32 %0, %1, %2;" : "=r"(d) : "f"(hi), "f"(lo));
    return d;
}
// packed 2^x on half2
__device__ __forceinline__ uint32_t h2ex2(uint32_t x) {
    uint32_t d;
    asm("ex2.approx.f16x2 %0, %1;" : "=r"(d) : "r"(x));
    return d;
}

// Markidis split store: hi+lo carries ~22 mantissa bits.
__device__ __forceinline__ void store_split(
    __half* hp, __half* lp, size_t idx, float x, float yv)
{
    __half hx = __float2half_rn(x),  hy = __float2half_rn(yv);
    __half lx = __float2half_rn(x  - __half2float(hx));
    __half ly = __float2half_rn(yv - __half2float(hy));
    *(__half2*)&hp[idx] = __halves2half2(hx, hy);
    *(__half2*)&lp[idx] = __halves2half2(lx, ly);
}

// ---------------------------------------------------------------------------
// Fused prepass: f32 -> f16 for x, w_qkv, w_out in one launch.
// ---------------------------------------------------------------------------
#define N4_X  (4096 * 1024 / 4)
#define N4_WQ (1024 * 3072 / 4)
#define N4_WO (1024 * 1024 / 4)

__global__ __launch_bounds__(256) void to_half3(
    const float* __restrict__ x,  __half* __restrict__ dx,
    const float* __restrict__ wq, __half* __restrict__ dwq,
    const float* __restrict__ wo, __half* __restrict__ dwo)
{
    const int total = N4_X + N4_WQ + N4_WO;
    int stride = gridDim.x * blockDim.x;
    for (int i = blockIdx.x * blockDim.x + threadIdx.x; i < total; i += stride) {
        const float* s;
        __half* d;
        int j = i;
        if (j < N4_X)            { s = x;  d = dx; }
        else if (j < N4_X+N4_WQ) { s = wq; d = dwq; j -= N4_X; }
        else                     { s = wo; d = dwo; j -= N4_X + N4_WQ; }
        float4 v = ((const float4*)s)[j];
        uint2 o;
        o.x = packh2(v.x, v.y);
        o.y = packh2(v.z, v.w);
        ((uint2*)d)[j] = o;
    }
}

// ---------------------------------------------------------------------------
// fp16 mma.sync GEMM + bias (unchanged from round 10; 94us QKV).
// ---------------------------------------------------------------------------
#define GA_TILE_H (128 * 72)
#define GB_TILE_H (64 * 136)
#define GSTAGE_H  (GA_TILE_H + GB_TILE_H)
#define GEMM_SMEM (3 * GSTAGE_H * 2)        // 107,520 B

__global__ __launch_bounds__(256, 2)
void gemm_tc(const __half* __restrict__ A, const __half* __restrict__ B,
             const float* __restrict__ bias, float* __restrict__ C,
             int M, int N, int K,
             __half* qhi, __half* qlo, __half* khi, __half* klo,
             __half* vplane, int split_mode)
{
    extern __shared__ __align__(16) __half smh[];

    const int tid = threadIdx.x;
    const int wid = tid >> 5, lane = tid & 31;
    const int m0 = blockIdx.x * 128;
    const int n0 = blockIdx.y * 128;
    const int wm = wid & 1;
    const int wn = wid >> 1;

    const uint32_t sbase = smem_u32(smh);

    auto prefetch = [&](int k0, int stage) {
        uint32_t Ad = sbase + stage * GSTAGE_H * 2;
        uint32_t Bd = Ad + GA_TILE_H * 2;
        #pragma unroll
        for (int i = 0; i < 4; i++) {
            int s = tid + i * 256;
            int r = s >> 3, seg = s & 7;
            cp_async16(Ad + (r * 72 + seg * 8) * 2,
                       A + (size_t)(m0 + r) * K + k0 + seg * 8);
        }
        #pragma unroll
        for (int i = 0; i < 4; i++) {
            int s = tid + i * 256;
            int r = s >> 4, seg = s & 15;
            cp_async16(Bd + (r * 136 + seg * 8) * 2,
                       B + (size_t)(k0 + r) * N + n0 + seg * 8);
        }
        cp_commit();
    };

    float acc[4][4][4];
    #pragma unroll
    for (int i = 0; i < 4; i++)
        #pragma unroll
        for (int j = 0; j < 4; j++)
            #pragma unroll
            for (int r = 0; r < 4; r++) acc[i][j][r] = 0.f;

    const int NCH = K >> 6;
    prefetch(0, 0);
    if (NCH > 1) prefetch(64, 1);

    const int l15 = lane & 15;
    const uint32_t koff16 = (lane & 16) ? 8 : 0;

    for (int c = 0; c < NCH; c++) {
        if (c == NCH - 1)
            asm volatile("cp.async.wait_group 0;" ::: "memory");
        else
            asm volatile("cp.async.wait_group 1;" ::: "memory");
        __syncthreads();

        if (c + 2 < NCH) prefetch((c + 2) * 64, (c + 2) % 3);

        const uint32_t Asm = sbase + (c % 3) * GSTAGE_H * 2;
        const uint32_t Bsm = Asm + GA_TILE_H * 2;

        #pragma unroll
        for (int ks = 0; ks < 4; ks++) {
            const int kb = ks * 16;
            uint32_t af[4][4], bf[4][2];
            #pragma unroll
            for (int mf = 0; mf < 4; mf++)
                ldmx4(af[mf], Asm + ((wm * 64 + mf * 16 + l15) * 72 + kb + koff16) * 2);
            #pragma unroll
            for (int nfp = 0; nfp < 2; nfp++) {
                uint32_t t[4];
                ldmx4t(t, Bsm + ((kb + l15) * 136 + wn * 32 + nfp * 16 + koff16) * 2);
                bf[2 * nfp][0] = t[0]; bf[2 * nfp][1] = t[1];
                bf[2 * nfp + 1][0] = t[2]; bf[2 * nfp + 1][1] = t[3];
            }
            #pragma unroll
            for (int mf = 0; mf < 4; mf++)
                #pragma unroll
                for (int nf = 0; nf < 4; nf++)
                    mma_f16_16x8x16(acc[mf][nf], af[mf], bf[nf]);
        }
        __syncthreads();
    }

    const int lr = lane >> 2;
    const int lc = lane & 3;
    #pragma unroll
    for (int mf = 0; mf < 4; mf++) {
        int row = m0 + wm * 64 + mf * 16 + lr;
        #pragma unroll
        for (int nf = 0; nf < 4; nf++) {
            int col = n0 + wn * 32 + nf * 8 + 2 * lc;
            float b0 = bias[col], b1 = bias[col + 1];
            float v00 = acc[mf][nf][0] + b0, v01 = acc[mf][nf][1] + b1;
            float v10 = acc[mf][nf][2] + b0, v11 = acc[mf][nf][3] + b1;
            if (!split_mode) {
                *(float2*)&C[(size_t)row * N + col] = make_float2(v00, v01);
                *(float2*)&C[(size_t)(row + 8) * N + col] = make_float2(v10, v11);
            } else if (col < 1024) {
                store_split(qhi, qlo, (size_t)row * 1024 + col,
                            v00 * 0.125f, v01 * 0.125f);
                store_split(qhi, qlo, (size_t)(row + 8) * 1024 + col,
                            v10 * 0.125f, v11 * 0.125f);
            } else if (col < 2048) {
                store_split(khi, klo, (size_t)row * 1024 + col - 1024, v00, v01);
                store_split(khi, klo, (size_t)(row + 8) * 1024 + col - 1024, v10, v11);
            } else {
                *(uint32_t*)&vplane[(size_t)row * 1024 + col - 2048] = packh2(v00, v01);
                *(uint32_t*)&vplane[(size_t)(row + 8) * 1024 + col - 2048] = packh2(v10, v11);
            }
        }
    }
}

// ---------------------------------------------------------------------------
// Causal flash attention, all-fp16 tensor ops.
// Round-11: softmax exp via packed ex2.approx.f16x2 (half the MUFU ops; result
// IS the PV A-fragment), and the row-sum l comes FREE from the PV MMA via a
// ones-column at V smem col 64 (l obeys the same scale-recurrence as O).
// smem halves: Qh/Ql[128][72], Kh/Kl ring2[64][72], Vh ring2[64][72] = 92,160 B.
// ---------------------------------------------------------------------------
#define ATTN_SMEM 92160
#define LOG2E 1.4426950408889634f

__global__ __launch_bounds__(256, 2)
void attn_tc(const __half* __restrict__ qh_g, const __half* __restrict__ ql_g,
             const __half* __restrict__ kh_g, const __half* __restrict__ kl_g,
             const __half* __restrict__ v_g,  __half* __restrict__ y)
{
    extern __shared__ __align__(16) __half smh[];

    const int qt = 15 - blockIdx.x;
    const int bh = blockIdx.y;
    const int b = bh >> 4, h = bh & 15;
    const int tid = threadIdx.x;
    const int wid = tid >> 5, lane = tid & 31;
    const int lr = lane >> 2, lc = lane & 3;
    const int l15 = lane & 15;
    const uint32_t koff16 = (lane & 16) ? 8 : 0;
    const uint32_t koff8  = (lane & 8)  ? 8 : 0;
    const int l7 = lane & 7;
    const int q0 = qt * 128;
    const int rowbase = b * 2048;
    const int colq = h * 64;

    const uint32_t sbase = smem_u32(smh);
    const uint32_t QhA = sbase;
    const uint32_t QlA = QhA + 128 * 72 * 2;
    const uint32_t KhA = QlA + 128 * 72 * 2;
    const uint32_t KlA = KhA + 2 * 64 * 72 * 2;
    const uint32_t VA  = KlA + 2 * 64 * 72 * 2;

    // Async-load Q hi/lo tiles
    #pragma unroll
    for (int j = 0; j < 4; j++) {
        int s = tid + j * 256;
        int r = s >> 3, seg = s & 7;
        size_t g = (size_t)(rowbase + q0 + r) * 1024 + colq + seg * 8;
        cp_async16(QhA + (r * 72 + seg * 8) * 2, qh_g + g);
        cp_async16(QlA + (r * 72 + seg * 8) * 2, ql_g + g);
    }
    cp_commit();

    // Ones-column init: V padding cols 64..71 = {1,0,...,0} in BOTH ring bufs.
    // cp.async only ever writes cols 0..63, so this survives all tiles.
    if (tid < 128) {
        int buf = tid >> 6, r = tid & 63;
        uint32_t a = VA + (uint32_t)buf * (64 * 72 * 2) + (r * 72 + 64) * 2;
        asm volatile("st.shared.v4.b32 [%0], {%1,%2,%3,%4};"
                     :: "r"(a), "r"(0x00003C00u), "r"(0u), "r"(0u), "r"(0u));
    }

    auto prefetch = [&](int kt) {
        const int buf = kt & 1;
        const uint32_t Khd = KhA + buf * (64 * 72 * 2);
        const uint32_t Kld = KlA + buf * (64 * 72 * 2);
        const uint32_t Vd  = VA  + buf * (64 * 72 * 2);
        #pragma unroll
        for (int j = 0; j < 2; j++) {
            int s = tid + j * 256;
            int r = s >> 3, seg = s & 7;
            size_t g = (size_t)(rowbase + kt * 64 + r) * 1024 + colq + seg * 8;
            cp_async16(Khd + (r * 72 + seg * 8) * 2, kh_g + g);
            cp_async16(Kld + (r * 72 + seg * 8) * 2, kl_g + g);
            cp_async16(Vd  + (r * 72 + seg * 8) * 2, v_g  + g);
        }
        cp_commit();
    };

    const int ktmax = 2 * qt + 1;
    prefetch(0);

    float m_i[2] = {-INFINITY, -INFINITY};
    float acc_o[8][4];
    float acc_l[4] = {0.f, 0.f, 0.f, 0.f};     // col-64 ones-column: l in c0/c2
    #pragma unroll
    for (int nf = 0; nf < 8; nf++)
        #pragma unroll
        for (int c = 0; c < 4; c++) acc_o[nf][c] = 0.f;

    const int r_row = 16 * wid + lr;

    for (int kt = 0; kt <= ktmax; kt++) {
        asm volatile("cp.async.wait_group 0;" ::: "memory");
        __syncthreads();

        if (kt + 1 <= ktmax) prefetch(kt + 1);

        const uint32_t KhB = KhA + (kt & 1) * (64 * 72 * 2);
        const uint32_t KlB = KlA + (kt & 1) * (64 * 72 * 2);
        const uint32_t VB  = VA  + (kt & 1) * (64 * 72 * 2);

        // ---- S = Q K^T : fp16 Markidis split, ldmatrix frags ----
        float sacc[8][4];
        #pragma unroll
        for (int nf = 0; nf < 8; nf++)
            #pragma unroll
            for (int c = 0; c < 4; c++) sacc[nf][c] = 0.f;

        #pragma unroll
        for (int ks = 0; ks < 4; ks++) {
            const int kb = ks * 16;
            uint32_t ah[4], al[4];
            ldmx4(ah, QhA + ((16 * wid + l15) * 72 + kb + koff16) * 2);
            ldmx4(al, QlA + ((16 * wid + l15) * 72 + kb + koff16) * 2);
            #pragma unroll
            for (int nfp = 0; nfp < 4; nfp++) {
                uint32_t bh2[4], bl2[4];
                uint32_t kaddr = ((16 * nfp + l7 + koff16) * 72 + kb + koff8) * 2;
                ldmx4(bh2, KhB + kaddr);
                ldmx4(bl2, KlB + kaddr);
                mma_f16_16x8x16(sacc[2 * nfp],     ah, bh2);
                mma_f16_16x8x16(sacc[2 * nfp],     ah, bl2);
                mma_f16_16x8x16(sacc[2 * nfp],     al, bh2);
                mma_f16_16x8x16(sacc[2 * nfp + 1], ah, bh2 + 2);
                mma_f16_16x8x16(sacc[2 * nfp + 1], ah, bl2 + 2);
                mma_f16_16x8x16(sacc[2 * nfp + 1], al, bh2 + 2);
            }
        }

        // ---- Causal mask (only the 2 diagonal k-tiles) ----
        if (kt >= 2 * qt) {
            const int rg = q0 + r_row;
            const int cb0 = kt * 64 + 2 * lc;
            #pragma unroll
            for (int nf = 0; nf < 8; nf++) {
                int c0 = cb0 + 8 * nf;
                if (c0     > rg)     sacc[nf][0] = -INFINITY;
                if (c0 + 1 > rg)     sacc[nf][1] = -INFINITY;
                if (c0     > rg + 8) sacc[nf][2] = -INFINITY;
                if (c0 + 1 > rg + 8) sacc[nf][3] = -INFINITY;
            }
        }

        // ---- Online softmax: max update + packed exp2 ----
        float tm0 = -INFINITY, tm1 = -INFINITY;
        #pragma unroll
        for (int nf = 0; nf < 8; nf++) {
            tm0 = fmaxf(tm0, fmaxf(sacc[nf][0], sacc[nf][1]));
            tm1 = fmaxf(tm1, fmaxf(sacc[nf][2], sacc[nf][3]));
        }
        tm0 = fmaxf(tm0, __shfl_xor_sync(0xffffffffu, tm0, 1));
        tm0 = fmaxf(tm0, __shfl_xor_sync(0xffffffffu, tm0, 2));
        tm1 = fmaxf(tm1, __shfl_xor_sync(0xffffffffu, tm1, 1));
        tm1 = fmaxf(tm1, __shfl_xor_sync(0xffffffffu, tm1, 2));

        const float nm0 = fmaxf(m_i[0], tm0);
        const float nm1 = fmaxf(m_i[1], tm1);
        const float sc0 = __expf(m_i[0] - nm0);
        const float sc1 = __expf(m_i[1] - nm1);
        m_i[0] = nm0;
        m_i[1] = nm1;
        const float nmL0 = nm0 * LOG2E, nmL1 = nm1 * LOG2E;

        // P packed as half2 exp2((s-m)*log2e): this IS the PV A-frag.
        uint32_t pfr[8][2];
        #pragma unroll
        for (int nf = 0; nf < 8; nf++) {
            pfr[nf][0] = h2ex2(packh2(fmaf(sacc[nf][0], LOG2E, -nmL0),
                                      fmaf(sacc[nf][1], LOG2E, -nmL0)));
            pfr[nf][1] = h2ex2(packh2(fmaf(sacc[nf][2], LOG2E, -nmL1),
                                      fmaf(sacc[nf][3], LOG2E, -nmL1)));
        }

        // Rescale O and l accumulators
        #pragma unroll
        for (int nf = 0; nf < 8; nf++) {
            acc_o[nf][0] *= sc0; acc_o[nf][1] *= sc0;
            acc_o[nf][2] *= sc1; acc_o[nf][3] *= sc1;
        }
        acc_l[0] *= sc0; acc_l[1] *= sc0;
        acc_l[2] *= sc1; acc_l[3] *= sc1;

        // ---- O += P V ; l += P @ ones (col 64) ----
        #pragma unroll
        for (int ks = 0; ks < 4; ks++) {
            uint32_t pa[4];
            pa[0] = pfr[2 * ks][0];
            pa[1] = pfr[2 * ks][1];
            pa[2] = pfr[2 * ks + 1][0];
            pa[3] = pfr[2 * ks + 1][1];
            #pragma unroll
            for (int nfp = 0; nfp < 4; nfp++) {
                uint32_t tv[4];
                ldmx4t(tv, VB + ((16 * ks + l7 + koff8) * 72 + 16 * nfp + koff16) * 2);
                mma_f16_16x8x16(acc_o[2 * nfp],     pa, tv);
                mma_f16_16x8x16(acc_o[2 * nfp + 1], pa, tv + 2);
            }
            uint32_t tl[2];
            ldmx2t(tl, VB + ((16 * ks + l7 + koff8) * 72 + 64) * 2);
            mma_f16_16x8x16(acc_l, pa, tl);
        }
    }

    // ---- Epilogue: l lives at col 64 (lanes lc==0); broadcast, normalize ----
    const float l0 = __shfl_sync(0xffffffffu, acc_l[0], lane & 28);
    const float l1 = __shfl_sync(0xffffffffu, acc_l[2], lane & 28);
    const float il0 = 1.f / l0;
    const float il1 = 1.f / l1;
    const size_t row0 = (size_t)(rowbase + q0 + r_row) * 1024;
    const size_t row1 = row0 + 8 * 1024;
    #pragma unroll
    for (int nf = 0; nf < 8; nf++) {
        int col = colq + 8 * nf + 2 * lc;
        *(uint32_t*)&y[row0 + col] = packh2(acc_o[nf][0] * il0, acc_o[nf][1] * il0);
        *(uint32_t*)&y[row1 + col] = packh2(acc_o[nf][2] * il1, acc_o[nf][3] * il1);
    }
}

// ---------------------------------------------------------------------------
extern "C" void kernel_launch(void* const* d_in, const int* in_sizes, int n_in,
                              void* d_out, int out_size)
{
    const float* x     = (const float*)d_in[0];
    const float* w_qkv = (const float*)d_in[1];
    const float* b_qkv = (const float*)d_in[2];
    const float* w_out = (const float*)d_in[3];
    const float* b_out = (const float*)d_in[4];
    float* out = (float*)d_out;

    __half *qhi, *qlo, *khi, *klo, *vh, *yh, *xh, *wqh, *woh;
    cudaGetSymbolAddress((void**)&qhi, g_qhi);
    cudaGetSymbolAddress((void**)&qlo, g_qlo);
    cudaGetSymbolAddress((void**)&khi, g_khi);
    cudaGetSymbolAddress((void**)&klo, g_klo);
    cudaGetSymbolAddress((void**)&vh,  g_vh);
    cudaGetSymbolAddress((void**)&yh,  g_yh);
    cudaGetSymbolAddress((void**)&xh,  g_xh);
    cudaGetSymbolAddress((void**)&wqh, g_wqkvh);
    cudaGetSymbolAddress((void**)&woh, g_wouth);

    cudaFuncSetAttribute(gemm_tc, cudaFuncAttributeMaxDynamicSharedMemorySize, GEMM_SMEM);
    cudaFuncSetAttribute(attn_tc, cudaFuncAttributeMaxDynamicSharedMemorySize, ATTN_SMEM);

    // 0) Fused f32->f16 conversion of all operands, one launch
    to_half3<<<2048, 256>>>(x, xh, w_qkv, wqh, w_out, woh);

    // 1) QKV projection -> Q/K hi-lo split planes + V f16 plane
    gemm_tc<<<dim3(32, 24), 256, GEMM_SMEM>>>(xh, wqh, b_qkv, nullptr,
                                              4096, 3072, 1024,
                                              qhi, qlo, khi, klo, vh, 1);

    // 2) Causal flash attention (fp16 split QK^T + fp16 PV, MMA row-sum)
    attn_tc<<<dim3(16, 32), 256, ATTN_SMEM>>>(qhi, qlo, khi, klo, vh, yh);

    // 3) Output projection
    gemm_tc<<<dim3(32, 8), 256, GEMM_SMEM>>>(yh, woh, b_out, out,
                                             4096, 1024, 1024,
                                             nullptr, nullptr, nullptr, nullptr,
                                             nullptr, 0);
}

// round 13
// speedup vs baseline: 9.0664x; 1.2558x over previous
#include <cuda_runtime.h>
#include <cuda_fp16.h>
#include <math.h>
#include <cstdint>

// Scratch (allocation-free rule: __device__ globals)
__device__ __half g_qh[4096 * 1024];     // Q fp16 (pre-scaled by 0.125)
__device__ __half g_kh[4096 * 1024];     // K fp16
__device__ __half g_vh[4096 * 1024];     // V fp16
__device__ __half g_yh[4096 * 1024];     // attention output, fp16
__device__ __half g_xh[4096 * 1024];     // fp16 x
__device__ __half g_wqkvh[1024 * 3072];  // fp16 w_qkv
__device__ __half g_wouth[1024 * 1024];  // fp16 w_out

// ---------------------------------------------------------------------------
// Helpers
// ---------------------------------------------------------------------------
__device__ __forceinline__ uint32_t smem_u32(const void* p) {
    uint32_t a;
    asm("{ .reg .u64 t; cvta.to.shared.u64 t, %1; cvt.u32.u64 %0, t; }"
        : "=r"(a) : "l"(p));
    return a;
}
__device__ __forceinline__ void cp_async16(uint32_t dst, const void* src) {
    asm volatile("cp.async.cg.shared.global [%0], [%1], 16;" :: "r"(dst), "l"(src));
}
__device__ __forceinline__ void cp_commit() {
    asm volatile("cp.async.commit_group;");
}
__device__ __forceinline__ void mma_f16_16x8x16(
    float* c, const uint32_t* a, const uint32_t* b) {
    asm volatile(
        "mma.sync.aligned.m16n8k16.row.col.f32.f16.f16.f32 "
        "{%0,%1,%2,%3}, {%4,%5,%6,%7}, {%8,%9}, {%0,%1,%2,%3};"
        : "+f"(c[0]), "+f"(c[1]), "+f"(c[2]), "+f"(c[3])
        : "r"(a[0]), "r"(a[1]), "r"(a[2]), "r"(a[3]), "r"(b[0]), "r"(b[1]));
}
__device__ __forceinline__ void ldmx4(uint32_t* r, uint32_t addr) {
    asm volatile("ldmatrix.sync.aligned.m8n8.x4.shared.b16 {%0,%1,%2,%3}, [%4];"
        : "=r"(r[0]), "=r"(r[1]), "=r"(r[2]), "=r"(r[3]) : "r"(addr));
}
__device__ __forceinline__ void ldmx4t(uint32_t* r, uint32_t addr) {
    asm volatile("ldmatrix.sync.aligned.m8n8.x4.trans.shared.b16 {%0,%1,%2,%3}, [%4];"
        : "=r"(r[0]), "=r"(r[1]), "=r"(r[2]), "=r"(r[3]) : "r"(addr));
}
__device__ __forceinline__ void ldmx2t(uint32_t* r, uint32_t addr) {
    asm volatile("ldmatrix.sync.aligned.m8n8.x2.trans.shared.b16 {%0,%1}, [%2];"
        : "=r"(r[0]), "=r"(r[1]) : "r"(addr));
}
// pack(lo, hi) -> b32 half2 {lo in [15:0], hi in [31:16]}
__device__ __forceinline__ uint32_t packh2(float lo, float hi) {
    uint32_t d;
    asm("cvt.rn.f16x2.f32 %0, %1, %2;" : "=r"(d) : "f"(hi), "f"(lo));
    return d;
}
// packed 2^x on half2
__device__ __forceinline__ uint32_t h2ex2(uint32_t x) {
    uint32_t d;
    asm("ex2.approx.f16x2 %0, %1;" : "=r"(d) : "r"(x));
    return d;
}

// ---------------------------------------------------------------------------
// Fused prepass: f32 -> f16 for x, w_qkv, w_out in one launch.
// ---------------------------------------------------------------------------
#define N4_X  (4096 * 1024 / 4)
#define N4_WQ (1024 * 3072 / 4)
#define N4_WO (1024 * 1024 / 4)

__global__ __launch_bounds__(256) void to_half3(
    const float* __restrict__ x,  __half* __restrict__ dx,
    const float* __restrict__ wq, __half* __restrict__ dwq,
    const float* __restrict__ wo, __half* __restrict__ dwo)
{
    const int total = N4_X + N4_WQ + N4_WO;
    int stride = gridDim.x * blockDim.x;
    for (int i = blockIdx.x * blockDim.x + threadIdx.x; i < total; i += stride) {
        const float* s;
        __half* d;
        int j = i;
        if (j < N4_X)            { s = x;  d = dx; }
        else if (j < N4_X+N4_WQ) { s = wq; d = dwq; j -= N4_X; }
        else                     { s = wo; d = dwo; j -= N4_X + N4_WQ; }
        float4 v = ((const float4*)s)[j];
        uint2 o;
        o.x = packh2(v.x, v.y);
        o.y = packh2(v.z, v.w);
        ((uint2*)d)[j] = o;
    }
}

// ---------------------------------------------------------------------------
// fp16 mma.sync GEMM + bias.  split_mode=1: epilogue writes single f16
// Q (x0.125) / K / V planes for attention (round 12: no hi/lo split planes).
// ---------------------------------------------------------------------------
#define GA_TILE_H (128 * 72)
#define GB_TILE_H (64 * 136)
#define GSTAGE_H  (GA_TILE_H + GB_TILE_H)
#define GEMM_SMEM (3 * GSTAGE_H * 2)        // 107,520 B

__global__ __launch_bounds__(256, 2)
void gemm_tc(const __half* __restrict__ A, const __half* __restrict__ B,
             const float* __restrict__ bias, float* __restrict__ C,
             int M, int N, int K,
             __half* qh, __half* kh, __half* vh, int split_mode)
{
    extern __shared__ __align__(16) __half smh[];

    const int tid = threadIdx.x;
    const int wid = tid >> 5, lane = tid & 31;
    const int m0 = blockIdx.x * 128;
    const int n0 = blockIdx.y * 128;
    const int wm = wid & 1;
    const int wn = wid >> 1;

    const uint32_t sbase = smem_u32(smh);

    auto prefetch = [&](int k0, int stage) {
        uint32_t Ad = sbase + stage * GSTAGE_H * 2;
        uint32_t Bd = Ad + GA_TILE_H * 2;
        #pragma unroll
        for (int i = 0; i < 4; i++) {
            int s = tid + i * 256;
            int r = s >> 3, seg = s & 7;
            cp_async16(Ad + (r * 72 + seg * 8) * 2,
                       A + (size_t)(m0 + r) * K + k0 + seg * 8);
        }
        #pragma unroll
        for (int i = 0; i < 4; i++) {
            int s = tid + i * 256;
            int r = s >> 4, seg = s & 15;
            cp_async16(Bd + (r * 136 + seg * 8) * 2,
                       B + (size_t)(k0 + r) * N + n0 + seg * 8);
        }
        cp_commit();
    };

    float acc[4][4][4];
    #pragma unroll
    for (int i = 0; i < 4; i++)
        #pragma unroll
        for (int j = 0; j < 4; j++)
            #pragma unroll
            for (int r = 0; r < 4; r++) acc[i][j][r] = 0.f;

    const int NCH = K >> 6;
    prefetch(0, 0);
    if (NCH > 1) prefetch(64, 1);

    const int l15 = lane & 15;
    const uint32_t koff16 = (lane & 16) ? 8 : 0;

    for (int c = 0; c < NCH; c++) {
        if (c == NCH - 1)
            asm volatile("cp.async.wait_group 0;" ::: "memory");
        else
            asm volatile("cp.async.wait_group 1;" ::: "memory");
        __syncthreads();

        if (c + 2 < NCH) prefetch((c + 2) * 64, (c + 2) % 3);

        const uint32_t Asm = sbase + (c % 3) * GSTAGE_H * 2;
        const uint32_t Bsm = Asm + GA_TILE_H * 2;

        #pragma unroll
        for (int ks = 0; ks < 4; ks++) {
            const int kb = ks * 16;
            uint32_t af[4][4], bf[4][2];
            #pragma unroll
            for (int mf = 0; mf < 4; mf++)
                ldmx4(af[mf], Asm + ((wm * 64 + mf * 16 + l15) * 72 + kb + koff16) * 2);
            #pragma unroll
            for (int nfp = 0; nfp < 2; nfp++) {
                uint32_t t[4];
                ldmx4t(t, Bsm + ((kb + l15) * 136 + wn * 32 + nfp * 16 + koff16) * 2);
                bf[2 * nfp][0] = t[0]; bf[2 * nfp][1] = t[1];
                bf[2 * nfp + 1][0] = t[2]; bf[2 * nfp + 1][1] = t[3];
            }
            #pragma unroll
            for (int mf = 0; mf < 4; mf++)
                #pragma unroll
                for (int nf = 0; nf < 4; nf++)
                    mma_f16_16x8x16(acc[mf][nf], af[mf], bf[nf]);
        }
        __syncthreads();
    }

    const int lr = lane >> 2;
    const int lc = lane & 3;
    #pragma unroll
    for (int mf = 0; mf < 4; mf++) {
        int row = m0 + wm * 64 + mf * 16 + lr;
        #pragma unroll
        for (int nf = 0; nf < 4; nf++) {
            int col = n0 + wn * 32 + nf * 8 + 2 * lc;
            float b0 = bias[col], b1 = bias[col + 1];
            float v00 = acc[mf][nf][0] + b0, v01 = acc[mf][nf][1] + b1;
            float v10 = acc[mf][nf][2] + b0, v11 = acc[mf][nf][3] + b1;
            if (!split_mode) {
                *(float2*)&C[(size_t)row * N + col] = make_float2(v00, v01);
                *(float2*)&C[(size_t)(row + 8) * N + col] = make_float2(v10, v11);
            } else if (col < 1024) {           // Q plane, fold 1/sqrt(hd)
                *(uint32_t*)&qh[(size_t)row * 1024 + col] =
                    packh2(v00 * 0.125f, v01 * 0.125f);
                *(uint32_t*)&qh[(size_t)(row + 8) * 1024 + col] =
                    packh2(v10 * 0.125f, v11 * 0.125f);
            } else if (col < 2048) {           // K plane
                *(uint32_t*)&kh[(size_t)row * 1024 + col - 1024] = packh2(v00, v01);
                *(uint32_t*)&kh[(size_t)(row + 8) * 1024 + col - 1024] = packh2(v10, v11);
            } else {                           // V plane
                *(uint32_t*)&vh[(size_t)row * 1024 + col - 2048] = packh2(v00, v01);
                *(uint32_t*)&vh[(size_t)(row + 8) * 1024 + col - 2048] = packh2(v10, v11);
            }
        }
    }
}

// ---------------------------------------------------------------------------
// Causal flash attention, all-fp16 tensor ops.
// Round-12: PLAIN fp16 QK^T (no Markidis split; S abs-noise ~1.8e-4 — safe),
// single Q/K/V planes, K/V ring-3 pipeline.  P via packed ex2.approx.f16x2
// (= the PV A-frag); row-sum l free via ones-column at V col 64.
// smem halves: Q[128][72], K ring3[64][72], V ring3[64][72] = 73,728 B.
// ---------------------------------------------------------------------------
#define ATTN_SMEM 73728
#define LOG2E 1.4426950408889634f

__global__ __launch_bounds__(256, 2)
void attn_tc(const __half* __restrict__ qh_g, const __half* __restrict__ kh_g,
             const __half* __restrict__ v_g,  __half* __restrict__ y)
{
    extern __shared__ __align__(16) __half smh[];

    const int qt = 15 - blockIdx.x;              // heavy tiles first
    const int bh = blockIdx.y;
    const int b = bh >> 4, h = bh & 15;
    const int tid = threadIdx.x;
    const int wid = tid >> 5, lane = tid & 31;
    const int lr = lane >> 2, lc = lane & 3;
    const int l15 = lane & 15;
    const uint32_t koff16 = (lane & 16) ? 8 : 0;
    const uint32_t koff8  = (lane & 8)  ? 8 : 0;
    const int l7 = lane & 7;
    const int q0 = qt * 128;
    const int rowbase = b * 2048;
    const int colq = h * 64;

    const uint32_t sbase = smem_u32(smh);
    const uint32_t QA = sbase;                   // 128*72 h = 18,432 B
    const uint32_t KA = QA + 128 * 72 * 2;       // 3 x 64*72 h
    const uint32_t VA = KA + 3 * 64 * 72 * 2;    // 3 x 64*72 h

    // Async-load Q tile (own commit group; completed by first wait at kt=0)
    #pragma unroll
    for (int j = 0; j < 4; j++) {
        int s = tid + j * 256;
        int r = s >> 3, seg = s & 7;
        cp_async16(QA + (r * 72 + seg * 8) * 2,
                   qh_g + (size_t)(rowbase + q0 + r) * 1024 + colq + seg * 8);
    }
    cp_commit();

    // Ones-column init: V padding cols 64..71 = {1,0,...,0} in all 3 ring bufs.
    // cp.async only writes cols 0..63, so this survives all tiles.
    if (tid < 192) {
        int buf = tid >> 6, r = tid & 63;
        uint32_t a = VA + (uint32_t)buf * (64 * 72 * 2) + (r * 72 + 64) * 2;
        asm volatile("st.shared.v4.b32 [%0], {%1,%2,%3,%4};"
                     :: "r"(a), "r"(0x00003C00u), "r"(0u), "r"(0u), "r"(0u));
    }

    auto prefetch = [&](int kt) {
        const int buf = kt % 3;
        const uint32_t Kd = KA + buf * (64 * 72 * 2);
        const uint32_t Vd = VA + buf * (64 * 72 * 2);
        #pragma unroll
        for (int j = 0; j < 2; j++) {
            int s = tid + j * 256;
            int r = s >> 3, seg = s & 7;
            size_t g = (size_t)(rowbase + kt * 64 + r) * 1024 + colq + seg * 8;
            cp_async16(Kd + (r * 72 + seg * 8) * 2, kh_g + g);
            cp_async16(Vd + (r * 72 + seg * 8) * 2, v_g  + g);
        }
        cp_commit();
    };

    const int ktmax = 2 * qt + 1;                // >= 1 always
    prefetch(0);
    prefetch(1);

    float m_i[2] = {-INFINITY, -INFINITY};
    float acc_o[8][4];
    float acc_l[4] = {0.f, 0.f, 0.f, 0.f};       // ones-column: l in c0/c2
    #pragma unroll
    for (int nf = 0; nf < 8; nf++)
        #pragma unroll
        for (int c = 0; c < 4; c++) acc_o[nf][c] = 0.f;

    const int r_row = 16 * wid + lr;

    for (int kt = 0; kt <= ktmax; kt++) {
        // in-flight budget: 1 while more tiles are coming, 0 at the end
        if (kt < ktmax)
            asm volatile("cp.async.wait_group 1;" ::: "memory");
        else
            asm volatile("cp.async.wait_group 0;" ::: "memory");
        __syncthreads();     // tile kt (and Q at kt=0) ready; buf (kt+2)%3 free

        if (kt + 2 <= ktmax) prefetch(kt + 2);

        const uint32_t KB = KA + (kt % 3) * (64 * 72 * 2);
        const uint32_t VB = VA + (kt % 3) * (64 * 72 * 2);

        // ---- S = Q K^T : plain fp16, ldmatrix frags ----
        float sacc[8][4];
        #pragma unroll
        for (int nf = 0; nf < 8; nf++)
            #pragma unroll
            for (int c = 0; c < 4; c++) sacc[nf][c] = 0.f;

        #pragma unroll
        for (int ks = 0; ks < 4; ks++) {
            const int kb = ks * 16;
            uint32_t ah[4];
            ldmx4(ah, QA + ((16 * wid + l15) * 72 + kb + koff16) * 2);
            #pragma unroll
            for (int nfp = 0; nfp < 4; nfp++) {
                uint32_t bh2[4];
                ldmx4(bh2, KB + ((16 * nfp + l7 + koff16) * 72 + kb + koff8) * 2);
                mma_f16_16x8x16(sacc[2 * nfp],     ah, bh2);
                mma_f16_16x8x16(sacc[2 * nfp + 1], ah, bh2 + 2);
            }
        }

        // ---- Causal mask (only the 2 diagonal k-tiles) ----
        if (kt >= 2 * qt) {
            const int rg = q0 + r_row;
            const int cb0 = kt * 64 + 2 * lc;
            #pragma unroll
            for (int nf = 0; nf < 8; nf++) {
                int c0 = cb0 + 8 * nf;
                if (c0     > rg)     sacc[nf][0] = -INFINITY;
                if (c0 + 1 > rg)     sacc[nf][1] = -INFINITY;
                if (c0     > rg + 8) sacc[nf][2] = -INFINITY;
                if (c0 + 1 > rg + 8) sacc[nf][3] = -INFINITY;
            }
        }

        // ---- Online softmax: max update + packed exp2 ----
        float tm0 = -INFINITY, tm1 = -INFINITY;
        #pragma unroll
        for (int nf = 0; nf < 8; nf++) {
            tm0 = fmaxf(tm0, fmaxf(sacc[nf][0], sacc[nf][1]));
            tm1 = fmaxf(tm1, fmaxf(sacc[nf][2], sacc[nf][3]));
        }
        tm0 = fmaxf(tm0, __shfl_xor_sync(0xffffffffu, tm0, 1));
        tm0 = fmaxf(tm0, __shfl_xor_sync(0xffffffffu, tm0, 2));
        tm1 = fmaxf(tm1, __shfl_xor_sync(0xffffffffu, tm1, 1));
        tm1 = fmaxf(tm1, __shfl_xor_sync(0xffffffffu, tm1, 2));

        const float nm0 = fmaxf(m_i[0], tm0);
        const float nm1 = fmaxf(m_i[1], tm1);
        const float sc0 = __expf(m_i[0] - nm0);
        const float sc1 = __expf(m_i[1] - nm1);
        m_i[0] = nm0;
        m_i[1] = nm1;
        const float nmL0 = nm0 * LOG2E, nmL1 = nm1 * LOG2E;

        // P packed as half2 exp2((s-m)*log2e): this IS the PV A-frag.
        uint32_t pfr[8][2];
        #pragma unroll
        for (int nf = 0; nf < 8; nf++) {
            pfr[nf][0] = h2ex2(packh2(fmaf(sacc[nf][0], LOG2E, -nmL0),
                                      fmaf(sacc[nf][1], LOG2E, -nmL0)));
            pfr[nf][1] = h2ex2(packh2(fmaf(sacc[nf][2], LOG2E, -nmL1),
                                      fmaf(sacc[nf][3], LOG2E, -nmL1)));
        }

        // Rescale O and l accumulators
        #pragma unroll
        for (int nf = 0; nf < 8; nf++) {
            acc_o[nf][0] *= sc0; acc_o[nf][1] *= sc0;
            acc_o[nf][2] *= sc1; acc_o[nf][3] *= sc1;
        }
        acc_l[0] *= sc0; acc_l[1] *= sc0;
        acc_l[2] *= sc1; acc_l[3] *= sc1;

        // ---- O += P V ; l += P @ ones (col 64) ----
        #pragma unroll
        for (int ks = 0; ks < 4; ks++) {
            uint32_t pa[4];
            pa[0] = pfr[2 * ks][0];
            pa[1] = pfr[2 * ks][1];
            pa[2] = pfr[2 * ks + 1][0];
            pa[3] = pfr[2 * ks + 1][1];
            #pragma unroll
            for (int nfp = 0; nfp < 4; nfp++) {
                uint32_t tv[4];
                ldmx4t(tv, VB + ((16 * ks + l7 + koff8) * 72 + 16 * nfp + koff16) * 2);
                mma_f16_16x8x16(acc_o[2 * nfp],     pa, tv);
                mma_f16_16x8x16(acc_o[2 * nfp + 1], pa, tv + 2);
            }
            uint32_t tl[2];
            ldmx2t(tl, VB + ((16 * ks + l7 + koff8) * 72 + 64) * 2);
            mma_f16_16x8x16(acc_l, pa, tl);
        }
    }

    // ---- Epilogue: l lives at col 64 (lanes lc==0); broadcast, normalize ----
    const float l0 = __shfl_sync(0xffffffffu, acc_l[0], lane & 28);
    const float l1 = __shfl_sync(0xffffffffu, acc_l[2], lane & 28);
    const float il0 = 1.f / l0;
    const float il1 = 1.f / l1;
    const size_t row0 = (size_t)(rowbase + q0 + r_row) * 1024;
    const size_t row1 = row0 + 8 * 1024;
    #pragma unroll
    for (int nf = 0; nf < 8; nf++) {
        int col = colq + 8 * nf + 2 * lc;
        *(uint32_t*)&y[row0 + col] = packh2(acc_o[nf][0] * il0, acc_o[nf][1] * il0);
        *(uint32_t*)&y[row1 + col] = packh2(acc_o[nf][2] * il1, acc_o[nf][3] * il1);
    }
}

// ---------------------------------------------------------------------------
extern "C" void kernel_launch(void* const* d_in, const int* in_sizes, int n_in,
                              void* d_out, int out_size)
{
    const float* x     = (const float*)d_in[0];
    const float* w_qkv = (const float*)d_in[1];
    const float* b_qkv = (const float*)d_in[2];
    const float* w_out = (const float*)d_in[3];
    const float* b_out = (const float*)d_in[4];
    float* out = (float*)d_out;

    __half *qh, *kh, *vh, *yh, *xh, *wqh, *woh;
    cudaGetSymbolAddress((void**)&qh,  g_qh);
    cudaGetSymbolAddress((void**)&kh,  g_kh);
    cudaGetSymbolAddress((void**)&vh,  g_vh);
    cudaGetSymbolAddress((void**)&yh,  g_yh);
    cudaGetSymbolAddress((void**)&xh,  g_xh);
    cudaGetSymbolAddress((void**)&wqh, g_wqkvh);
    cudaGetSymbolAddress((void**)&woh, g_wouth);

    cudaFuncSetAttribute(gemm_tc, cudaFuncAttributeMaxDynamicSharedMemorySize, GEMM_SMEM);
    cudaFuncSetAttribute(attn_tc, cudaFuncAttributeMaxDynamicSharedMemorySize, ATTN_SMEM);

    // 0) Fused f32->f16 conversion of all operands, one launch
    to_half3<<<2048, 256>>>(x, xh, w_qkv, wqh, w_out, woh);

    // 1) QKV projection -> single Q (x0.125) / K / V f16 planes
    gemm_tc<<<dim3(32, 24), 256, GEMM_SMEM>>>(xh, wqh, b_qkv, nullptr,
                                              4096, 3072, 1024,
                                              qh, kh, vh, 1);

    // 2) Causal flash attention (plain fp16 QK^T + fp16 PV, MMA row-sum)
    attn_tc<<<dim3(16, 32), 256, ATTN_SMEM>>>(qh, kh, vh, yh);

    // 3) Output projection
    gemm_tc<<<dim3(32, 8), 256, GEMM_SMEM>>>(yh, woh, b_out, out,
                                             4096, 1024, 1024,
                                             nullptr, nullptr, nullptr, 0);
}

// round 14
// speedup vs baseline: 10.1644x; 1.1211x over previous
#include <cuda_runtime.h>
#include <cuda_fp16.h>
#include <math.h>
#include <cstdint>

// Scratch (allocation-free rule: __device__ globals)
__device__ __half g_qh[4096 * 1024];     // Q fp16 (pre-scaled by 0.125)
__device__ __half g_kh[4096 * 1024];     // K fp16
__device__ __half g_vh[4096 * 1024];     // V fp16
__device__ __half g_yh[4096 * 1024];     // attention output, fp16
__device__ __half g_xh[4096 * 1024];     // fp16 x
__device__ __half g_wqkvh[1024 * 3072];  // fp16 w_qkv
__device__ __half g_wouth[1024 * 1024];  // fp16 w_out

// ---------------------------------------------------------------------------
// Helpers
// ---------------------------------------------------------------------------
__device__ __forceinline__ uint32_t smem_u32(const void* p) {
    uint32_t a;
    asm("{ .reg .u64 t; cvta.to.shared.u64 t, %1; cvt.u32.u64 %0, t; }"
        : "=r"(a) : "l"(p));
    return a;
}
__device__ __forceinline__ void cp_async16(uint32_t dst, const void* src) {
    asm volatile("cp.async.cg.shared.global [%0], [%1], 16;" :: "r"(dst), "l"(src));
}
__device__ __forceinline__ void cp_commit() {
    asm volatile("cp.async.commit_group;");
}
__device__ __forceinline__ void mma_f16_16x8x16(
    float* c, const uint32_t* a, const uint32_t* b) {
    asm volatile(
        "mma.sync.aligned.m16n8k16.row.col.f32.f16.f16.f32 "
        "{%0,%1,%2,%3}, {%4,%5,%6,%7}, {%8,%9}, {%0,%1,%2,%3};"
        : "+f"(c[0]), "+f"(c[1]), "+f"(c[2]), "+f"(c[3])
        : "r"(a[0]), "r"(a[1]), "r"(a[2]), "r"(a[3]), "r"(b[0]), "r"(b[1]));
}
__device__ __forceinline__ void ldmx4(uint32_t* r, uint32_t addr) {
    asm volatile("ldmatrix.sync.aligned.m8n8.x4.shared.b16 {%0,%1,%2,%3}, [%4];"
        : "=r"(r[0]), "=r"(r[1]), "=r"(r[2]), "=r"(r[3]) : "r"(addr));
}
__device__ __forceinline__ void ldmx4t(uint32_t* r, uint32_t addr) {
    asm volatile("ldmatrix.sync.aligned.m8n8.x4.trans.shared.b16 {%0,%1,%2,%3}, [%4];"
        : "=r"(r[0]), "=r"(r[1]), "=r"(r[2]), "=r"(r[3]) : "r"(addr));
}
// pack(lo, hi) -> b32 half2 {lo in [15:0], hi in [31:16]}
__device__ __forceinline__ uint32_t packh2(float lo, float hi) {
    uint32_t d;
    asm("cvt.rn.f16x2.f32 %0, %1, %2;" : "=r"(d) : "f"(hi), "f"(lo));
    return d;
}
// packed 2^x on half2
__device__ __forceinline__ uint32_t h2ex2(uint32_t x) {
    uint32_t d;
    asm("ex2.approx.f16x2 %0, %1;" : "=r"(d) : "r"(x));
    return d;
}

// ---------------------------------------------------------------------------
// Fused prepass: f32 -> f16 for x, w_qkv, w_out in one launch.
// ---------------------------------------------------------------------------
#define N4_X  (4096 * 1024 / 4)
#define N4_WQ (1024 * 3072 / 4)
#define N4_WO (1024 * 1024 / 4)

__global__ __launch_bounds__(256) void to_half3(
    const float* __restrict__ x,  __half* __restrict__ dx,
    const float* __restrict__ wq, __half* __restrict__ dwq,
    const float* __restrict__ wo, __half* __restrict__ dwo)
{
    const int total = N4_X + N4_WQ + N4_WO;
    int stride = gridDim.x * blockDim.x;
    for (int i = blockIdx.x * blockDim.x + threadIdx.x; i < total; i += stride) {
        const float* s;
        __half* d;
        int j = i;
        if (j < N4_X)            { s = x;  d = dx; }
        else if (j < N4_X+N4_WQ) { s = wq; d = dwq; j -= N4_X; }
        else                     { s = wo; d = dwo; j -= N4_X + N4_WQ; }
        float4 v = ((const float4*)s)[j];
        uint2 o;
        o.x = packh2(v.x, v.y);
        o.y = packh2(v.z, v.w);
        ((uint2*)d)[j] = o;
    }
}

// ---------------------------------------------------------------------------
// fp16 mma.sync GEMM + bias (unchanged; at the rt=16 HMMA issue ceiling).
// split_mode=1: epilogue writes single f16 Q (x0.125) / K / V planes.
// ---------------------------------------------------------------------------
#define GA_TILE_H (128 * 72)
#define GB_TILE_H (64 * 136)
#define GSTAGE_H  (GA_TILE_H + GB_TILE_H)
#define GEMM_SMEM (3 * GSTAGE_H * 2)        // 107,520 B

__global__ __launch_bounds__(256, 2)
void gemm_tc(const __half* __restrict__ A, const __half* __restrict__ B,
             const float* __restrict__ bias, float* __restrict__ C,
             int M, int N, int K,
             __half* qh, __half* kh, __half* vh, int split_mode)
{
    extern __shared__ __align__(16) __half smh[];

    const int tid = threadIdx.x;
    const int wid = tid >> 5, lane = tid & 31;
    const int m0 = blockIdx.x * 128;
    const int n0 = blockIdx.y * 128;
    const int wm = wid & 1;
    const int wn = wid >> 1;

    const uint32_t sbase = smem_u32(smh);

    auto prefetch = [&](int k0, int stage) {
        uint32_t Ad = sbase + stage * GSTAGE_H * 2;
        uint32_t Bd = Ad + GA_TILE_H * 2;
        #pragma unroll
        for (int i = 0; i < 4; i++) {
            int s = tid + i * 256;
            int r = s >> 3, seg = s & 7;
            cp_async16(Ad + (r * 72 + seg * 8) * 2,
                       A + (size_t)(m0 + r) * K + k0 + seg * 8);
        }
        #pragma unroll
        for (int i = 0; i < 4; i++) {
            int s = tid + i * 256;
            int r = s >> 4, seg = s & 15;
            cp_async16(Bd + (r * 136 + seg * 8) * 2,
                       B + (size_t)(k0 + r) * N + n0 + seg * 8);
        }
        cp_commit();
    };

    float acc[4][4][4];
    #pragma unroll
    for (int i = 0; i < 4; i++)
        #pragma unroll
        for (int j = 0; j < 4; j++)
            #pragma unroll
            for (int r = 0; r < 4; r++) acc[i][j][r] = 0.f;

    const int NCH = K >> 6;
    prefetch(0, 0);
    if (NCH > 1) prefetch(64, 1);

    const int l15 = lane & 15;
    const uint32_t koff16 = (lane & 16) ? 8 : 0;

    for (int c = 0; c < NCH; c++) {
        if (c == NCH - 1)
            asm volatile("cp.async.wait_group 0;" ::: "memory");
        else
            asm volatile("cp.async.wait_group 1;" ::: "memory");
        __syncthreads();

        if (c + 2 < NCH) prefetch((c + 2) * 64, (c + 2) % 3);

        const uint32_t Asm = sbase + (c % 3) * GSTAGE_H * 2;
        const uint32_t Bsm = Asm + GA_TILE_H * 2;

        #pragma unroll
        for (int ks = 0; ks < 4; ks++) {
            const int kb = ks * 16;
            uint32_t af[4][4], bf[4][2];
            #pragma unroll
            for (int mf = 0; mf < 4; mf++)
                ldmx4(af[mf], Asm + ((wm * 64 + mf * 16 + l15) * 72 + kb + koff16) * 2);
            #pragma unroll
            for (int nfp = 0; nfp < 2; nfp++) {
                uint32_t t[4];
                ldmx4t(t, Bsm + ((kb + l15) * 136 + wn * 32 + nfp * 16 + koff16) * 2);
                bf[2 * nfp][0] = t[0]; bf[2 * nfp][1] = t[1];
                bf[2 * nfp + 1][0] = t[2]; bf[2 * nfp + 1][1] = t[3];
            }
            #pragma unroll
            for (int mf = 0; mf < 4; mf++)
                #pragma unroll
                for (int nf = 0; nf < 4; nf++)
                    mma_f16_16x8x16(acc[mf][nf], af[mf], bf[nf]);
        }
        __syncthreads();
    }

    const int lr = lane >> 2;
    const int lc = lane & 3;
    #pragma unroll
    for (int mf = 0; mf < 4; mf++) {
        int row = m0 + wm * 64 + mf * 16 + lr;
        #pragma unroll
        for (int nf = 0; nf < 4; nf++) {
            int col = n0 + wn * 32 + nf * 8 + 2 * lc;
            float b0 = bias[col], b1 = bias[col + 1];
            float v00 = acc[mf][nf][0] + b0, v01 = acc[mf][nf][1] + b1;
            float v10 = acc[mf][nf][2] + b0, v11 = acc[mf][nf][3] + b1;
            if (!split_mode) {
                *(float2*)&C[(size_t)row * N + col] = make_float2(v00, v01);
                *(float2*)&C[(size_t)(row + 8) * N + col] = make_float2(v10, v11);
            } else if (col < 1024) {           // Q plane, fold 1/sqrt(hd)
                *(uint32_t*)&qh[(size_t)row * 1024 + col] =
                    packh2(v00 * 0.125f, v01 * 0.125f);
                *(uint32_t*)&qh[(size_t)(row + 8) * 1024 + col] =
                    packh2(v10 * 0.125f, v11 * 0.125f);
            } else if (col < 2048) {           // K plane
                *(uint32_t*)&kh[(size_t)row * 1024 + col - 1024] = packh2(v00, v01);
                *(uint32_t*)&kh[(size_t)(row + 8) * 1024 + col - 1024] = packh2(v10, v11);
            } else {                           // V plane
                *(uint32_t*)&vh[(size_t)row * 1024 + col - 2048] = packh2(v00, v01);
                *(uint32_t*)&vh[(size_t)(row + 8) * 1024 + col - 2048] = packh2(v10, v11);
            }
        }
    }
}

// ---------------------------------------------------------------------------
// Causal flash attention, all-fp16 tensor ops.
// Round-14:
//  - l row-sum moved OFF the tensor pipe: sum the f16-rounded pfr values in
//    f32 on the idle FMA/ALU pipes (same p as the PV MMA -> common-mode error
//    cancellation preserved).  Ones-column MMAs deleted.
//  - At kt==ktmax (odd diagonal tile), warps 0-3 are 100% causally masked ->
//    skip their entire QK/softmax/PV (exact no-op; no barriers inside).
//  - Grid transposed to (bh, qtile) so ALL heavy q-tiles start in wave 1.
// smem halves: Q[128][72], K ring3[64][72], V ring3[64][72] = 73,728 B.
// ---------------------------------------------------------------------------
#define ATTN_SMEM 73728
#define LOG2E 1.4426950408889634f

__global__ __launch_bounds__(256, 2)
void attn_tc(const __half* __restrict__ qh_g, const __half* __restrict__ kh_g,
             const __half* __restrict__ v_g,  __half* __restrict__ y)
{
    extern __shared__ __align__(16) __half smh[];

    const int bh = blockIdx.x;                   // 0..31
    const int qt = 15 - blockIdx.y;              // heavy tiles first in wave 1
    const int b = bh >> 4, h = bh & 15;
    const int tid = threadIdx.x;
    const int wid = tid >> 5, lane = tid & 31;
    const int lr = lane >> 2, lc = lane & 3;
    const int l15 = lane & 15;
    const uint32_t koff16 = (lane & 16) ? 8 : 0;
    const uint32_t koff8  = (lane & 8)  ? 8 : 0;
    const int l7 = lane & 7;
    const int q0 = qt * 128;
    const int rowbase = b * 2048;
    const int colq = h * 64;

    const uint32_t sbase = smem_u32(smh);
    const uint32_t QA = sbase;                   // 128*72 h
    const uint32_t KA = QA + 128 * 72 * 2;       // 3 x 64*72 h
    const uint32_t VA = KA + 3 * 64 * 72 * 2;    // 3 x 64*72 h

    // Async-load Q tile (own commit group; completed by first wait at kt=0)
    #pragma unroll
    for (int j = 0; j < 4; j++) {
        int s = tid + j * 256;
        int r = s >> 3, seg = s & 7;
        cp_async16(QA + (r * 72 + seg * 8) * 2,
                   qh_g + (size_t)(rowbase + q0 + r) * 1024 + colq + seg * 8);
    }
    cp_commit();

    auto prefetch = [&](int kt) {
        const int buf = kt % 3;
        const uint32_t Kd = KA + buf * (64 * 72 * 2);
        const uint32_t Vd = VA + buf * (64 * 72 * 2);
        #pragma unroll
        for (int j = 0; j < 2; j++) {
            int s = tid + j * 256;
            int r = s >> 3, seg = s & 7;
            size_t g = (size_t)(rowbase + kt * 64 + r) * 1024 + colq + seg * 8;
            cp_async16(Kd + (r * 72 + seg * 8) * 2, kh_g + g);
            cp_async16(Vd + (r * 72 + seg * 8) * 2, v_g  + g);
        }
        cp_commit();
    };

    const int ktmax = 2 * qt + 1;                // >= 1 always
    prefetch(0);
    prefetch(1);

    float m_i[2] = {-INFINITY, -INFINITY};
    float l_i[2] = {0.f, 0.f};
    float acc_o[8][4];
    #pragma unroll
    for (int nf = 0; nf < 8; nf++)
        #pragma unroll
        for (int c = 0; c < 4; c++) acc_o[nf][c] = 0.f;

    const int r_row = 16 * wid + lr;

    for (int kt = 0; kt <= ktmax; kt++) {
        // in-flight budget: 1 while more tiles are coming, 0 at the end
        if (kt < ktmax)
            asm volatile("cp.async.wait_group 1;" ::: "memory");
        else
            asm volatile("cp.async.wait_group 0;" ::: "memory");
        __syncthreads();     // tile kt (and Q at kt=0) ready; buf (kt+2)%3 free

        if (kt + 2 <= ktmax) prefetch(kt + 2);

        // Odd diagonal tile: keys [128qt+64, 128qt+128) — rows < 64 (warps 0-3)
        // are entirely masked; skipping is an exact no-op for m/l/O.
        if (kt == ktmax && wid < 4) continue;

        const uint32_t KB = KA + (kt % 3) * (64 * 72 * 2);
        const uint32_t VB = VA + (kt % 3) * (64 * 72 * 2);

        // ---- S = Q K^T : plain fp16, ldmatrix frags ----
        float sacc[8][4];
        #pragma unroll
        for (int nf = 0; nf < 8; nf++)
            #pragma unroll
            for (int c = 0; c < 4; c++) sacc[nf][c] = 0.f;

        #pragma unroll
        for (int ks = 0; ks < 4; ks++) {
            const int kb = ks * 16;
            uint32_t ah[4];
            ldmx4(ah, QA + ((16 * wid + l15) * 72 + kb + koff16) * 2);
            #pragma unroll
            for (int nfp = 0; nfp < 4; nfp++) {
                uint32_t bh2[4];
                ldmx4(bh2, KB + ((16 * nfp + l7 + koff16) * 72 + kb + koff8) * 2);
                mma_f16_16x8x16(sacc[2 * nfp],     ah, bh2);
                mma_f16_16x8x16(sacc[2 * nfp + 1], ah, bh2 + 2);
            }
        }

        // ---- Causal mask (only the 2 diagonal k-tiles) ----
        if (kt >= 2 * qt) {
            const int rg = q0 + r_row;
            const int cb0 = kt * 64 + 2 * lc;
            #pragma unroll
            for (int nf = 0; nf < 8; nf++) {
                int c0 = cb0 + 8 * nf;
                if (c0     > rg)     sacc[nf][0] = -INFINITY;
                if (c0 + 1 > rg)     sacc[nf][1] = -INFINITY;
                if (c0     > rg + 8) sacc[nf][2] = -INFINITY;
                if (c0 + 1 > rg + 8) sacc[nf][3] = -INFINITY;
            }
        }

        // ---- Online softmax: max update + packed exp2 ----
        float tm0 = -INFINITY, tm1 = -INFINITY;
        #pragma unroll
        for (int nf = 0; nf < 8; nf++) {
            tm0 = fmaxf(tm0, fmaxf(sacc[nf][0], sacc[nf][1]));
            tm1 = fmaxf(tm1, fmaxf(sacc[nf][2], sacc[nf][3]));
        }
        tm0 = fmaxf(tm0, __shfl_xor_sync(0xffffffffu, tm0, 1));
        tm0 = fmaxf(tm0, __shfl_xor_sync(0xffffffffu, tm0, 2));
        tm1 = fmaxf(tm1, __shfl_xor_sync(0xffffffffu, tm1, 1));
        tm1 = fmaxf(tm1, __shfl_xor_sync(0xffffffffu, tm1, 2));

        const float nm0 = fmaxf(m_i[0], tm0);
        const float nm1 = fmaxf(m_i[1], tm1);
        const float sc0 = __expf(m_i[0] - nm0);
        const float sc1 = __expf(m_i[1] - nm1);
        m_i[0] = nm0;
        m_i[1] = nm1;
        const float nmL0 = nm0 * LOG2E, nmL1 = nm1 * LOG2E;

        // P packed as half2 exp2((s-m)*log2e): this IS the PV A-frag.
        uint32_t pfr[8][2];
        #pragma unroll
        for (int nf = 0; nf < 8; nf++) {
            pfr[nf][0] = h2ex2(packh2(fmaf(sacc[nf][0], LOG2E, -nmL0),
                                      fmaf(sacc[nf][1], LOG2E, -nmL0)));
            pfr[nf][1] = h2ex2(packh2(fmaf(sacc[nf][2], LOG2E, -nmL1),
                                      fmaf(sacc[nf][3], LOG2E, -nmL1)));
        }

        // ---- Row-sum l from the SAME f16 p values, in f32 on the FMA pipe ----
        float rs0 = 0.f, rs1 = 0.f;
        #pragma unroll
        for (int nf = 0; nf < 8; nf++) {
            float2 p0 = __half22float2(*(const __half2*)&pfr[nf][0]);
            float2 p1 = __half22float2(*(const __half2*)&pfr[nf][1]);
            rs0 += p0.x + p0.y;
            rs1 += p1.x + p1.y;
        }
        rs0 += __shfl_xor_sync(0xffffffffu, rs0, 1);
        rs0 += __shfl_xor_sync(0xffffffffu, rs0, 2);
        rs1 += __shfl_xor_sync(0xffffffffu, rs1, 1);
        rs1 += __shfl_xor_sync(0xffffffffu, rs1, 2);
        l_i[0] = l_i[0] * sc0 + rs0;
        l_i[1] = l_i[1] * sc1 + rs1;

        // Rescale O accumulators
        #pragma unroll
        for (int nf = 0; nf < 8; nf++) {
            acc_o[nf][0] *= sc0; acc_o[nf][1] *= sc0;
            acc_o[nf][2] *= sc1; acc_o[nf][3] *= sc1;
        }

        // ---- O += P V ----
        #pragma unroll
        for (int ks = 0; ks < 4; ks++) {
            uint32_t pa[4];
            pa[0] = pfr[2 * ks][0];
            pa[1] = pfr[2 * ks][1];
            pa[2] = pfr[2 * ks + 1][0];
            pa[3] = pfr[2 * ks + 1][1];
            #pragma unroll
            for (int nfp = 0; nfp < 4; nfp++) {
                uint32_t tv[4];
                ldmx4t(tv, VB + ((16 * ks + l7 + koff8) * 72 + 16 * nfp + koff16) * 2);
                mma_f16_16x8x16(acc_o[2 * nfp],     pa, tv);
                mma_f16_16x8x16(acc_o[2 * nfp + 1], pa, tv + 2);
            }
        }
    }

    // ---- Epilogue: normalize, store y as f16 (out-proj A operand) ----
    const float il0 = 1.f / l_i[0];
    const float il1 = 1.f / l_i[1];
    const size_t row0 = (size_t)(rowbase + q0 + r_row) * 1024;
    const size_t row1 = row0 + 8 * 1024;
    #pragma unroll
    for (int nf = 0; nf < 8; nf++) {
        int col = colq + 8 * nf + 2 * lc;
        *(uint32_t*)&y[row0 + col] = packh2(acc_o[nf][0] * il0, acc_o[nf][1] * il0);
        *(uint32_t*)&y[row1 + col] = packh2(acc_o[nf][2] * il1, acc_o[nf][3] * il1);
    }
}

// ---------------------------------------------------------------------------
extern "C" void kernel_launch(void* const* d_in, const int* in_sizes, int n_in,
                              void* d_out, int out_size)
{
    const float* x     = (const float*)d_in[0];
    const float* w_qkv = (const float*)d_in[1];
    const float* b_qkv = (const float*)d_in[2];
    const float* w_out = (const float*)d_in[3];
    const float* b_out = (const float*)d_in[4];
    float* out = (float*)d_out;

    __half *qh, *kh, *vh, *yh, *xh, *wqh, *woh;
    cudaGetSymbolAddress((void**)&qh,  g_qh);
    cudaGetSymbolAddress((void**)&kh,  g_kh);
    cudaGetSymbolAddress((void**)&vh,  g_vh);
    cudaGetSymbolAddress((void**)&yh,  g_yh);
    cudaGetSymbolAddress((void**)&xh,  g_xh);
    cudaGetSymbolAddress((void**)&wqh, g_wqkvh);
    cudaGetSymbolAddress((void**)&woh, g_wouth);

    cudaFuncSetAttribute(gemm_tc, cudaFuncAttributeMaxDynamicSharedMemorySize, GEMM_SMEM);
    cudaFuncSetAttribute(attn_tc, cudaFuncAttributeMaxDynamicSharedMemorySize, ATTN_SMEM);

    // 0) Fused f32->f16 conversion of all operands, one launch
    to_half3<<<2048, 256>>>(x, xh, w_qkv, wqh, w_out, woh);

    // 1) QKV projection -> single Q (x0.125) / K / V f16 planes
    gemm_tc<<<dim3(32, 24), 256, GEMM_SMEM>>>(xh, wqh, b_qkv, nullptr,
                                              4096, 3072, 1024,
                                              qh, kh, vh, 1);

    // 2) Causal flash attention (plain fp16 QK^T + fp16 PV, FMA-pipe row-sum)
    //    grid (bh, qtile): all heavy q-tiles land in scheduling wave 1.
    attn_tc<<<dim3(32, 16), 256, ATTN_SMEM>>>(qh, kh, vh, yh);

    // 3) Output projection
    gemm_tc<<<dim3(32, 8), 256, GEMM_SMEM>>>(yh, woh, b_out, out,
                                             4096, 1024, 1024,
                                             nullptr, nullptr, nullptr, 0);
}

// round 15
// speedup vs baseline: 10.1928x; 1.0028x over previous
#include <cuda_runtime.h>
#include <cuda_fp16.h>
#include <math.h>
#include <cstdint>

// Scratch (allocation-free rule: __device__ globals)
__device__ __half g_qh[4096 * 1024];     // Q fp16 (pre-scaled by 0.125)
__device__ __half g_kh[4096 * 1024];     // K fp16
__device__ __half g_vh[4096 * 1024];     // V fp16
__device__ __half g_yh[4096 * 1024];     // attention output, fp16
__device__ __half g_xh[4096 * 1024];     // fp16 x
__device__ __half g_wqkvh[1024 * 3072];  // fp16 w_qkv
__device__ __half g_wouth[1024 * 1024];  // fp16 w_out

// ---------------------------------------------------------------------------
// Helpers
// ---------------------------------------------------------------------------
__device__ __forceinline__ uint32_t smem_u32(const void* p) {
    uint32_t a;
    asm("{ .reg .u64 t; cvta.to.shared.u64 t, %1; cvt.u32.u64 %0, t; }"
        : "=r"(a) : "l"(p));
    return a;
}
__device__ __forceinline__ void cp_async16(uint32_t dst, const void* src) {
    asm volatile("cp.async.cg.shared.global [%0], [%1], 16;" :: "r"(dst), "l"(src));
}
__device__ __forceinline__ void cp_commit() {
    asm volatile("cp.async.commit_group;");
}
__device__ __forceinline__ void mma_f16_16x8x16(
    float* c, const uint32_t* a, const uint32_t* b) {
    asm volatile(
        "mma.sync.aligned.m16n8k16.row.col.f32.f16.f16.f32 "
        "{%0,%1,%2,%3}, {%4,%5,%6,%7}, {%8,%9}, {%0,%1,%2,%3};"
        : "+f"(c[0]), "+f"(c[1]), "+f"(c[2]), "+f"(c[3])
        : "r"(a[0]), "r"(a[1]), "r"(a[2]), "r"(a[3]), "r"(b[0]), "r"(b[1]));
}
__device__ __forceinline__ void ldmx4(uint32_t* r, uint32_t addr) {
    asm volatile("ldmatrix.sync.aligned.m8n8.x4.shared.b16 {%0,%1,%2,%3}, [%4];"
        : "=r"(r[0]), "=r"(r[1]), "=r"(r[2]), "=r"(r[3]) : "r"(addr));
}
__device__ __forceinline__ void ldmx4t(uint32_t* r, uint32_t addr) {
    asm volatile("ldmatrix.sync.aligned.m8n8.x4.trans.shared.b16 {%0,%1,%2,%3}, [%4];"
        : "=r"(r[0]), "=r"(r[1]), "=r"(r[2]), "=r"(r[3]) : "r"(addr));
}
// pack(lo, hi) -> b32 half2 {lo in [15:0], hi in [31:16]}
__device__ __forceinline__ uint32_t packh2(float lo, float hi) {
    uint32_t d;
    asm("cvt.rn.f16x2.f32 %0, %1, %2;" : "=r"(d) : "f"(hi), "f"(lo));
    return d;
}
// packed 2^x on half2
__device__ __forceinline__ uint32_t h2ex2(uint32_t x) {
    uint32_t d;
    asm("ex2.approx.f16x2 %0, %1;" : "=r"(d) : "r"(x));
    return d;
}

// ---------------------------------------------------------------------------
// Fused prepass: f32 -> f16 for x, w_qkv, w_out in one launch.
// ---------------------------------------------------------------------------
#define N4_X  (4096 * 1024 / 4)
#define N4_WQ (1024 * 3072 / 4)
#define N4_WO (1024 * 1024 / 4)

__global__ __launch_bounds__(256) void to_half3(
    const float* __restrict__ x,  __half* __restrict__ dx,
    const float* __restrict__ wq, __half* __restrict__ dwq,
    const float* __restrict__ wo, __half* __restrict__ dwo)
{
    const int total = N4_X + N4_WQ + N4_WO;
    int stride = gridDim.x * blockDim.x;
    for (int i = blockIdx.x * blockDim.x + threadIdx.x; i < total; i += stride) {
        const float* s;
        __half* d;
        int j = i;
        if (j < N4_X)            { s = x;  d = dx; }
        else if (j < N4_X+N4_WQ) { s = wq; d = dwq; j -= N4_X; }
        else                     { s = wo; d = dwo; j -= N4_X + N4_WQ; }
        float4 v = ((const float4*)s)[j];
        uint2 o;
        o.x = packh2(v.x, v.y);
        o.y = packh2(v.z, v.w);
        ((uint2*)d)[j] = o;
    }
}

// ---------------------------------------------------------------------------
// fp16 GEMM, 128x96 CTA tile (QKV path): 1024 CTAs -> 6.92 CTAs/SM -> 1.2%
// wave imbalance (vs 15.6% at 128x128/768).  Warp grid 4(M)x2(N), warp tile
// 32x48 = 2 mf x 6 nf.  B smem [64][104]h (bank-verified conflict-free).
// Epilogue writes Q (x0.125) / K / V f16 planes (boundary handled per elem).
// ---------------------------------------------------------------------------
#define G96A_H (128 * 72)
#define G96B_H (64 * 104)
#define G96S_H (G96A_H + G96B_H)
#define GEMM96_SMEM (3 * G96S_H * 2)        // 95,232 B

__global__ __launch_bounds__(256, 2)
void gemm_qkv96(const __half* __restrict__ A, const __half* __restrict__ B,
                const float* __restrict__ bias,
                __half* qh, __half* kh, __half* vh)
{
    extern __shared__ __align__(16) __half smh[];
    const int K = 1024, N = 3072;

    const int tid = threadIdx.x;
    const int wid = tid >> 5, lane = tid & 31;
    const int m0 = blockIdx.x * 128;
    const int n0 = blockIdx.y * 96;
    const int wm = wid & 3;                  // m offset wm*32
    const int wn = wid >> 2;                 // n offset wn*48

    const uint32_t sbase = smem_u32(smh);

    auto prefetch = [&](int k0, int stage) {
        uint32_t Ad = sbase + stage * G96S_H * 2;
        uint32_t Bd = Ad + G96A_H * 2;
        #pragma unroll
        for (int i = 0; i < 4; i++) {        // A: 128 rows x 8 segs
            int s = tid + i * 256;
            int r = s >> 3, seg = s & 7;
            cp_async16(Ad + (r * 72 + seg * 8) * 2,
                       A + (size_t)(m0 + r) * K + k0 + seg * 8);
        }
        #pragma unroll
        for (int i = 0; i < 3; i++) {        // B: 64 rows x 12 segs = 768
            int s = tid + i * 256;
            int r = s / 12, seg = s % 12;
            cp_async16(Bd + (r * 104 + seg * 8) * 2,
                       B + (size_t)(k0 + r) * N + n0 + seg * 8);
        }
        cp_commit();
    };

    float acc[2][6][4];
    #pragma unroll
    for (int i = 0; i < 2; i++)
        #pragma unroll
        for (int j = 0; j < 6; j++)
            #pragma unroll
            for (int r = 0; r < 4; r++) acc[i][j][r] = 0.f;

    const int NCH = K >> 6;
    prefetch(0, 0);
    prefetch(64, 1);

    const int l15 = lane & 15;
    const uint32_t koff16 = (lane & 16) ? 8 : 0;

    for (int c = 0; c < NCH; c++) {
        if (c == NCH - 1)
            asm volatile("cp.async.wait_group 0;" ::: "memory");
        else
            asm volatile("cp.async.wait_group 1;" ::: "memory");
        __syncthreads();

        if (c + 2 < NCH) prefetch((c + 2) * 64, (c + 2) % 3);

        const uint32_t Asm = sbase + (c % 3) * G96S_H * 2;
        const uint32_t Bsm = Asm + G96A_H * 2;

        #pragma unroll
        for (int ks = 0; ks < 4; ks++) {
            const int kb = ks * 16;
            uint32_t af[2][4], bf[6][2];
            #pragma unroll
            for (int mf = 0; mf < 2; mf++)
                ldmx4(af[mf], Asm + ((wm * 32 + mf * 16 + l15) * 72 + kb + koff16) * 2);
            #pragma unroll
            for (int nfp = 0; nfp < 3; nfp++) {
                uint32_t t[4];
                ldmx4t(t, Bsm + ((kb + l15) * 104 + wn * 48 + nfp * 16 + koff16) * 2);
                bf[2 * nfp][0] = t[0]; bf[2 * nfp][1] = t[1];
                bf[2 * nfp + 1][0] = t[2]; bf[2 * nfp + 1][1] = t[3];
            }
            #pragma unroll
            for (int mf = 0; mf < 2; mf++)
                #pragma unroll
                for (int nf = 0; nf < 6; nf++)
                    mma_f16_16x8x16(acc[mf][nf], af[mf], bf[nf]);
        }
        __syncthreads();
    }

    const int lr = lane >> 2;
    const int lc = lane & 3;
    #pragma unroll
    for (int mf = 0; mf < 2; mf++) {
        int row = m0 + wm * 32 + mf * 16 + lr;
        #pragma unroll
        for (int nf = 0; nf < 6; nf++) {
            int col = n0 + wn * 48 + nf * 8 + 2 * lc;
            float b0 = bias[col], b1 = bias[col + 1];
            float v00 = acc[mf][nf][0] + b0, v01 = acc[mf][nf][1] + b1;
            float v10 = acc[mf][nf][2] + b0, v11 = acc[mf][nf][3] + b1;
            if (col < 1024) {                  // Q plane, fold 1/sqrt(hd)
                *(uint32_t*)&qh[(size_t)row * 1024 + col] =
                    packh2(v00 * 0.125f, v01 * 0.125f);
                *(uint32_t*)&qh[(size_t)(row + 8) * 1024 + col] =
                    packh2(v10 * 0.125f, v11 * 0.125f);
            } else if (col < 2048) {           // K plane
                *(uint32_t*)&kh[(size_t)row * 1024 + col - 1024] = packh2(v00, v01);
                *(uint32_t*)&kh[(size_t)(row + 8) * 1024 + col - 1024] = packh2(v10, v11);
            } else {                           // V plane
                *(uint32_t*)&vh[(size_t)row * 1024 + col - 2048] = packh2(v00, v01);
                *(uint32_t*)&vh[(size_t)(row + 8) * 1024 + col - 2048] = packh2(v10, v11);
            }
        }
    }
}

// ---------------------------------------------------------------------------
// fp16 GEMM 128x128 + bias -> f32 C (out-projection; 256 CTAs = one wave).
// ---------------------------------------------------------------------------
#define GA_TILE_H (128 * 72)
#define GB_TILE_H (64 * 136)
#define GSTAGE_H  (GA_TILE_H + GB_TILE_H)
#define GEMM_SMEM (3 * GSTAGE_H * 2)        // 107,520 B

__global__ __launch_bounds__(256, 2)
void gemm_tc(const __half* __restrict__ A, const __half* __restrict__ B,
             const float* __restrict__ bias, float* __restrict__ C,
             int M, int N, int K)
{
    extern __shared__ __align__(16) __half smh[];

    const int tid = threadIdx.x;
    const int wid = tid >> 5, lane = tid & 31;
    const int m0 = blockIdx.x * 128;
    const int n0 = blockIdx.y * 128;
    const int wm = wid & 1;
    const int wn = wid >> 1;

    const uint32_t sbase = smem_u32(smh);

    auto prefetch = [&](int k0, int stage) {
        uint32_t Ad = sbase + stage * GSTAGE_H * 2;
        uint32_t Bd = Ad + GA_TILE_H * 2;
        #pragma unroll
        for (int i = 0; i < 4; i++) {
            int s = tid + i * 256;
            int r = s >> 3, seg = s & 7;
            cp_async16(Ad + (r * 72 + seg * 8) * 2,
                       A + (size_t)(m0 + r) * K + k0 + seg * 8);
        }
        #pragma unroll
        for (int i = 0; i < 4; i++) {
            int s = tid + i * 256;
            int r = s >> 4, seg = s & 15;
            cp_async16(Bd + (r * 136 + seg * 8) * 2,
                       B + (size_t)(k0 + r) * N + n0 + seg * 8);
        }
        cp_commit();
    };

    float acc[4][4][4];
    #pragma unroll
    for (int i = 0; i < 4; i++)
        #pragma unroll
        for (int j = 0; j < 4; j++)
            #pragma unroll
            for (int r = 0; r < 4; r++) acc[i][j][r] = 0.f;

    const int NCH = K >> 6;
    prefetch(0, 0);
    if (NCH > 1) prefetch(64, 1);

    const int l15 = lane & 15;
    const uint32_t koff16 = (lane & 16) ? 8 : 0;

    for (int c = 0; c < NCH; c++) {
        if (c == NCH - 1)
            asm volatile("cp.async.wait_group 0;" ::: "memory");
        else
            asm volatile("cp.async.wait_group 1;" ::: "memory");
        __syncthreads();

        if (c + 2 < NCH) prefetch((c + 2) * 64, (c + 2) % 3);

        const uint32_t Asm = sbase + (c % 3) * GSTAGE_H * 2;
        const uint32_t Bsm = Asm + GA_TILE_H * 2;

        #pragma unroll
        for (int ks = 0; ks < 4; ks++) {
            const int kb = ks * 16;
            uint32_t af[4][4], bf[4][2];
            #pragma unroll
            for (int mf = 0; mf < 4; mf++)
                ldmx4(af[mf], Asm + ((wm * 64 + mf * 16 + l15) * 72 + kb + koff16) * 2);
            #pragma unroll
            for (int nfp = 0; nfp < 2; nfp++) {
                uint32_t t[4];
                ldmx4t(t, Bsm + ((kb + l15) * 136 + wn * 32 + nfp * 16 + koff16) * 2);
                bf[2 * nfp][0] = t[0]; bf[2 * nfp][1] = t[1];
                bf[2 * nfp + 1][0] = t[2]; bf[2 * nfp + 1][1] = t[3];
            }
            #pragma unroll
            for (int mf = 0; mf < 4; mf++)
                #pragma unroll
                for (int nf = 0; nf < 4; nf++)
                    mma_f16_16x8x16(acc[mf][nf], af[mf], bf[nf]);
        }
        __syncthreads();
    }

    const int lr = lane >> 2;
    const int lc = lane & 3;
    #pragma unroll
    for (int mf = 0; mf < 4; mf++) {
        int row = m0 + wm * 64 + mf * 16 + lr;
        #pragma unroll
        for (int nf = 0; nf < 4; nf++) {
            int col = n0 + wn * 32 + nf * 8 + 2 * lc;
            float b0 = bias[col], b1 = bias[col + 1];
            *(float2*)&C[(size_t)row * N + col] =
                make_float2(acc[mf][nf][0] + b0, acc[mf][nf][1] + b1);
            *(float2*)&C[(size_t)(row + 8) * N + col] =
                make_float2(acc[mf][nf][2] + b0, acc[mf][nf][3] + b1);
        }
    }
}

// ---------------------------------------------------------------------------
// Causal flash attention, all-fp16 tensor ops.
// Round-15: diagonal-tile MMA skipping — on diag tiles warp `wid` only needs
// n-frag pairs nfp <= lim (QK) and key-chunks ks <= lim (PV), where
// lim = wid - 4*(kt - 2qt); beyond is fully causally masked (exact no-op:
// the mask sets those S entries to -inf regardless, and skipped PV chunks
// multiply all-zero P columns).  Warp-uniform predicate, no divergence.
// smem halves: Q[128][72], K ring3[64][72], V ring3[64][72] = 73,728 B.
// ---------------------------------------------------------------------------
#define ATTN_SMEM 73728
#define LOG2E 1.4426950408889634f

__global__ __launch_bounds__(256, 2)
void attn_tc(const __half* __restrict__ qh_g, const __half* __restrict__ kh_g,
             const __half* __restrict__ v_g,  __half* __restrict__ y)
{
    extern __shared__ __align__(16) __half smh[];

    const int bh = blockIdx.x;                   // 0..31
    const int qt = 15 - blockIdx.y;              // heavy tiles first in wave 1
    const int b = bh >> 4, h = bh & 15;
    const int tid = threadIdx.x;
    const int wid = tid >> 5, lane = tid & 31;
    const int lr = lane >> 2, lc = lane & 3;
    const int l15 = lane & 15;
    const uint32_t koff16 = (lane & 16) ? 8 : 0;
    const uint32_t koff8  = (lane & 8)  ? 8 : 0;
    const int l7 = lane & 7;
    const int q0 = qt * 128;
    const int rowbase = b * 2048;
    const int colq = h * 64;

    const uint32_t sbase = smem_u32(smh);
    const uint32_t QA = sbase;                   // 128*72 h
    const uint32_t KA = QA + 128 * 72 * 2;       // 3 x 64*72 h
    const uint32_t VA = KA + 3 * 64 * 72 * 2;    // 3 x 64*72 h

    // Async-load Q tile (own commit group; completed by first wait at kt=0)
    #pragma unroll
    for (int j = 0; j < 4; j++) {
        int s = tid + j * 256;
        int r = s >> 3, seg = s & 7;
        cp_async16(QA + (r * 72 + seg * 8) * 2,
                   qh_g + (size_t)(rowbase + q0 + r) * 1024 + colq + seg * 8);
    }
    cp_commit();

    auto prefetch = [&](int kt) {
        const int buf = kt % 3;
        const uint32_t Kd = KA + buf * (64 * 72 * 2);
        const uint32_t Vd = VA + buf * (64 * 72 * 2);
        #pragma unroll
        for (int j = 0; j < 2; j++) {
            int s = tid + j * 256;
            int r = s >> 3, seg = s & 7;
            size_t g = (size_t)(rowbase + kt * 64 + r) * 1024 + colq + seg * 8;
            cp_async16(Kd + (r * 72 + seg * 8) * 2, kh_g + g);
            cp_async16(Vd + (r * 72 + seg * 8) * 2, v_g  + g);
        }
        cp_commit();
    };

    const int ktmax = 2 * qt + 1;                // >= 1 always
    prefetch(0);
    prefetch(1);

    float m_i[2] = {-INFINITY, -INFINITY};
    float l_i[2] = {0.f, 0.f};
    float acc_o[8][4];
    #pragma unroll
    for (int nf = 0; nf < 8; nf++)
        #pragma unroll
        for (int c = 0; c < 4; c++) acc_o[nf][c] = 0.f;

    const int r_row = 16 * wid + lr;

    for (int kt = 0; kt <= ktmax; kt++) {
        // in-flight budget: 1 while more tiles are coming, 0 at the end
        if (kt < ktmax)
            asm volatile("cp.async.wait_group 1;" ::: "memory");
        else
            asm volatile("cp.async.wait_group 0;" ::: "memory");
        __syncthreads();     // tile kt (and Q at kt=0) ready; buf (kt+2)%3 free

        if (kt + 2 <= ktmax) prefetch(kt + 2);

        // Odd diagonal tile: rows < 64 (warps 0-3) are entirely masked.
        if (kt == ktmax && wid < 4) continue;

        // Fragment-level diag limit (warp-uniform): frags beyond lim are
        // fully masked (QK) / all-zero P (PV).  Non-diag: lim = 3 (all).
        const int lim = (kt >= 2 * qt) ? (wid - ((kt - 2 * qt) << 2)) : 3;

        const uint32_t KB = KA + (kt % 3) * (64 * 72 * 2);
        const uint32_t VB = VA + (kt % 3) * (64 * 72 * 2);

        // ---- S = Q K^T : plain fp16, ldmatrix frags ----
        float sacc[8][4];
        #pragma unroll
        for (int nf = 0; nf < 8; nf++)
            #pragma unroll
            for (int c = 0; c < 4; c++) sacc[nf][c] = 0.f;

        #pragma unroll
        for (int ks = 0; ks < 4; ks++) {
            const int kb = ks * 16;
            uint32_t ah[4];
            ldmx4(ah, QA + ((16 * wid + l15) * 72 + kb + koff16) * 2);
            #pragma unroll
            for (int nfp = 0; nfp < 4; nfp++) {
                if (nfp <= lim) {
                    uint32_t bh2[4];
                    ldmx4(bh2, KB + ((16 * nfp + l7 + koff16) * 72 + kb + koff8) * 2);
                    mma_f16_16x8x16(sacc[2 * nfp],     ah, bh2);
                    mma_f16_16x8x16(sacc[2 * nfp + 1], ah, bh2 + 2);
                }
            }
        }

        // ---- Causal mask (only the 2 diagonal k-tiles) ----
        if (kt >= 2 * qt) {
            const int rg = q0 + r_row;
            const int cb0 = kt * 64 + 2 * lc;
            #pragma unroll
            for (int nf = 0; nf < 8; nf++) {
                int c0 = cb0 + 8 * nf;
                if (c0     > rg)     sacc[nf][0] = -INFINITY;
                if (c0 + 1 > rg)     sacc[nf][1] = -INFINITY;
                if (c0     > rg + 8) sacc[nf][2] = -INFINITY;
                if (c0 + 1 > rg + 8) sacc[nf][3] = -INFINITY;
            }
        }

        // ---- Online softmax: max update + packed exp2 ----
        float tm0 = -INFINITY, tm1 = -INFINITY;
        #pragma unroll
        for (int nf = 0; nf < 8; nf++) {
            tm0 = fmaxf(tm0, fmaxf(sacc[nf][0], sacc[nf][1]));
            tm1 = fmaxf(tm1, fmaxf(sacc[nf][2], sacc[nf][3]));
        }
        tm0 = fmaxf(tm0, __shfl_xor_sync(0xffffffffu, tm0, 1));
        tm0 = fmaxf(tm0, __shfl_xor_sync(0xffffffffu, tm0, 2));
        tm1 = fmaxf(tm1, __shfl_xor_sync(0xffffffffu, tm1, 1));
        tm1 = fmaxf(tm1, __shfl_xor_sync(0xffffffffu, tm1, 2));

        const float nm0 = fmaxf(m_i[0], tm0);
        const float nm1 = fmaxf(m_i[1], tm1);
        const float sc0 = __expf(m_i[0] - nm0);
        const float sc1 = __expf(m_i[1] - nm1);
        m_i[0] = nm0;
        m_i[1] = nm1;
        const float nmL0 = nm0 * LOG2E, nmL1 = nm1 * LOG2E;

        // P packed as half2 exp2((s-m)*log2e): this IS the PV A-frag.
        uint32_t pfr[8][2];
        #pragma unroll
        for (int nf = 0; nf < 8; nf++) {
            pfr[nf][0] = h2ex2(packh2(fmaf(sacc[nf][0], LOG2E, -nmL0),
                                      fmaf(sacc[nf][1], LOG2E, -nmL0)));
            pfr[nf][1] = h2ex2(packh2(fmaf(sacc[nf][2], LOG2E, -nmL1),
                                      fmaf(sacc[nf][3], LOG2E, -nmL1)));
        }

        // ---- Row-sum l from the SAME f16 p values, in f32 (FMA pipe) ----
        float rs0 = 0.f, rs1 = 0.f;
        #pragma unroll
        for (int nf = 0; nf < 8; nf++) {
            float2 p0 = __half22float2(*(const __half2*)&pfr[nf][0]);
            float2 p1 = __half22float2(*(const __half2*)&pfr[nf][1]);
            rs0 += p0.x + p0.y;
            rs1 += p1.x + p1.y;
        }
        rs0 += __shfl_xor_sync(0xffffffffu, rs0, 1);
        rs0 += __shfl_xor_sync(0xffffffffu, rs0, 2);
        rs1 += __shfl_xor_sync(0xffffffffu, rs1, 1);
        rs1 += __shfl_xor_sync(0xffffffffu, rs1, 2);
        l_i[0] = l_i[0] * sc0 + rs0;
        l_i[1] = l_i[1] * sc1 + rs1;

        // Rescale O accumulators
        #pragma unroll
        for (int nf = 0; nf < 8; nf++) {
            acc_o[nf][0] *= sc0; acc_o[nf][1] *= sc0;
            acc_o[nf][2] *= sc1; acc_o[nf][3] *= sc1;
        }

        // ---- O += P V  (skip key-chunks with all-zero P on diag tiles) ----
        #pragma unroll
        for (int ks = 0; ks < 4; ks++) {
            if (ks <= lim) {
                uint32_t pa[4];
                pa[0] = pfr[2 * ks][0];
                pa[1] = pfr[2 * ks][1];
                pa[2] = pfr[2 * ks + 1][0];
                pa[3] = pfr[2 * ks + 1][1];
                #pragma unroll
                for (int nfp = 0; nfp < 4; nfp++) {
                    uint32_t tv[4];
                    ldmx4t(tv, VB + ((16 * ks + l7 + koff8) * 72 + 16 * nfp + koff16) * 2);
                    mma_f16_16x8x16(acc_o[2 * nfp],     pa, tv);
                    mma_f16_16x8x16(acc_o[2 * nfp + 1], pa, tv + 2);
                }
            }
        }
    }

    // ---- Epilogue: normalize, store y as f16 (out-proj A operand) ----
    const float il0 = 1.f / l_i[0];
    const float il1 = 1.f / l_i[1];
    const size_t row0 = (size_t)(rowbase + q0 + r_row) * 1024;
    const size_t row1 = row0 + 8 * 1024;
    #pragma unroll
    for (int nf = 0; nf < 8; nf++) {
        int col = colq + 8 * nf + 2 * lc;
        *(uint32_t*)&y[row0 + col] = packh2(acc_o[nf][0] * il0, acc_o[nf][1] * il0);
        *(uint32_t*)&y[row1 + col] = packh2(acc_o[nf][2] * il1, acc_o[nf][3] * il1);
    }
}

// ---------------------------------------------------------------------------
extern "C" void kernel_launch(void* const* d_in, const int* in_sizes, int n_in,
                              void* d_out, int out_size)
{
    const float* x     = (const float*)d_in[0];
    const float* w_qkv = (const float*)d_in[1];
    const float* b_qkv = (const float*)d_in[2];
    const float* w_out = (const float*)d_in[3];
    const float* b_out = (const float*)d_in[4];
    float* out = (float*)d_out;

    __half *qh, *kh, *vh, *yh, *xh, *wqh, *woh;
    cudaGetSymbolAddress((void**)&qh,  g_qh);
    cudaGetSymbolAddress((void**)&kh,  g_kh);
    cudaGetSymbolAddress((void**)&vh,  g_vh);
    cudaGetSymbolAddress((void**)&yh,  g_yh);
    cudaGetSymbolAddress((void**)&xh,  g_xh);
    cudaGetSymbolAddress((void**)&wqh, g_wqkvh);
    cudaGetSymbolAddress((void**)&woh, g_wouth);

    cudaFuncSetAttribute(gemm_qkv96, cudaFuncAttributeMaxDynamicSharedMemorySize, GEMM96_SMEM);
    cudaFuncSetAttribute(gemm_tc, cudaFuncAttributeMaxDynamicSharedMemorySize, GEMM_SMEM);
    cudaFuncSetAttribute(attn_tc, cudaFuncAttributeMaxDynamicSharedMemorySize, ATTN_SMEM);

    // 0) Fused f32->f16 conversion of all operands, one launch
    to_half3<<<2048, 256>>>(x, xh, w_qkv, wqh, w_out, woh);

    // 1) QKV projection (128x96 tiles, 1024 CTAs -> balanced waves)
    gemm_qkv96<<<dim3(32, 32), 256, GEMM96_SMEM>>>(xh, wqh, b_qkv, qh, kh, vh);

    // 2) Causal flash attention (fp16 QK^T + fp16 PV, diag-frag skipping)
    attn_tc<<<dim3(32, 16), 256, ATTN_SMEM>>>(qh, kh, vh, yh);

    // 3) Output projection (128x128 tiles, 256 CTAs = one wave)
    gemm_tc<<<dim3(32, 8), 256, GEMM_SMEM>>>(yh, woh, b_out, out, 4096, 1024, 1024);
}